// round 1
// baseline (speedup 1.0000x reference)
#include <cuda_runtime.h>
#include <cuda_bf16.h>
#include <cstdint>

// Problem constants (fixed by reference)
#define DMODEL 1024
#define HEADS  16
#define DH     64
#define BATCH  4
#define SEQ    4096
#define ROWS   (BATCH * SEQ)   // 16384
#define KSPLIT 8                // split-M factor for kv aggregation
#define EPSV   1e-6f

// ---------------- scratch (device globals; no allocation allowed) ------------
__device__ float g_Q[ROWS * DMODEL];
__device__ float g_K[ROWS * DMODEL];
__device__ float g_V[ROWS * DMODEL];
__device__ float g_S[ROWS * DMODEL];
__device__ float g_kvp[BATCH * HEADS * KSPLIT * DH * DH];
__device__ float g_zp [BATCH * HEADS * KSPLIT * DH];
__device__ float g_kv [BATCH * HEADS * DH * DH];
__device__ float g_z  [BATCH * HEADS * DH];

typedef unsigned long long ull;

// Packed fp32x2 FMA (sm_103a FFMA2 — ptxas never auto-generates this)
__device__ __forceinline__ ull ffma2(ull a, ull b, ull c) {
    ull d;
    asm("fma.rn.f32x2 %0, %1, %2, %3;" : "=l"(d) : "l"(a), "l"(b), "l"(c));
    return d;
}
__device__ __forceinline__ float2 unpack2(ull v) {
    float2 r;
    asm("mov.b64 {%0, %1}, %2;" : "=f"(r.x), "=f"(r.y) : "l"(v));
    return r;
}

// =============================================================================
// GEMM (NT):  Y[r][c] = sum_k X[r][k] * W[c][k] + bias[c], optional phi()
// X: [ROWS, 1024] row-major, W: [1024, 1024] row-major (rows are output cols)
// Tile 128x128x16, 256 threads, 8x8 per thread, FFMA2 packed along N.
// =============================================================================
template<bool PHI>
__global__ __launch_bounds__(256, 2)
void gemm_nt(const float* __restrict__ X, const float* __restrict__ W,
             const float* __restrict__ bias, float* __restrict__ Y) {
    const int tid = threadIdx.x;
    const int bm = blockIdx.y;   // row tile
    const int bn = blockIdx.x;   // col tile

    // A stored duplicated: As[k][2m] = As[k][2m+1] = A[m][k]
    __shared__ __align__(16) float As[16][256];
    __shared__ __align__(16) float Ws[16][128];

    const int lrow = tid & 127;   // loader row within tile
    const int kq   = tid >> 7;    // which 8-wide k half this thread loads

    const float* Xg = X + (size_t)(bm * 128 + lrow) * DMODEL + kq * 8;
    const float* Wg = W + (size_t)(bn * 128 + lrow) * DMODEL + kq * 8;

    const int ty = tid >> 4;      // 0..15 (m direction)
    const int tx = tid & 15;      // 0..15 (n direction)

    ull acc[8][4];
    #pragma unroll
    for (int i = 0; i < 8; i++)
        #pragma unroll
        for (int j = 0; j < 4; j++) acc[i][j] = 0ull;

    float2* As2 = reinterpret_cast<float2*>(&As[0][0]);   // [k*128 + m]

    for (int kt = 0; kt < DMODEL / 16; kt++) {
        // global loads for this k-tile (overlap with previous compute)
        float4 xa = *(const float4*)(Xg + kt * 16);
        float4 xb = *(const float4*)(Xg + kt * 16 + 4);
        float4 wa = *(const float4*)(Wg + kt * 16);
        float4 wb = *(const float4*)(Wg + kt * 16 + 4);

        __syncthreads();   // previous compute done reading smem

        const int kb = kq * 8;
        As2[(kb + 0) * 128 + lrow] = make_float2(xa.x, xa.x);
        As2[(kb + 1) * 128 + lrow] = make_float2(xa.y, xa.y);
        As2[(kb + 2) * 128 + lrow] = make_float2(xa.z, xa.z);
        As2[(kb + 3) * 128 + lrow] = make_float2(xa.w, xa.w);
        As2[(kb + 4) * 128 + lrow] = make_float2(xb.x, xb.x);
        As2[(kb + 5) * 128 + lrow] = make_float2(xb.y, xb.y);
        As2[(kb + 6) * 128 + lrow] = make_float2(xb.z, xb.z);
        As2[(kb + 7) * 128 + lrow] = make_float2(xb.w, xb.w);
        Ws[kb + 0][lrow] = wa.x;
        Ws[kb + 1][lrow] = wa.y;
        Ws[kb + 2][lrow] = wa.z;
        Ws[kb + 3][lrow] = wa.w;
        Ws[kb + 4][lrow] = wb.x;
        Ws[kb + 5][lrow] = wb.y;
        Ws[kb + 6][lrow] = wb.z;
        Ws[kb + 7][lrow] = wb.w;

        __syncthreads();

        const ulonglong2* Au = reinterpret_cast<const ulonglong2*>(&As[0][0]); // 64 ull2/row
        const ulonglong2* Bu = reinterpret_cast<const ulonglong2*>(&Ws[0][0]); // 32 ull2/row

        #pragma unroll
        for (int k = 0; k < 16; k++) {
            ulonglong2 a01 = Au[k * 64 + ty * 4 + 0];
            ulonglong2 a23 = Au[k * 64 + ty * 4 + 1];
            ulonglong2 a45 = Au[k * 64 + ty * 4 + 2];
            ulonglong2 a67 = Au[k * 64 + ty * 4 + 3];
            ulonglong2 b01 = Bu[k * 32 + tx * 2 + 0];
            ulonglong2 b23 = Bu[k * 32 + tx * 2 + 1];
            ull av[8] = {a01.x, a01.y, a23.x, a23.y, a45.x, a45.y, a67.x, a67.y};
            ull bv[4] = {b01.x, b01.y, b23.x, b23.y};
            #pragma unroll
            for (int mi = 0; mi < 8; mi++)
                #pragma unroll
                for (int ni = 0; ni < 4; ni++)
                    acc[mi][ni] = ffma2(av[mi], bv[ni], acc[mi][ni]);
        }
    }

    // epilogue: bias (+ phi), store
    const int col0 = bn * 128 + tx * 8;
    float bcol[8];
    *(float4*)&bcol[0] = *(const float4*)&bias[col0];
    *(float4*)&bcol[4] = *(const float4*)&bias[col0 + 4];

    #pragma unroll
    for (int mi = 0; mi < 8; mi++) {
        const int row = bm * 128 + ty * 8 + mi;
        float o[8];
        #pragma unroll
        for (int ni = 0; ni < 4; ni++) {
            float2 p = unpack2(acc[mi][ni]);
            o[2 * ni]     = p.x + bcol[2 * ni];
            o[2 * ni + 1] = p.y + bcol[2 * ni + 1];
        }
        if (PHI) {
            #pragma unroll
            for (int j = 0; j < 8; j++)
                o[j] = (o[j] > 0.f) ? (o[j] + 1.f) : __expf(o[j]);
        }
        float* yp = Y + (size_t)row * DMODEL + col0;
        *(float4*)(yp)     = make_float4(o[0], o[1], o[2], o[3]);
        *(float4*)(yp + 4) = make_float4(o[4], o[5], o[6], o[7]);
    }
}

// =============================================================================
// kv partial:  per (b,h,split) block compute KV[d][e] += K[m][d]*V[m][e],
// z[d] += K[m][d] over a 512-row m chunk.
// =============================================================================
__global__ __launch_bounds__(256)
void kv_partial(const float* __restrict__ K, const float* __restrict__ V,
                float* __restrict__ kvp, float* __restrict__ zp) {
    const int tid = threadIdx.x;
    const int s  = blockIdx.x % KSPLIT;
    const int bh = blockIdx.x / KSPLIT;
    const int b = bh / HEADS, h = bh % HEADS;

    __shared__ __align__(16) float Ks[64][64];
    __shared__ __align__(16) float Vs[64][64];

    const int d0 = (tid >> 4) * 4;
    const int e0 = (tid & 15) * 4;
    float acc[4][4] = {};
    float zacc[4] = {};

    const size_t base = (size_t)b * SEQ * DMODEL + (size_t)h * DH;
    const int m_begin = s * (SEQ / KSPLIT);
    const int m_end   = m_begin + (SEQ / KSPLIT);

    for (int m0 = m_begin; m0 < m_end; m0 += 64) {
        // stage loads in regs
        float4 kreg[4], vreg[4];
        #pragma unroll
        for (int t = 0; t < 4; t++) {
            int lin = tid + t * 256;
            int r = lin >> 4, c4 = (lin & 15) * 4;
            kreg[t] = *(const float4*)&K[base + (size_t)(m0 + r) * DMODEL + c4];
            vreg[t] = *(const float4*)&V[base + (size_t)(m0 + r) * DMODEL + c4];
        }
        __syncthreads();
        #pragma unroll
        for (int t = 0; t < 4; t++) {
            int lin = tid + t * 256;
            int r = lin >> 4, c4 = (lin & 15) * 4;
            *(float4*)&Ks[r][c4] = kreg[t];
            *(float4*)&Vs[r][c4] = vreg[t];
        }
        __syncthreads();

        #pragma unroll 4
        for (int mm = 0; mm < 64; mm++) {
            float4 k4 = *(const float4*)&Ks[mm][d0];
            float4 v4 = *(const float4*)&Vs[mm][e0];
            float kk[4] = {k4.x, k4.y, k4.z, k4.w};
            float vv[4] = {v4.x, v4.y, v4.z, v4.w};
            #pragma unroll
            for (int i = 0; i < 4; i++)
                #pragma unroll
                for (int j = 0; j < 4; j++)
                    acc[i][j] += kk[i] * vv[j];
            if ((tid & 15) == 0) {
                #pragma unroll
                for (int i = 0; i < 4; i++) zacc[i] += kk[i];
            }
        }
    }

    float* kout = kvp + (size_t)blockIdx.x * (DH * DH);
    #pragma unroll
    for (int i = 0; i < 4; i++)
        *(float4*)&kout[(d0 + i) * DH + e0] = make_float4(acc[i][0], acc[i][1], acc[i][2], acc[i][3]);
    if ((tid & 15) == 0) {
        #pragma unroll
        for (int i = 0; i < 4; i++) zp[(size_t)blockIdx.x * DH + d0 + i] = zacc[i];
    }
}

// reduce KSPLIT partials -> kv[bh][d][e], z[bh][d]
__global__ __launch_bounds__(256)
void kv_reduce(const float* __restrict__ kvp, const float* __restrict__ zp,
               float* __restrict__ kvo, float* __restrict__ zo) {
    const int bh = blockIdx.x;
    const int tid = threadIdx.x;
    for (int i = tid; i < DH * DH; i += 256) {
        float sum = 0.f;
        #pragma unroll
        for (int s = 0; s < KSPLIT; s++)
            sum += kvp[((size_t)bh * KSPLIT + s) * (DH * DH) + i];
        kvo[(size_t)bh * (DH * DH) + i] = sum;
    }
    if (tid < DH) {
        float sum = 0.f;
        #pragma unroll
        for (int s = 0; s < KSPLIT; s++)
            sum += zp[((size_t)bh * KSPLIT + s) * DH + tid];
        zo[(size_t)bh * DH + tid] = sum;
    }
}

// =============================================================================
// attn:  S[n][h*64+e] = (sum_d Q[n][h*64+d]*kv[bh][d][e]) / (sum_d Q*z + eps)
// one block per 64 query rows, loops over heads
// =============================================================================
__global__ __launch_bounds__(256)
void attn(const float* __restrict__ Q, const float* __restrict__ kv,
          const float* __restrict__ z, float* __restrict__ S) {
    const int tid = threadIdx.x;
    const int row0 = blockIdx.x * 64;
    const int b = row0 / SEQ;

    __shared__ __align__(16) float qs[64][64];
    __shared__ __align__(16) float kvs[64][64];
    __shared__ __align__(16) float zs[64];
    __shared__ float dens[64];

    const int r0 = (tid >> 4) * 4;
    const int e0 = (tid & 15) * 4;

    for (int h = 0; h < HEADS; h++) {
        const int bh = b * HEADS + h;
        __syncthreads();   // previous head done reading smem
        #pragma unroll
        for (int t = 0; t < 4; t++) {
            int lin = tid + t * 256;
            int r = lin >> 4, c4 = (lin & 15) * 4;
            *(float4*)&qs[r][c4] =
                *(const float4*)&Q[(size_t)(row0 + r) * DMODEL + h * DH + c4];
            ((float4*)&kvs[0][0])[lin] =
                ((const float4*)(kv + (size_t)bh * DH * DH))[lin];
        }
        if (tid < 16)
            ((float4*)zs)[tid] = ((const float4*)(z + (size_t)bh * DH))[tid];
        __syncthreads();

        if (tid < 64) {
            float sden = 0.f;
            #pragma unroll 8
            for (int d = 0; d < 64; d++) sden += qs[tid][d] * zs[d];
            dens[tid] = sden + EPSV;
        }
        __syncthreads();

        float acc[4][4] = {};
        #pragma unroll 4
        for (int d = 0; d < 64; d++) {
            float4 k4 = *(const float4*)&kvs[d][e0];
            float kk[4] = {k4.x, k4.y, k4.z, k4.w};
            #pragma unroll
            for (int i = 0; i < 4; i++) {
                float qv = qs[r0 + i][d];
                #pragma unroll
                for (int j = 0; j < 4; j++) acc[i][j] += qv * kk[j];
            }
        }
        #pragma unroll
        for (int i = 0; i < 4; i++) {
            float rinv = 1.0f / dens[r0 + i];
            float* sp = S + (size_t)(row0 + r0 + i) * DMODEL + h * DH + e0;
            *(float4*)sp = make_float4(acc[i][0] * rinv, acc[i][1] * rinv,
                                       acc[i][2] * rinv, acc[i][3] * rinv);
        }
    }
}

// =============================================================================
extern "C" void kernel_launch(void* const* d_in, const int* in_sizes, int n_in,
                              void* d_out, int out_size) {
    const float* queries = (const float*)d_in[0];
    const float* keys    = (const float*)d_in[1];
    const float* values  = (const float*)d_in[2];
    const float* wq = (const float*)d_in[3];
    const float* bq = (const float*)d_in[4];
    const float* wk = (const float*)d_in[5];
    const float* bk = (const float*)d_in[6];
    const float* wv = (const float*)d_in[7];
    const float* bv = (const float*)d_in[8];
    const float* wo = (const float*)d_in[9];
    const float* bo = (const float*)d_in[10];
    float* out = (float*)d_out;

    float *Q, *K, *V, *S, *kvp, *zp, *kvb, *zb;
    cudaGetSymbolAddress((void**)&Q,   g_Q);
    cudaGetSymbolAddress((void**)&K,   g_K);
    cudaGetSymbolAddress((void**)&V,   g_V);
    cudaGetSymbolAddress((void**)&S,   g_S);
    cudaGetSymbolAddress((void**)&kvp, g_kvp);
    cudaGetSymbolAddress((void**)&zp,  g_zp);
    cudaGetSymbolAddress((void**)&kvb, g_kv);
    cudaGetSymbolAddress((void**)&zb,  g_z);

    dim3 blk(256);
    dim3 gg(DMODEL / 128, ROWS / 128);   // (8, 128)

    gemm_nt<true ><<<gg, blk>>>(queries, wq, bq, Q);
    gemm_nt<true ><<<gg, blk>>>(keys,    wk, bk, K);
    gemm_nt<false><<<gg, blk>>>(values,  wv, bv, V);
    kv_partial<<<BATCH * HEADS * KSPLIT, blk>>>(K, V, kvp, zp);
    kv_reduce <<<BATCH * HEADS, blk>>>(kvp, zp, kvb, zb);
    attn      <<<ROWS / 64, blk>>>(Q, kvb, zb, S);
    gemm_nt<false><<<gg, blk>>>(S, wo, bo, out);
}

// round 3
// speedup vs baseline: 2.1554x; 2.1554x over previous
#include <cuda_runtime.h>
#include <cuda_bf16.h>
#include <cstdint>

// Problem constants (fixed by reference)
#define DMODEL 1024
#define HEADS  16
#define DH     64
#define BATCH  4
#define SEQ    4096
#define ROWS   (BATCH * SEQ)   // 16384
#define KSPLIT 8
#define EPSV   1e-6f

// GEMM tiling (HMMA mma.sync path; tcgen05 is unavailable on compute_103 virtual arch)
#define BM 128
#define BN 128
#define BK 64
#define NCH (DMODEL / BK)      // 16 k-chunks
#define GTHREADS 256

// smem stage layout (bytes): four 16KB planes of bf16 [rows][64] w/ 128B rows
#define A_HI 0
#define A_LO 16384
#define B_HI 32768
#define B_LO 49152
#define STAGE 65536
#define SMEM_BYTES (2 * STAGE)   // 128KB dynamic

// ---------------- scratch (device globals; no allocation allowed) ------------
__device__ float g_Q[ROWS * DMODEL];
__device__ float g_K[ROWS * DMODEL];
__device__ float g_V[ROWS * DMODEL];
__device__ float g_S[ROWS * DMODEL];
__device__ float g_kvp[BATCH * HEADS * KSPLIT * DH * DH];
__device__ float g_zp [BATCH * HEADS * KSPLIT * DH];
__device__ float g_kv [BATCH * HEADS * DH * DH];
__device__ float g_z  [BATCH * HEADS * DH];

// =============================== helpers ====================================
__device__ __forceinline__ uint32_t smem_u32(const void* p) {
    uint32_t a;
    asm("{ .reg .u64 t; cvta.to.shared.u64 t, %1; cvt.u32.u64 %0, t; }"
        : "=r"(a) : "l"(p));
    return a;
}

__device__ __forceinline__ void ldsm4(uint32_t& r0, uint32_t& r1, uint32_t& r2,
                                      uint32_t& r3, uint32_t addr) {
    asm volatile("ldmatrix.sync.aligned.m8n8.x4.shared.b16 {%0,%1,%2,%3}, [%4];"
                 : "=r"(r0), "=r"(r1), "=r"(r2), "=r"(r3) : "r"(addr));
}

__device__ __forceinline__ void mma_bf16(float* c, const uint32_t* a, const uint32_t* b) {
    asm volatile(
        "mma.sync.aligned.m16n8k16.row.col.f32.bf16.bf16.f32 "
        "{%0,%1,%2,%3}, {%4,%5,%6,%7}, {%8,%9}, {%0,%1,%2,%3};"
        : "+f"(c[0]), "+f"(c[1]), "+f"(c[2]), "+f"(c[3])
        : "r"(a[0]), "r"(a[1]), "r"(a[2]), "r"(a[3]), "r"(b[0]), "r"(b[1]));
}

// float4 -> packed bf16 hi (uint2) and residual lo (uint2)
__device__ __forceinline__ void cvt_split(float4 v, uint2& hi, uint2& lo) {
    __nv_bfloat16 hx = __float2bfloat16(v.x);
    __nv_bfloat16 hy = __float2bfloat16(v.y);
    __nv_bfloat16 hz = __float2bfloat16(v.z);
    __nv_bfloat16 hw = __float2bfloat16(v.w);
    __nv_bfloat16 lx = __float2bfloat16(v.x - __bfloat162float(hx));
    __nv_bfloat16 ly = __float2bfloat16(v.y - __bfloat162float(hy));
    __nv_bfloat16 lz = __float2bfloat16(v.z - __bfloat162float(hz));
    __nv_bfloat16 lw = __float2bfloat16(v.w - __bfloat162float(hw));
    __nv_bfloat162 h01, h23, l01, l23;
    h01.x = hx; h01.y = hy; h23.x = hz; h23.y = hw;
    l01.x = lx; l01.y = ly; l23.x = lz; l23.y = lw;
    hi = make_uint2(*(uint32_t*)&h01, *(uint32_t*)&h23);
    lo = make_uint2(*(uint32_t*)&l01, *(uint32_t*)&l23);
}

// =============================================================================
// GEMM (NT) via HMMA: Y[r][c] = sum_k X[r][k]*W[c][k] + bias[c], optional phi.
// bf16x3 split: hh + hl + lh  (~1e-5 relative error).
// CTA tile 128x128x64(f32 k). 8 warps (4m x 2n), warp tile 32x64.
// Double-buffered smem; gmem->reg prefetch overlaps MMA.
// =============================================================================
template<bool PHI>
__global__ __launch_bounds__(GTHREADS, 1)
void gemm_hmma(const float* __restrict__ X, const float* __restrict__ W,
               const float* __restrict__ bias, float* __restrict__ Y) {
    extern __shared__ char sm[];
    const uint32_t sbase = smem_u32(sm);
    const int tid = threadIdx.x;
    const int lane = tid & 31;
    const int wid = tid >> 5;
    const int wm = wid & 3;          // 0..3  (m group of 32 rows)
    const int wn = wid >> 2;         // 0..1  (n group of 64 cols)
    const int bm = blockIdx.y;
    const int bn = blockIdx.x;

    // ---- loader mapping: 2 threads per row, each 32 f32 (8 float4) ----
    const int srow = tid >> 1;                 // 0..127
    const int scol = (tid & 1) * 32;           // f32 col base
    const float* Ag = X + (size_t)(bm * BM + srow) * DMODEL + scol;
    const float* Bg = W + (size_t)(bn * BN + srow) * DMODEL + scol;

    const uint32_t smask = (uint32_t)((srow & 7) << 4);
    uint32_t st_off[8];
    #pragma unroll
    for (int i = 0; i < 8; i++) {
        uint32_t c2 = (uint32_t)((tid & 1) * 64 + i * 8);   // byte col in row
        st_off[i] = (uint32_t)(srow * 128) + (c2 ^ smask);
    }

    // ---- ldmatrix address precompute ----
    // A: rows wm*32 + mt*16 + (lane&15), col-bytes ks*32 + (lane>>4)*16
    int row_a[2];
    row_a[0] = wm * 32 + (lane & 15);
    row_a[1] = row_a[0] + 16;
    const uint32_t a_colb = (uint32_t)((lane >> 4) << 4);
    uint32_t a_base[2], a_mask[2];
    #pragma unroll
    for (int mt = 0; mt < 2; mt++) {
        a_base[mt] = (uint32_t)(row_a[mt] * 128);
        a_mask[mt] = (uint32_t)((row_a[mt] & 7) << 4);
    }
    // B: n-rows wn*64 + ntp*16 + (lane&7) + ((lane>>4)<<3), col-bytes ks*32 + ((lane&8)?16:0)
    int nrow[4];
    #pragma unroll
    for (int ntp = 0; ntp < 4; ntp++)
        nrow[ntp] = wn * 64 + ntp * 16 + (lane & 7) + ((lane >> 4) << 3);
    const uint32_t b_colb = (lane & 8) ? 16u : 0u;
    uint32_t b_base[4], b_mask[4];
    #pragma unroll
    for (int ntp = 0; ntp < 4; ntp++) {
        b_base[ntp] = (uint32_t)(nrow[ntp] * 128);
        b_mask[ntp] = (uint32_t)((nrow[ntp] & 7) << 4);
    }

    float acc[2][8][4];
    #pragma unroll
    for (int mt = 0; mt < 2; mt++)
        #pragma unroll
        for (int nt = 0; nt < 8; nt++)
            #pragma unroll
            for (int i = 0; i < 4; i++) acc[mt][nt][i] = 0.f;

    float4 preA[8], preB[8];

    // prologue: chunk 0 -> stage 0
    #pragma unroll
    for (int i = 0; i < 8; i++) {
        preA[i] = *(const float4*)(Ag + i * 4);
        preB[i] = *(const float4*)(Bg + i * 4);
    }
    #pragma unroll
    for (int i = 0; i < 8; i++) {
        uint2 hi, lo;
        cvt_split(preA[i], hi, lo);
        *(uint2*)(sm + A_HI + st_off[i]) = hi;
        *(uint2*)(sm + A_LO + st_off[i]) = lo;
        cvt_split(preB[i], hi, lo);
        *(uint2*)(sm + B_HI + st_off[i]) = hi;
        *(uint2*)(sm + B_LO + st_off[i]) = lo;
    }
    __syncthreads();
    // prefetch chunk 1
    #pragma unroll
    for (int i = 0; i < 8; i++) {
        preA[i] = *(const float4*)(Ag + BK + i * 4);
        preB[i] = *(const float4*)(Bg + BK + i * 4);
    }

    for (int c = 0; c < NCH; c++) {
        const int s = c & 1;
        const uint32_t stg = sbase + (uint32_t)(s * STAGE);

        // store prefetched chunk c+1 into the other stage
        if (c + 1 < NCH) {
            char* dst = sm + (s ^ 1) * STAGE;
            #pragma unroll
            for (int i = 0; i < 8; i++) {
                uint2 hi, lo;
                cvt_split(preA[i], hi, lo);
                *(uint2*)(dst + A_HI + st_off[i]) = hi;
                *(uint2*)(dst + A_LO + st_off[i]) = lo;
                cvt_split(preB[i], hi, lo);
                *(uint2*)(dst + B_HI + st_off[i]) = hi;
                *(uint2*)(dst + B_LO + st_off[i]) = lo;
            }
        }
        // issue gmem loads for chunk c+2 (latency hides under MMA below)
        if (c + 2 < NCH) {
            const float* Ap = Ag + (c + 2) * BK;
            const float* Bp = Bg + (c + 2) * BK;
            #pragma unroll
            for (int i = 0; i < 8; i++) {
                preA[i] = *(const float4*)(Ap + i * 4);
                preB[i] = *(const float4*)(Bp + i * 4);
            }
        }

        // compute on stage s
        #pragma unroll
        for (int ks = 0; ks < 4; ks++) {
            const uint32_t kb = (uint32_t)(ks * 32);
            uint32_t Ah[2][4], Al[2][4];
            #pragma unroll
            for (int mt = 0; mt < 2; mt++) {
                uint32_t off = a_base[mt] + ((kb + a_colb) ^ a_mask[mt]);
                ldsm4(Ah[mt][0], Ah[mt][1], Ah[mt][2], Ah[mt][3], stg + A_HI + off);
                ldsm4(Al[mt][0], Al[mt][1], Al[mt][2], Al[mt][3], stg + A_LO + off);
            }
            uint32_t Bh[8][2], Bl[8][2];
            #pragma unroll
            for (int ntp = 0; ntp < 4; ntp++) {
                uint32_t off = b_base[ntp] + ((kb + b_colb) ^ b_mask[ntp]);
                ldsm4(Bh[2 * ntp][0], Bh[2 * ntp][1], Bh[2 * ntp + 1][0], Bh[2 * ntp + 1][1],
                      stg + B_HI + off);
                ldsm4(Bl[2 * ntp][0], Bl[2 * ntp][1], Bl[2 * ntp + 1][0], Bl[2 * ntp + 1][1],
                      stg + B_LO + off);
            }
            #pragma unroll
            for (int mt = 0; mt < 2; mt++)
                #pragma unroll
                for (int nt = 0; nt < 8; nt++) {
                    mma_bf16(acc[mt][nt], Ah[mt], Bh[nt]);
                    mma_bf16(acc[mt][nt], Ah[mt], Bl[nt]);
                    mma_bf16(acc[mt][nt], Al[mt], Bh[nt]);
                }
        }
        __syncthreads();
    }

    // ---- epilogue ----
    const int lr = lane >> 2;        // 0..7
    const int lc = lane & 3;         // 0..3
    #pragma unroll
    for (int mt = 0; mt < 2; mt++) {
        const int gr0 = bm * BM + wm * 32 + mt * 16 + lr;
        #pragma unroll
        for (int nt = 0; nt < 8; nt++) {
            const int gc = bn * BN + wn * 64 + nt * 8 + lc * 2;
            const float b0 = __ldg(&bias[gc]);
            const float b1 = __ldg(&bias[gc + 1]);
            float o00 = acc[mt][nt][0] + b0;
            float o01 = acc[mt][nt][1] + b1;
            float o10 = acc[mt][nt][2] + b0;
            float o11 = acc[mt][nt][3] + b1;
            if (PHI) {
                o00 = (o00 > 0.f) ? (o00 + 1.f) : __expf(o00);
                o01 = (o01 > 0.f) ? (o01 + 1.f) : __expf(o01);
                o10 = (o10 > 0.f) ? (o10 + 1.f) : __expf(o10);
                o11 = (o11 > 0.f) ? (o11 + 1.f) : __expf(o11);
            }
            *(float2*)(Y + (size_t)gr0 * DMODEL + gc)       = make_float2(o00, o01);
            *(float2*)(Y + (size_t)(gr0 + 8) * DMODEL + gc) = make_float2(o10, o11);
        }
    }
}

// =============================================================================
// kv partial:  per (b,h,split) block compute KV[d][e] += K[m][d]*V[m][e],
// z[d] += K[m][d] over a 512-row m chunk.
// =============================================================================
__global__ __launch_bounds__(256)
void kv_partial(const float* __restrict__ K, const float* __restrict__ V,
                float* __restrict__ kvp, float* __restrict__ zp) {
    const int tid = threadIdx.x;
    const int s  = blockIdx.x % KSPLIT;
    const int bh = blockIdx.x / KSPLIT;
    const int b = bh / HEADS, h = bh % HEADS;

    __shared__ __align__(16) float Ks[64][64];
    __shared__ __align__(16) float Vs[64][64];

    const int d0 = (tid >> 4) * 4;
    const int e0 = (tid & 15) * 4;
    float acc[4][4] = {};
    float zacc[4] = {};

    const size_t base = (size_t)b * SEQ * DMODEL + (size_t)h * DH;
    const int m_begin = s * (SEQ / KSPLIT);
    const int m_end   = m_begin + (SEQ / KSPLIT);

    for (int m0 = m_begin; m0 < m_end; m0 += 64) {
        float4 kreg[4], vreg[4];
        #pragma unroll
        for (int t = 0; t < 4; t++) {
            int lin = tid + t * 256;
            int r = lin >> 4, c4 = (lin & 15) * 4;
            kreg[t] = *(const float4*)&K[base + (size_t)(m0 + r) * DMODEL + c4];
            vreg[t] = *(const float4*)&V[base + (size_t)(m0 + r) * DMODEL + c4];
        }
        __syncthreads();
        #pragma unroll
        for (int t = 0; t < 4; t++) {
            int lin = tid + t * 256;
            int r = lin >> 4, c4 = (lin & 15) * 4;
            *(float4*)&Ks[r][c4] = kreg[t];
            *(float4*)&Vs[r][c4] = vreg[t];
        }
        __syncthreads();

        #pragma unroll 4
        for (int mm = 0; mm < 64; mm++) {
            float4 k4 = *(const float4*)&Ks[mm][d0];
            float4 v4 = *(const float4*)&Vs[mm][e0];
            float kk[4] = {k4.x, k4.y, k4.z, k4.w};
            float vv[4] = {v4.x, v4.y, v4.z, v4.w};
            #pragma unroll
            for (int i = 0; i < 4; i++)
                #pragma unroll
                for (int j = 0; j < 4; j++)
                    acc[i][j] += kk[i] * vv[j];
            if ((tid & 15) == 0) {
                #pragma unroll
                for (int i = 0; i < 4; i++) zacc[i] += kk[i];
            }
        }
    }

    float* kout = kvp + (size_t)blockIdx.x * (DH * DH);
    #pragma unroll
    for (int i = 0; i < 4; i++)
        *(float4*)&kout[(d0 + i) * DH + e0] = make_float4(acc[i][0], acc[i][1], acc[i][2], acc[i][3]);
    if ((tid & 15) == 0) {
        #pragma unroll
        for (int i = 0; i < 4; i++) zp[(size_t)blockIdx.x * DH + d0 + i] = zacc[i];
    }
}

__global__ __launch_bounds__(256)
void kv_reduce(const float* __restrict__ kvp, const float* __restrict__ zp,
               float* __restrict__ kvo, float* __restrict__ zo) {
    const int bh = blockIdx.x;
    const int tid = threadIdx.x;
    for (int i = tid; i < DH * DH; i += 256) {
        float sum = 0.f;
        #pragma unroll
        for (int s = 0; s < KSPLIT; s++)
            sum += kvp[((size_t)bh * KSPLIT + s) * (DH * DH) + i];
        kvo[(size_t)bh * (DH * DH) + i] = sum;
    }
    if (tid < DH) {
        float sum = 0.f;
        #pragma unroll
        for (int s = 0; s < KSPLIT; s++)
            sum += zp[((size_t)bh * KSPLIT + s) * DH + tid];
        zo[(size_t)bh * DH + tid] = sum;
    }
}

// =============================================================================
// attn:  S[n][h*64+e] = (sum_d Q[n][h*64+d]*kv[bh][d][e]) / (sum_d Q*z + eps)
// =============================================================================
__global__ __launch_bounds__(256)
void attn(const float* __restrict__ Q, const float* __restrict__ kv,
          const float* __restrict__ z, float* __restrict__ S) {
    const int tid = threadIdx.x;
    const int row0 = blockIdx.x * 64;
    const int b = row0 / SEQ;

    __shared__ __align__(16) float qs[64][64];
    __shared__ __align__(16) float kvs[64][64];
    __shared__ __align__(16) float zs[64];
    __shared__ float dens[64];

    const int r0 = (tid >> 4) * 4;
    const int e0 = (tid & 15) * 4;

    for (int h = 0; h < HEADS; h++) {
        const int bh = b * HEADS + h;
        __syncthreads();
        #pragma unroll
        for (int t = 0; t < 4; t++) {
            int lin = tid + t * 256;
            int r = lin >> 4, c4 = (lin & 15) * 4;
            *(float4*)&qs[r][c4] =
                *(const float4*)&Q[(size_t)(row0 + r) * DMODEL + h * DH + c4];
            ((float4*)&kvs[0][0])[lin] =
                ((const float4*)(kv + (size_t)bh * DH * DH))[lin];
        }
        if (tid < 16)
            ((float4*)zs)[tid] = ((const float4*)(z + (size_t)bh * DH))[tid];
        __syncthreads();

        if (tid < 64) {
            float sden = 0.f;
            #pragma unroll 8
            for (int d = 0; d < 64; d++) sden += qs[tid][d] * zs[d];
            dens[tid] = sden + EPSV;
        }
        __syncthreads();

        float acc[4][4] = {};
        #pragma unroll 4
        for (int d = 0; d < 64; d++) {
            float4 k4 = *(const float4*)&kvs[d][e0];
            float kk[4] = {k4.x, k4.y, k4.z, k4.w};
            #pragma unroll
            for (int i = 0; i < 4; i++) {
                float qv = qs[r0 + i][d];
                #pragma unroll
                for (int j = 0; j < 4; j++) acc[i][j] += qv * kk[j];
            }
        }
        #pragma unroll
        for (int i = 0; i < 4; i++) {
            float rinv = 1.0f / dens[r0 + i];
            float* sp = S + (size_t)(row0 + r0 + i) * DMODEL + h * DH + e0;
            *(float4*)sp = make_float4(acc[i][0] * rinv, acc[i][1] * rinv,
                                       acc[i][2] * rinv, acc[i][3] * rinv);
        }
    }
}

// =============================================================================
extern "C" void kernel_launch(void* const* d_in, const int* in_sizes, int n_in,
                              void* d_out, int out_size) {
    const float* queries = (const float*)d_in[0];
    const float* keys    = (const float*)d_in[1];
    const float* values  = (const float*)d_in[2];
    const float* wq = (const float*)d_in[3];
    const float* bq = (const float*)d_in[4];
    const float* wk = (const float*)d_in[5];
    const float* bk = (const float*)d_in[6];
    const float* wv = (const float*)d_in[7];
    const float* bv = (const float*)d_in[8];
    const float* wo = (const float*)d_in[9];
    const float* bo = (const float*)d_in[10];
    float* out = (float*)d_out;

    float *Q, *K, *V, *S, *kvp, *zp, *kvb, *zb;
    cudaGetSymbolAddress((void**)&Q,   g_Q);
    cudaGetSymbolAddress((void**)&K,   g_K);
    cudaGetSymbolAddress((void**)&V,   g_V);
    cudaGetSymbolAddress((void**)&S,   g_S);
    cudaGetSymbolAddress((void**)&kvp, g_kvp);
    cudaGetSymbolAddress((void**)&zp,  g_zp);
    cudaGetSymbolAddress((void**)&kvb, g_kv);
    cudaGetSymbolAddress((void**)&zb,  g_z);

    cudaFuncSetAttribute(gemm_hmma<true >, cudaFuncAttributeMaxDynamicSharedMemorySize, SMEM_BYTES);
    cudaFuncSetAttribute(gemm_hmma<false>, cudaFuncAttributeMaxDynamicSharedMemorySize, SMEM_BYTES);

    dim3 gg(DMODEL / BN, ROWS / BM);   // (8, 128)
    dim3 gb(GTHREADS);

    gemm_hmma<true ><<<gg, gb, SMEM_BYTES>>>(queries, wq, bq, Q);
    gemm_hmma<true ><<<gg, gb, SMEM_BYTES>>>(keys,    wk, bk, K);
    gemm_hmma<false><<<gg, gb, SMEM_BYTES>>>(values,  wv, bv, V);
    kv_partial<<<BATCH * HEADS * KSPLIT, 256>>>(K, V, kvp, zp);
    kv_reduce <<<BATCH * HEADS, 256>>>(kvp, zp, kvb, zb);
    attn      <<<ROWS / 64, 256>>>(Q, kvb, zb, S);
    gemm_hmma<false><<<gg, gb, SMEM_BYTES>>>(S, wo, bo, out);
}

// round 4
// speedup vs baseline: 2.7408x; 1.2716x over previous
#include <cuda_runtime.h>
#include <cuda_bf16.h>
#include <cstdint>

// Problem constants (fixed by reference)
#define DMODEL 1024
#define HEADS  16
#define DH     64
#define BATCH  4
#define SEQ    4096
#define ROWS   (BATCH * SEQ)   // 16384
#define KSPLIT 8
#define EPSV   1e-6f

// GEMM tiling (HMMA mma.sync; tcgen05 unavailable on compute_103 virtual arch)
#define BM 128
#define BN 128
#define BK 64                   // k-values per chunk (bf16) = 128B rows
#define NCH (DMODEL / BK)       // 16 chunks
#define GTHREADS 256
#define STAGES 3

// smem stage layout (bytes): four 16KB planes of bf16 [128 rows][128B]
#define A_HI 0
#define A_LO 16384
#define B_HI 32768
#define B_LO 49152
#define STAGE 65536
#define SMEM_BYTES (STAGES * STAGE)   // 192KB dynamic

// ---------------- scratch (device globals; no allocation allowed) ------------
__device__ float g_Q[ROWS * DMODEL];
__device__ float g_K[ROWS * DMODEL];
__device__ float g_V[ROWS * DMODEL];
__device__ __nv_bfloat16 g_Ah[ROWS * DMODEL];     // activation hi plane (reused)
__device__ __nv_bfloat16 g_Al[ROWS * DMODEL];     // activation lo plane (reused)
__device__ __nv_bfloat16 g_Wh[4 * DMODEL * DMODEL]; // wq,wk,wv,wo hi planes
__device__ __nv_bfloat16 g_Wl[4 * DMODEL * DMODEL]; // lo planes
__device__ float g_kvp[BATCH * HEADS * KSPLIT * DH * DH];
__device__ float g_zp [BATCH * HEADS * KSPLIT * DH];
__device__ float g_kv [BATCH * HEADS * DH * DH];
__device__ float g_z  [BATCH * HEADS * DH];

// =============================== helpers ====================================
__device__ __forceinline__ uint32_t smem_u32(const void* p) {
    uint32_t a;
    asm("{ .reg .u64 t; cvta.to.shared.u64 t, %1; cvt.u32.u64 %0, t; }"
        : "=r"(a) : "l"(p));
    return a;
}
__device__ __forceinline__ void ldsm4(uint32_t& r0, uint32_t& r1, uint32_t& r2,
                                      uint32_t& r3, uint32_t addr) {
    asm volatile("ldmatrix.sync.aligned.m8n8.x4.shared.b16 {%0,%1,%2,%3}, [%4];"
                 : "=r"(r0), "=r"(r1), "=r"(r2), "=r"(r3) : "r"(addr));
}
__device__ __forceinline__ void mma_bf16(float* c, const uint32_t* a, const uint32_t* b) {
    asm volatile(
        "mma.sync.aligned.m16n8k16.row.col.f32.bf16.bf16.f32 "
        "{%0,%1,%2,%3}, {%4,%5,%6,%7}, {%8,%9}, {%0,%1,%2,%3};"
        : "+f"(c[0]), "+f"(c[1]), "+f"(c[2]), "+f"(c[3])
        : "r"(a[0]), "r"(a[1]), "r"(a[2]), "r"(a[3]), "r"(b[0]), "r"(b[1]));
}
__device__ __forceinline__ void cp16(uint32_t smem_dst, const void* gsrc) {
    asm volatile("cp.async.cg.shared.global [%0], [%1], 16;"
                 :: "r"(smem_dst), "l"(gsrc));
}
__device__ __forceinline__ void cp_commit() {
    asm volatile("cp.async.commit_group;" ::: "memory");
}
template<int N>
__device__ __forceinline__ void cp_wait() {
    asm volatile("cp.async.wait_group %0;" :: "n"(N) : "memory");
}

// float4 -> packed bf16 hi (uint2) and residual lo (uint2)
__device__ __forceinline__ void cvt_split(float4 v, uint2& hi, uint2& lo) {
    __nv_bfloat16 hx = __float2bfloat16(v.x);
    __nv_bfloat16 hy = __float2bfloat16(v.y);
    __nv_bfloat16 hz = __float2bfloat16(v.z);
    __nv_bfloat16 hw = __float2bfloat16(v.w);
    __nv_bfloat16 lx = __float2bfloat16(v.x - __bfloat162float(hx));
    __nv_bfloat16 ly = __float2bfloat16(v.y - __bfloat162float(hy));
    __nv_bfloat16 lz = __float2bfloat16(v.z - __bfloat162float(hz));
    __nv_bfloat16 lw = __float2bfloat16(v.w - __bfloat162float(hw));
    __nv_bfloat162 h01, h23, l01, l23;
    h01.x = hx; h01.y = hy; h23.x = hz; h23.y = hw;
    l01.x = lx; l01.y = ly; l23.x = lz; l23.y = lw;
    hi = make_uint2(*(uint32_t*)&h01, *(uint32_t*)&h23);
    lo = make_uint2(*(uint32_t*)&l01, *(uint32_t*)&l23);
}

// =============================================================================
// fp32 -> (bf16 hi, bf16 lo) plane conversion, vectorized, grid-stride
// =============================================================================
__global__ __launch_bounds__(256)
void cvt_pair(const float* __restrict__ src, __nv_bfloat16* __restrict__ hi,
              __nv_bfloat16* __restrict__ lo, int n4) {
    for (int i = blockIdx.x * 256 + threadIdx.x; i < n4; i += gridDim.x * 256) {
        float4 v = ((const float4*)src)[i];
        uint2 h, l;
        cvt_split(v, h, l);
        ((uint2*)hi)[i] = h;
        ((uint2*)lo)[i] = l;
    }
}

// =============================================================================
// GEMM (NT) via HMMA on pre-split bf16 planes:
//   Y[r][c] = sum_k (Ah+Al)[r][k] * (Bh+Bl)[c][k] + bias[c], optional phi.
// bf16x3: hh + hl + lh. CTA 128x128, 8 warps (4m x 2n), warp tile 32x64.
// 3-stage cp.async pipeline gmem->smem.
// =============================================================================
template<bool PHI>
__global__ __launch_bounds__(GTHREADS, 1)
void gemm_bf16(const __nv_bfloat16* __restrict__ Ah, const __nv_bfloat16* __restrict__ Al,
               const __nv_bfloat16* __restrict__ Bh, const __nv_bfloat16* __restrict__ Bl,
               const float* __restrict__ bias, float* __restrict__ Y) {
    extern __shared__ char sm[];
    const uint32_t sbase = smem_u32(sm);
    const int tid = threadIdx.x;
    const int lane = tid & 31;
    const int wid = tid >> 5;
    const int wm = wid & 3;          // m group of 32 rows
    const int wn = wid >> 2;         // n group of 64 cols
    const int bm = blockIdx.y;
    const int bn = blockIdx.x;

    // ---- cp.async loader mapping: 2 threads/row, each 4x16B ----
    const int srow = tid >> 1;                 // 0..127
    const int half = tid & 1;
    // gmem byte offsets (row stride = DMODEL*2 bytes)
    const char* gAh = (const char*)(Ah + (size_t)(bm * BM + srow) * DMODEL) + half * 64;
    const char* gAl = (const char*)(Al + (size_t)(bm * BM + srow) * DMODEL) + half * 64;
    const char* gBh = (const char*)(Bh + (size_t)(bn * BN + srow) * DMODEL) + half * 64;
    const char* gBl = (const char*)(Bl + (size_t)(bn * BN + srow) * DMODEL) + half * 64;
    // swizzled smem offsets within a plane
    uint32_t so[4];
    const uint32_t smask = (uint32_t)((srow & 7) << 4);
    #pragma unroll
    for (int j = 0; j < 4; j++)
        so[j] = (uint32_t)(srow * 128) + (((uint32_t)(half * 64 + j * 16)) ^ smask);

    // ---- ldmatrix address precompute (same as proven R3 layout) ----
    int row_a[2];
    row_a[0] = wm * 32 + (lane & 15);
    row_a[1] = row_a[0] + 16;
    const uint32_t a_colb = (uint32_t)((lane >> 4) << 4);
    uint32_t a_base[2], a_mask[2];
    #pragma unroll
    for (int mt = 0; mt < 2; mt++) {
        a_base[mt] = (uint32_t)(row_a[mt] * 128);
        a_mask[mt] = (uint32_t)((row_a[mt] & 7) << 4);
    }
    int nrow[4];
    #pragma unroll
    for (int ntp = 0; ntp < 4; ntp++)
        nrow[ntp] = wn * 64 + ntp * 16 + (lane & 7) + ((lane >> 4) << 3);
    const uint32_t b_colb = (lane & 8) ? 16u : 0u;
    uint32_t b_base[4], b_mask[4];
    #pragma unroll
    for (int ntp = 0; ntp < 4; ntp++) {
        b_base[ntp] = (uint32_t)(nrow[ntp] * 128);
        b_mask[ntp] = (uint32_t)((nrow[ntp] & 7) << 4);
    }

    float acc[2][8][4];
    #pragma unroll
    for (int mt = 0; mt < 2; mt++)
        #pragma unroll
        for (int nt = 0; nt < 8; nt++)
            #pragma unroll
            for (int i = 0; i < 4; i++) acc[mt][nt][i] = 0.f;

    // issue one chunk's cp.asyncs into stage s
    auto issue = [&](int c, int s) {
        const uint32_t stg = sbase + (uint32_t)(s * STAGE);
        const int gb = c * 128;   // byte offset along k
        #pragma unroll
        for (int j = 0; j < 4; j++) cp16(stg + A_HI + so[j], gAh + gb + j * 16);
        #pragma unroll
        for (int j = 0; j < 4; j++) cp16(stg + A_LO + so[j], gAl + gb + j * 16);
        #pragma unroll
        for (int j = 0; j < 4; j++) cp16(stg + B_HI + so[j], gBh + gb + j * 16);
        #pragma unroll
        for (int j = 0; j < 4; j++) cp16(stg + B_LO + so[j], gBl + gb + j * 16);
        cp_commit();
    };

    issue(0, 0);
    issue(1, 1);

    for (int c = 0; c < NCH; c++) {
        if (c + 2 < NCH) cp_wait<1>(); else cp_wait<0>();
        __syncthreads();
        if (c + 2 < NCH) issue(c + 2, (c + 2) % STAGES);

        const uint32_t stg = sbase + (uint32_t)((c % STAGES) * STAGE);
        #pragma unroll
        for (int ks = 0; ks < 4; ks++) {
            const uint32_t kb = (uint32_t)(ks * 32);
            uint32_t Ahr[2][4], Alr[2][4];
            #pragma unroll
            for (int mt = 0; mt < 2; mt++) {
                uint32_t off = a_base[mt] + ((kb + a_colb) ^ a_mask[mt]);
                ldsm4(Ahr[mt][0], Ahr[mt][1], Ahr[mt][2], Ahr[mt][3], stg + A_HI + off);
                ldsm4(Alr[mt][0], Alr[mt][1], Alr[mt][2], Alr[mt][3], stg + A_LO + off);
            }
            uint32_t Bhr[8][2], Blr[8][2];
            #pragma unroll
            for (int ntp = 0; ntp < 4; ntp++) {
                uint32_t off = b_base[ntp] + ((kb + b_colb) ^ b_mask[ntp]);
                ldsm4(Bhr[2 * ntp][0], Bhr[2 * ntp][1], Bhr[2 * ntp + 1][0], Bhr[2 * ntp + 1][1],
                      stg + B_HI + off);
                ldsm4(Blr[2 * ntp][0], Blr[2 * ntp][1], Blr[2 * ntp + 1][0], Blr[2 * ntp + 1][1],
                      stg + B_LO + off);
            }
            #pragma unroll
            for (int mt = 0; mt < 2; mt++)
                #pragma unroll
                for (int nt = 0; nt < 8; nt++) {
                    mma_bf16(acc[mt][nt], Ahr[mt], Bhr[nt]);
                    mma_bf16(acc[mt][nt], Ahr[mt], Blr[nt]);
                    mma_bf16(acc[mt][nt], Alr[mt], Bhr[nt]);
                }
        }
        __syncthreads();
    }

    // ---- epilogue ----
    const int lr = lane >> 2;
    const int lc = lane & 3;
    #pragma unroll
    for (int mt = 0; mt < 2; mt++) {
        const int gr0 = bm * BM + wm * 32 + mt * 16 + lr;
        #pragma unroll
        for (int nt = 0; nt < 8; nt++) {
            const int gc = bn * BN + wn * 64 + nt * 8 + lc * 2;
            const float b0 = __ldg(&bias[gc]);
            const float b1 = __ldg(&bias[gc + 1]);
            float o00 = acc[mt][nt][0] + b0;
            float o01 = acc[mt][nt][1] + b1;
            float o10 = acc[mt][nt][2] + b0;
            float o11 = acc[mt][nt][3] + b1;
            if (PHI) {
                o00 = (o00 > 0.f) ? (o00 + 1.f) : __expf(o00);
                o01 = (o01 > 0.f) ? (o01 + 1.f) : __expf(o01);
                o10 = (o10 > 0.f) ? (o10 + 1.f) : __expf(o10);
                o11 = (o11 > 0.f) ? (o11 + 1.f) : __expf(o11);
            }
            *(float2*)(Y + (size_t)gr0 * DMODEL + gc)       = make_float2(o00, o01);
            *(float2*)(Y + (size_t)(gr0 + 8) * DMODEL + gc) = make_float2(o10, o11);
        }
    }
}

// =============================================================================
// kv partial:  per (b,h,split) block: KV[d][e] += K[m][d]*V[m][e], z[d] += K[m][d]
// =============================================================================
__global__ __launch_bounds__(256)
void kv_partial(const float* __restrict__ K, const float* __restrict__ V,
                float* __restrict__ kvp, float* __restrict__ zp) {
    const int tid = threadIdx.x;
    const int s  = blockIdx.x % KSPLIT;
    const int bh = blockIdx.x / KSPLIT;
    const int b = bh / HEADS, h = bh % HEADS;

    __shared__ __align__(16) float Ks[64][64];
    __shared__ __align__(16) float Vs[64][64];

    const int d0 = (tid >> 4) * 4;
    const int e0 = (tid & 15) * 4;
    float acc[4][4] = {};
    float zacc[4] = {};

    const size_t base = (size_t)b * SEQ * DMODEL + (size_t)h * DH;
    const int m_begin = s * (SEQ / KSPLIT);
    const int m_end   = m_begin + (SEQ / KSPLIT);

    for (int m0 = m_begin; m0 < m_end; m0 += 64) {
        float4 kreg[4], vreg[4];
        #pragma unroll
        for (int t = 0; t < 4; t++) {
            int lin = tid + t * 256;
            int r = lin >> 4, c4 = (lin & 15) * 4;
            kreg[t] = *(const float4*)&K[base + (size_t)(m0 + r) * DMODEL + c4];
            vreg[t] = *(const float4*)&V[base + (size_t)(m0 + r) * DMODEL + c4];
        }
        __syncthreads();
        #pragma unroll
        for (int t = 0; t < 4; t++) {
            int lin = tid + t * 256;
            int r = lin >> 4, c4 = (lin & 15) * 4;
            *(float4*)&Ks[r][c4] = kreg[t];
            *(float4*)&Vs[r][c4] = vreg[t];
        }
        __syncthreads();

        #pragma unroll 4
        for (int mm = 0; mm < 64; mm++) {
            float4 k4 = *(const float4*)&Ks[mm][d0];
            float4 v4 = *(const float4*)&Vs[mm][e0];
            float kk[4] = {k4.x, k4.y, k4.z, k4.w};
            float vv[4] = {v4.x, v4.y, v4.z, v4.w};
            #pragma unroll
            for (int i = 0; i < 4; i++)
                #pragma unroll
                for (int j = 0; j < 4; j++)
                    acc[i][j] += kk[i] * vv[j];
            if ((tid & 15) == 0) {
                #pragma unroll
                for (int i = 0; i < 4; i++) zacc[i] += kk[i];
            }
        }
    }

    float* kout = kvp + (size_t)blockIdx.x * (DH * DH);
    #pragma unroll
    for (int i = 0; i < 4; i++)
        *(float4*)&kout[(d0 + i) * DH + e0] = make_float4(acc[i][0], acc[i][1], acc[i][2], acc[i][3]);
    if ((tid & 15) == 0) {
        #pragma unroll
        for (int i = 0; i < 4; i++) zp[(size_t)blockIdx.x * DH + d0 + i] = zacc[i];
    }
}

__global__ __launch_bounds__(256)
void kv_reduce(const float* __restrict__ kvp, const float* __restrict__ zp,
               float* __restrict__ kvo, float* __restrict__ zo) {
    const int bh = blockIdx.x;
    const int tid = threadIdx.x;
    for (int i = tid; i < DH * DH; i += 256) {
        float sum = 0.f;
        #pragma unroll
        for (int s = 0; s < KSPLIT; s++)
            sum += kvp[((size_t)bh * KSPLIT + s) * (DH * DH) + i];
        kvo[(size_t)bh * (DH * DH) + i] = sum;
    }
    if (tid < DH) {
        float sum = 0.f;
        #pragma unroll
        for (int s = 0; s < KSPLIT; s++)
            sum += zp[((size_t)bh * KSPLIT + s) * DH + tid];
        zo[(size_t)bh * DH + tid] = sum;
    }
}

// =============================================================================
// attn: S[n][h*64+e] = (sum_d Q[n][h*64+d]*kv[bh][d][e]) / (sum_d Q*z + eps)
// Writes S directly as bf16 hi/lo planes (feeds the output-projection GEMM).
// =============================================================================
__global__ __launch_bounds__(256)
void attn(const float* __restrict__ Q, const float* __restrict__ kv,
          const float* __restrict__ z, __nv_bfloat16* __restrict__ Sh,
          __nv_bfloat16* __restrict__ Sl) {
    const int tid = threadIdx.x;
    const int row0 = blockIdx.x * 64;
    const int b = row0 / SEQ;

    __shared__ __align__(16) float qs[64][64];
    __shared__ __align__(16) float kvs[64][64];
    __shared__ __align__(16) float zs[64];
    __shared__ float dens[64];

    const int r0 = (tid >> 4) * 4;
    const int e0 = (tid & 15) * 4;

    for (int h = 0; h < HEADS; h++) {
        const int bh = b * HEADS + h;
        __syncthreads();
        #pragma unroll
        for (int t = 0; t < 4; t++) {
            int lin = tid + t * 256;
            int r = lin >> 4, c4 = (lin & 15) * 4;
            *(float4*)&qs[r][c4] =
                *(const float4*)&Q[(size_t)(row0 + r) * DMODEL + h * DH + c4];
            ((float4*)&kvs[0][0])[lin] =
                ((const float4*)(kv + (size_t)bh * DH * DH))[lin];
        }
        if (tid < 16)
            ((float4*)zs)[tid] = ((const float4*)(z + (size_t)bh * DH))[tid];
        __syncthreads();

        if (tid < 64) {
            float sden = 0.f;
            #pragma unroll 8
            for (int d = 0; d < 64; d++) sden += qs[tid][d] * zs[d];
            dens[tid] = sden + EPSV;
        }
        __syncthreads();

        float acc[4][4] = {};
        #pragma unroll 4
        for (int d = 0; d < 64; d++) {
            float4 k4 = *(const float4*)&kvs[d][e0];
            float kk[4] = {k4.x, k4.y, k4.z, k4.w};
            #pragma unroll
            for (int i = 0; i < 4; i++) {
                float qv = qs[r0 + i][d];
                #pragma unroll
                for (int j = 0; j < 4; j++) acc[i][j] += qv * kk[j];
            }
        }
        #pragma unroll
        for (int i = 0; i < 4; i++) {
            float rinv = 1.0f / dens[r0 + i];
            float4 v = make_float4(acc[i][0] * rinv, acc[i][1] * rinv,
                                   acc[i][2] * rinv, acc[i][3] * rinv);
            uint2 hp, lp;
            cvt_split(v, hp, lp);
            const size_t idx = (size_t)(row0 + r0 + i) * DMODEL + h * DH + e0;
            *(uint2*)(Sh + idx) = hp;
            *(uint2*)(Sl + idx) = lp;
        }
    }
}

// =============================================================================
extern "C" void kernel_launch(void* const* d_in, const int* in_sizes, int n_in,
                              void* d_out, int out_size) {
    const float* queries = (const float*)d_in[0];
    const float* keys    = (const float*)d_in[1];
    const float* values  = (const float*)d_in[2];
    const float* wq = (const float*)d_in[3];
    const float* bq = (const float*)d_in[4];
    const float* wk = (const float*)d_in[5];
    const float* bk = (const float*)d_in[6];
    const float* wv = (const float*)d_in[7];
    const float* bv = (const float*)d_in[8];
    const float* wo = (const float*)d_in[9];
    const float* bo = (const float*)d_in[10];
    float* out = (float*)d_out;

    float *Q, *K, *V, *kvp, *zp, *kvb, *zb;
    __nv_bfloat16 *Ahp, *Alp, *Whp, *Wlp;
    cudaGetSymbolAddress((void**)&Q,   g_Q);
    cudaGetSymbolAddress((void**)&K,   g_K);
    cudaGetSymbolAddress((void**)&V,   g_V);
    cudaGetSymbolAddress((void**)&Ahp, g_Ah);
    cudaGetSymbolAddress((void**)&Alp, g_Al);
    cudaGetSymbolAddress((void**)&Whp, g_Wh);
    cudaGetSymbolAddress((void**)&Wlp, g_Wl);
    cudaGetSymbolAddress((void**)&kvp, g_kvp);
    cudaGetSymbolAddress((void**)&zp,  g_zp);
    cudaGetSymbolAddress((void**)&kvb, g_kv);
    cudaGetSymbolAddress((void**)&zb,  g_z);

    cudaFuncSetAttribute(gemm_bf16<true >, cudaFuncAttributeMaxDynamicSharedMemorySize, SMEM_BYTES);
    cudaFuncSetAttribute(gemm_bf16<false>, cudaFuncAttributeMaxDynamicSharedMemorySize, SMEM_BYTES);

    const int WSZ = DMODEL * DMODEL;       // 1M elems per weight
    const int XN4 = ROWS * DMODEL / 4;     // 4.19M float4 per activation
    const int WN4 = WSZ / 4;

    dim3 gg(DMODEL / BN, ROWS / BM);       // (8, 128)
    dim3 gb(GTHREADS);

    // weights -> bf16 hi/lo planes (once)
    cvt_pair<<<512, 256>>>(wq, Whp + 0 * WSZ, Wlp + 0 * WSZ, WN4);
    cvt_pair<<<512, 256>>>(wk, Whp + 1 * WSZ, Wlp + 1 * WSZ, WN4);
    cvt_pair<<<512, 256>>>(wv, Whp + 2 * WSZ, Wlp + 2 * WSZ, WN4);
    cvt_pair<<<512, 256>>>(wo, Whp + 3 * WSZ, Wlp + 3 * WSZ, WN4);

    // Q projection
    cvt_pair<<<4096, 256>>>(queries, Ahp, Alp, XN4);
    gemm_bf16<true ><<<gg, gb, SMEM_BYTES>>>(Ahp, Alp, Whp + 0 * WSZ, Wlp + 0 * WSZ, bq, Q);
    // K projection
    cvt_pair<<<4096, 256>>>(keys, Ahp, Alp, XN4);
    gemm_bf16<true ><<<gg, gb, SMEM_BYTES>>>(Ahp, Alp, Whp + 1 * WSZ, Wlp + 1 * WSZ, bk, K);
    // V projection
    cvt_pair<<<4096, 256>>>(values, Ahp, Alp, XN4);
    gemm_bf16<false><<<gg, gb, SMEM_BYTES>>>(Ahp, Alp, Whp + 2 * WSZ, Wlp + 2 * WSZ, bv, V);

    kv_partial<<<BATCH * HEADS * KSPLIT, 256>>>(K, V, kvp, zp);
    kv_reduce <<<BATCH * HEADS, 256>>>(kvp, zp, kvb, zb);
    attn      <<<ROWS / 64, 256>>>(Q, kvb, zb, Ahp, Alp);   // S -> planes

    // output projection
    gemm_bf16<false><<<gg, gb, SMEM_BYTES>>>(Ahp, Alp, Whp + 3 * WSZ, Wlp + 3 * WSZ, bo, out);
}

// round 5
// speedup vs baseline: 3.5111x; 1.2811x over previous
#include <cuda_runtime.h>
#include <cuda_fp16.h>
#include <cstdint>

// Problem constants (fixed by reference)
#define DMODEL 1024
#define HEADS  16
#define DH     64
#define BATCH  4
#define SEQ    4096
#define ROWS   (BATCH * SEQ)   // 16384
#define KSPLIT 8
#define EPSV   1e-6f

// GEMM tiling (HMMA mma.sync; tcgen05 unavailable on compute_103 virtual arch)
#define BM 128
#define BN 128
#define BK 64                   // k-values per chunk (fp16) = 128B rows
#define NCH (DMODEL / BK)       // 16 chunks
#define GTHREADS 256
#define STAGES 3

// smem stage layout (bytes): three 16KB planes of fp16 [128 rows][128B]
#define A_PL 0
#define B_HI 16384
#define B_LO 32768
#define STAGE 49152
#define SMEM_BYTES (STAGES * STAGE)   // 144KB dynamic

// ---------------- scratch (device globals; no allocation allowed) ------------
__device__ float g_Q[ROWS * DMODEL];
__device__ float g_K[ROWS * DMODEL];
__device__ float g_V[ROWS * DMODEL];
__device__ __half g_A [ROWS * DMODEL];              // activation fp16 plane (reused; also S)
__device__ __half g_Wh[4 * DMODEL * DMODEL];        // wq,wk,wv,wo hi planes
__device__ __half g_Wl[4 * DMODEL * DMODEL];        // lo planes
__device__ float g_kvp[BATCH * HEADS * KSPLIT * DH * DH];
__device__ float g_zp [BATCH * HEADS * KSPLIT * DH];
__device__ float g_kv [BATCH * HEADS * DH * DH];
__device__ float g_z  [BATCH * HEADS * DH];

// =============================== helpers ====================================
__device__ __forceinline__ uint32_t smem_u32(const void* p) {
    uint32_t a;
    asm("{ .reg .u64 t; cvta.to.shared.u64 t, %1; cvt.u32.u64 %0, t; }"
        : "=r"(a) : "l"(p));
    return a;
}
__device__ __forceinline__ void ldsm4(uint32_t& r0, uint32_t& r1, uint32_t& r2,
                                      uint32_t& r3, uint32_t addr) {
    asm volatile("ldmatrix.sync.aligned.m8n8.x4.shared.b16 {%0,%1,%2,%3}, [%4];"
                 : "=r"(r0), "=r"(r1), "=r"(r2), "=r"(r3) : "r"(addr));
}
__device__ __forceinline__ void mma_fp16(float* c, const uint32_t* a, const uint32_t* b) {
    asm volatile(
        "mma.sync.aligned.m16n8k16.row.col.f32.f16.f16.f32 "
        "{%0,%1,%2,%3}, {%4,%5,%6,%7}, {%8,%9}, {%0,%1,%2,%3};"
        : "+f"(c[0]), "+f"(c[1]), "+f"(c[2]), "+f"(c[3])
        : "r"(a[0]), "r"(a[1]), "r"(a[2]), "r"(a[3]), "r"(b[0]), "r"(b[1]));
}
__device__ __forceinline__ void cp16(uint32_t smem_dst, const void* gsrc) {
    asm volatile("cp.async.cg.shared.global [%0], [%1], 16;"
                 :: "r"(smem_dst), "l"(gsrc));
}
__device__ __forceinline__ void cp_commit() {
    asm volatile("cp.async.commit_group;" ::: "memory");
}
template<int N>
__device__ __forceinline__ void cp_wait() {
    asm volatile("cp.async.wait_group %0;" :: "n"(N) : "memory");
}

// float4 -> packed fp16 (uint2)
__device__ __forceinline__ uint2 cvt_f16x4(float4 v) {
    __half2 p01 = __floats2half2_rn(v.x, v.y);
    __half2 p23 = __floats2half2_rn(v.z, v.w);
    return make_uint2(*(uint32_t*)&p01, *(uint32_t*)&p23);
}
// float4 -> packed fp16 hi (uint2) and residual lo (uint2)
__device__ __forceinline__ void cvt_split_f16(float4 v, uint2& hi, uint2& lo) {
    __half hx = __float2half_rn(v.x);
    __half hy = __float2half_rn(v.y);
    __half hz = __float2half_rn(v.z);
    __half hw = __float2half_rn(v.w);
    __half lx = __float2half_rn(v.x - __half2float(hx));
    __half ly = __float2half_rn(v.y - __half2float(hy));
    __half lz = __float2half_rn(v.z - __half2float(hz));
    __half lw = __float2half_rn(v.w - __half2float(hw));
    __half2 h01, h23, l01, l23;
    h01.x = hx; h01.y = hy; h23.x = hz; h23.y = hw;
    l01.x = lx; l01.y = ly; l23.x = lz; l23.y = lw;
    hi = make_uint2(*(uint32_t*)&h01, *(uint32_t*)&h23);
    lo = make_uint2(*(uint32_t*)&l01, *(uint32_t*)&l23);
}

// =============================================================================
// conversions
// =============================================================================
__global__ __launch_bounds__(256)
void cvt_act(const float* __restrict__ src, __half* __restrict__ dst, int n4) {
    for (int i = blockIdx.x * 256 + threadIdx.x; i < n4; i += gridDim.x * 256)
        ((uint2*)dst)[i] = cvt_f16x4(((const float4*)src)[i]);
}
__global__ __launch_bounds__(256)
void cvt_wpair(const float* __restrict__ src, __half* __restrict__ hi,
               __half* __restrict__ lo, int n4) {
    for (int i = blockIdx.x * 256 + threadIdx.x; i < n4; i += gridDim.x * 256) {
        uint2 h, l;
        cvt_split_f16(((const float4*)src)[i], h, l);
        ((uint2*)hi)[i] = h;
        ((uint2*)lo)[i] = l;
    }
}

// =============================================================================
// GEMM (NT) via HMMA fp16x2:  Y[r][c] = sum_k A[r][k]*(Bh+Bl)[c][k] + bias[c].
// A = fp16-rounded activations (error ~2^-12); Bh+Bl = exact-split weights.
// CTA 128x128, 8 warps (4m x 2n), warp tile 32x64. 3-stage cp.async pipeline.
// =============================================================================
template<bool PHI>
__global__ __launch_bounds__(GTHREADS, 1)
void gemm_f16(const __half* __restrict__ A, const __half* __restrict__ Bh,
              const __half* __restrict__ Bl, const float* __restrict__ bias,
              float* __restrict__ Y) {
    extern __shared__ char sm[];
    const uint32_t sbase = smem_u32(sm);
    const int tid = threadIdx.x;
    const int lane = tid & 31;
    const int wid = tid >> 5;
    const int wm = wid & 3;          // m group of 32 rows
    const int wn = wid >> 2;         // n group of 64 cols
    const int bm = blockIdx.y;
    const int bn = blockIdx.x;

    // ---- cp.async loader mapping: 2 threads/row, each 4x16B per plane ----
    const int srow = tid >> 1;                 // 0..127
    const int half = tid & 1;
    const char* gA  = (const char*)(A  + (size_t)(bm * BM + srow) * DMODEL) + half * 64;
    const char* gBh = (const char*)(Bh + (size_t)(bn * BN + srow) * DMODEL) + half * 64;
    const char* gBl = (const char*)(Bl + (size_t)(bn * BN + srow) * DMODEL) + half * 64;
    uint32_t so[4];
    const uint32_t smask = (uint32_t)((srow & 7) << 4);
    #pragma unroll
    for (int j = 0; j < 4; j++)
        so[j] = (uint32_t)(srow * 128) + (((uint32_t)(half * 64 + j * 16)) ^ smask);

    // ---- ldmatrix address precompute (proven layout) ----
    int row_a[2];
    row_a[0] = wm * 32 + (lane & 15);
    row_a[1] = row_a[0] + 16;
    const uint32_t a_colb = (uint32_t)((lane >> 4) << 4);
    uint32_t a_base[2], a_mask[2];
    #pragma unroll
    for (int mt = 0; mt < 2; mt++) {
        a_base[mt] = (uint32_t)(row_a[mt] * 128);
        a_mask[mt] = (uint32_t)((row_a[mt] & 7) << 4);
    }
    int nrow[4];
    #pragma unroll
    for (int ntp = 0; ntp < 4; ntp++)
        nrow[ntp] = wn * 64 + ntp * 16 + (lane & 7) + ((lane >> 4) << 3);
    const uint32_t b_colb = (lane & 8) ? 16u : 0u;
    uint32_t b_base[4], b_mask[4];
    #pragma unroll
    for (int ntp = 0; ntp < 4; ntp++) {
        b_base[ntp] = (uint32_t)(nrow[ntp] * 128);
        b_mask[ntp] = (uint32_t)((nrow[ntp] & 7) << 4);
    }

    float acc[2][8][4];
    #pragma unroll
    for (int mt = 0; mt < 2; mt++)
        #pragma unroll
        for (int nt = 0; nt < 8; nt++)
            #pragma unroll
            for (int i = 0; i < 4; i++) acc[mt][nt][i] = 0.f;

    auto issue = [&](int c, int s) {
        const uint32_t stg = sbase + (uint32_t)(s * STAGE);
        const int gb = c * 128;   // byte offset along k
        #pragma unroll
        for (int j = 0; j < 4; j++) cp16(stg + A_PL + so[j], gA + gb + j * 16);
        #pragma unroll
        for (int j = 0; j < 4; j++) cp16(stg + B_HI + so[j], gBh + gb + j * 16);
        #pragma unroll
        for (int j = 0; j < 4; j++) cp16(stg + B_LO + so[j], gBl + gb + j * 16);
        cp_commit();
    };

    issue(0, 0);
    issue(1, 1);

    for (int c = 0; c < NCH; c++) {
        if (c + 2 < NCH) cp_wait<1>(); else cp_wait<0>();
        __syncthreads();
        if (c + 2 < NCH) issue(c + 2, (c + 2) % STAGES);

        const uint32_t stg = sbase + (uint32_t)((c % STAGES) * STAGE);
        #pragma unroll
        for (int ks = 0; ks < 4; ks++) {
            const uint32_t kb = (uint32_t)(ks * 32);
            uint32_t Ar[2][4];
            #pragma unroll
            for (int mt = 0; mt < 2; mt++) {
                uint32_t off = a_base[mt] + ((kb + a_colb) ^ a_mask[mt]);
                ldsm4(Ar[mt][0], Ar[mt][1], Ar[mt][2], Ar[mt][3], stg + A_PL + off);
            }
            uint32_t Bhr[8][2], Blr[8][2];
            #pragma unroll
            for (int ntp = 0; ntp < 4; ntp++) {
                uint32_t off = b_base[ntp] + ((kb + b_colb) ^ b_mask[ntp]);
                ldsm4(Bhr[2 * ntp][0], Bhr[2 * ntp][1], Bhr[2 * ntp + 1][0], Bhr[2 * ntp + 1][1],
                      stg + B_HI + off);
                ldsm4(Blr[2 * ntp][0], Blr[2 * ntp][1], Blr[2 * ntp + 1][0], Blr[2 * ntp + 1][1],
                      stg + B_LO + off);
            }
            #pragma unroll
            for (int mt = 0; mt < 2; mt++)
                #pragma unroll
                for (int nt = 0; nt < 8; nt++) {
                    mma_fp16(acc[mt][nt], Ar[mt], Bhr[nt]);
                    mma_fp16(acc[mt][nt], Ar[mt], Blr[nt]);
                }
        }
        __syncthreads();
    }

    // ---- epilogue ----
    const int lr = lane >> 2;
    const int lc = lane & 3;
    #pragma unroll
    for (int mt = 0; mt < 2; mt++) {
        const int gr0 = bm * BM + wm * 32 + mt * 16 + lr;
        #pragma unroll
        for (int nt = 0; nt < 8; nt++) {
            const int gc = bn * BN + wn * 64 + nt * 8 + lc * 2;
            const float b0 = __ldg(&bias[gc]);
            const float b1 = __ldg(&bias[gc + 1]);
            float o00 = acc[mt][nt][0] + b0;
            float o01 = acc[mt][nt][1] + b1;
            float o10 = acc[mt][nt][2] + b0;
            float o11 = acc[mt][nt][3] + b1;
            if (PHI) {
                o00 = (o00 > 0.f) ? (o00 + 1.f) : __expf(o00);
                o01 = (o01 > 0.f) ? (o01 + 1.f) : __expf(o01);
                o10 = (o10 > 0.f) ? (o10 + 1.f) : __expf(o10);
                o11 = (o11 > 0.f) ? (o11 + 1.f) : __expf(o11);
            }
            *(float2*)(Y + (size_t)gr0 * DMODEL + gc)       = make_float2(o00, o01);
            *(float2*)(Y + (size_t)(gr0 + 8) * DMODEL + gc) = make_float2(o10, o11);
        }
    }
}

// =============================================================================
// kv partial:  per (b,h,split) block: KV[d][e] += K[m][d]*V[m][e], z[d] += K[m][d]
// =============================================================================
__global__ __launch_bounds__(256)
void kv_partial(const float* __restrict__ K, const float* __restrict__ V,
                float* __restrict__ kvp, float* __restrict__ zp) {
    const int tid = threadIdx.x;
    const int s  = blockIdx.x % KSPLIT;
    const int bh = blockIdx.x / KSPLIT;
    const int b = bh / HEADS, h = bh % HEADS;

    __shared__ __align__(16) float Ks[64][64];
    __shared__ __align__(16) float Vs[64][64];

    const int d0 = (tid >> 4) * 4;
    const int e0 = (tid & 15) * 4;
    float acc[4][4] = {};
    float zacc[4] = {};

    const size_t base = (size_t)b * SEQ * DMODEL + (size_t)h * DH;
    const int m_begin = s * (SEQ / KSPLIT);
    const int m_end   = m_begin + (SEQ / KSPLIT);

    for (int m0 = m_begin; m0 < m_end; m0 += 64) {
        float4 kreg[4], vreg[4];
        #pragma unroll
        for (int t = 0; t < 4; t++) {
            int lin = tid + t * 256;
            int r = lin >> 4, c4 = (lin & 15) * 4;
            kreg[t] = *(const float4*)&K[base + (size_t)(m0 + r) * DMODEL + c4];
            vreg[t] = *(const float4*)&V[base + (size_t)(m0 + r) * DMODEL + c4];
        }
        __syncthreads();
        #pragma unroll
        for (int t = 0; t < 4; t++) {
            int lin = tid + t * 256;
            int r = lin >> 4, c4 = (lin & 15) * 4;
            *(float4*)&Ks[r][c4] = kreg[t];
            *(float4*)&Vs[r][c4] = vreg[t];
        }
        __syncthreads();

        #pragma unroll 4
        for (int mm = 0; mm < 64; mm++) {
            float4 k4 = *(const float4*)&Ks[mm][d0];
            float4 v4 = *(const float4*)&Vs[mm][e0];
            float kk[4] = {k4.x, k4.y, k4.z, k4.w};
            float vv[4] = {v4.x, v4.y, v4.z, v4.w};
            #pragma unroll
            for (int i = 0; i < 4; i++)
                #pragma unroll
                for (int j = 0; j < 4; j++)
                    acc[i][j] += kk[i] * vv[j];
            if ((tid & 15) == 0) {
                #pragma unroll
                for (int i = 0; i < 4; i++) zacc[i] += kk[i];
            }
        }
    }

    float* kout = kvp + (size_t)blockIdx.x * (DH * DH);
    #pragma unroll
    for (int i = 0; i < 4; i++)
        *(float4*)&kout[(d0 + i) * DH + e0] = make_float4(acc[i][0], acc[i][1], acc[i][2], acc[i][3]);
    if ((tid & 15) == 0) {
        #pragma unroll
        for (int i = 0; i < 4; i++) zp[(size_t)blockIdx.x * DH + d0 + i] = zacc[i];
    }
}

__global__ __launch_bounds__(256)
void kv_reduce(const float* __restrict__ kvp, const float* __restrict__ zp,
               float* __restrict__ kvo, float* __restrict__ zo) {
    const int bh = blockIdx.x;
    const int tid = threadIdx.x;
    for (int i = tid; i < DH * DH; i += 256) {
        float sum = 0.f;
        #pragma unroll
        for (int s = 0; s < KSPLIT; s++)
            sum += kvp[((size_t)bh * KSPLIT + s) * (DH * DH) + i];
        kvo[(size_t)bh * (DH * DH) + i] = sum;
    }
    if (tid < DH) {
        float sum = 0.f;
        #pragma unroll
        for (int s = 0; s < KSPLIT; s++)
            sum += zp[((size_t)bh * KSPLIT + s) * DH + tid];
        zo[(size_t)bh * DH + tid] = sum;
    }
}

// =============================================================================
// attn: S[n][h*64+e] = (sum_d Q[n][h*64+d]*kv[bh][d][e]) / (sum_d Q*z + eps)
// Writes S directly as a single fp16 plane (feeds output-projection GEMM).
// =============================================================================
__global__ __launch_bounds__(256)
void attn(const float* __restrict__ Q, const float* __restrict__ kv,
          const float* __restrict__ z, __half* __restrict__ Sp) {
    const int tid = threadIdx.x;
    const int row0 = blockIdx.x * 64;
    const int b = row0 / SEQ;

    __shared__ __align__(16) float qs[64][64];
    __shared__ __align__(16) float kvs[64][64];
    __shared__ __align__(16) float zs[64];
    __shared__ float dens[64];

    const int r0 = (tid >> 4) * 4;
    const int e0 = (tid & 15) * 4;

    for (int h = 0; h < HEADS; h++) {
        const int bh = b * HEADS + h;
        __syncthreads();
        #pragma unroll
        for (int t = 0; t < 4; t++) {
            int lin = tid + t * 256;
            int r = lin >> 4, c4 = (lin & 15) * 4;
            *(float4*)&qs[r][c4] =
                *(const float4*)&Q[(size_t)(row0 + r) * DMODEL + h * DH + c4];
            ((float4*)&kvs[0][0])[lin] =
                ((const float4*)(kv + (size_t)bh * DH * DH))[lin];
        }
        if (tid < 16)
            ((float4*)zs)[tid] = ((const float4*)(z + (size_t)bh * DH))[tid];
        __syncthreads();

        if (tid < 64) {
            float sden = 0.f;
            #pragma unroll 8
            for (int d = 0; d < 64; d++) sden += qs[tid][d] * zs[d];
            dens[tid] = sden + EPSV;
        }
        __syncthreads();

        float acc[4][4] = {};
        #pragma unroll 4
        for (int d = 0; d < 64; d++) {
            float4 k4 = *(const float4*)&kvs[d][e0];
            float kk[4] = {k4.x, k4.y, k4.z, k4.w};
            #pragma unroll
            for (int i = 0; i < 4; i++) {
                float qv = qs[r0 + i][d];
                #pragma unroll
                for (int j = 0; j < 4; j++) acc[i][j] += qv * kk[j];
            }
        }
        #pragma unroll
        for (int i = 0; i < 4; i++) {
            float rinv = 1.0f / dens[r0 + i];
            float4 v = make_float4(acc[i][0] * rinv, acc[i][1] * rinv,
                                   acc[i][2] * rinv, acc[i][3] * rinv);
            const size_t idx = (size_t)(row0 + r0 + i) * DMODEL + h * DH + e0;
            *(uint2*)(Sp + idx) = cvt_f16x4(v);
        }
    }
}

// =============================================================================
extern "C" void kernel_launch(void* const* d_in, const int* in_sizes, int n_in,
                              void* d_out, int out_size) {
    const float* queries = (const float*)d_in[0];
    const float* keys    = (const float*)d_in[1];
    const float* values  = (const float*)d_in[2];
    const float* wq = (const float*)d_in[3];
    const float* bq = (const float*)d_in[4];
    const float* wk = (const float*)d_in[5];
    const float* bk = (const float*)d_in[6];
    const float* wv = (const float*)d_in[7];
    const float* bv = (const float*)d_in[8];
    const float* wo = (const float*)d_in[9];
    const float* bo = (const float*)d_in[10];
    float* out = (float*)d_out;

    float *Q, *K, *V, *kvp, *zp, *kvb, *zb;
    __half *Ap, *Whp, *Wlp;
    cudaGetSymbolAddress((void**)&Q,   g_Q);
    cudaGetSymbolAddress((void**)&K,   g_K);
    cudaGetSymbolAddress((void**)&V,   g_V);
    cudaGetSymbolAddress((void**)&Ap,  g_A);
    cudaGetSymbolAddress((void**)&Whp, g_Wh);
    cudaGetSymbolAddress((void**)&Wlp, g_Wl);
    cudaGetSymbolAddress((void**)&kvp, g_kvp);
    cudaGetSymbolAddress((void**)&zp,  g_zp);
    cudaGetSymbolAddress((void**)&kvb, g_kv);
    cudaGetSymbolAddress((void**)&zb,  g_z);

    cudaFuncSetAttribute(gemm_f16<true >, cudaFuncAttributeMaxDynamicSharedMemorySize, SMEM_BYTES);
    cudaFuncSetAttribute(gemm_f16<false>, cudaFuncAttributeMaxDynamicSharedMemorySize, SMEM_BYTES);

    const int WSZ = DMODEL * DMODEL;       // 1M elems per weight
    const int XN4 = ROWS * DMODEL / 4;
    const int WN4 = WSZ / 4;

    dim3 gg(DMODEL / BN, ROWS / BM);       // (8, 128)
    dim3 gb(GTHREADS);

    // weights -> fp16 hi/lo planes (exact split)
    cvt_wpair<<<512, 256>>>(wq, Whp + 0 * WSZ, Wlp + 0 * WSZ, WN4);
    cvt_wpair<<<512, 256>>>(wk, Whp + 1 * WSZ, Wlp + 1 * WSZ, WN4);
    cvt_wpair<<<512, 256>>>(wv, Whp + 2 * WSZ, Wlp + 2 * WSZ, WN4);
    cvt_wpair<<<512, 256>>>(wo, Whp + 3 * WSZ, Wlp + 3 * WSZ, WN4);

    // Q projection
    cvt_act<<<2048, 256>>>(queries, Ap, XN4);
    gemm_f16<true ><<<gg, gb, SMEM_BYTES>>>(Ap, Whp + 0 * WSZ, Wlp + 0 * WSZ, bq, Q);
    // K projection
    cvt_act<<<2048, 256>>>(keys, Ap, XN4);
    gemm_f16<true ><<<gg, gb, SMEM_BYTES>>>(Ap, Whp + 1 * WSZ, Wlp + 1 * WSZ, bk, K);
    // V projection
    cvt_act<<<2048, 256>>>(values, Ap, XN4);
    gemm_f16<false><<<gg, gb, SMEM_BYTES>>>(Ap, Whp + 2 * WSZ, Wlp + 2 * WSZ, bv, V);

    kv_partial<<<BATCH * HEADS * KSPLIT, 256>>>(K, V, kvp, zp);
    kv_reduce <<<BATCH * HEADS, 256>>>(kvp, zp, kvb, zb);
    attn      <<<ROWS / 64, 256>>>(Q, kvb, zb, Ap);   // S -> fp16 plane

    // output projection
    gemm_f16<false><<<gg, gb, SMEM_BYTES>>>(Ap, Whp + 3 * WSZ, Wlp + 3 * WSZ, bo, out);
}

// round 6
// speedup vs baseline: 4.9412x; 1.4073x over previous
#include <cuda_runtime.h>
#include <cuda_fp16.h>
#include <cstdint>

// Problem constants (fixed by reference)
#define DMODEL 1024
#define HEADS  16
#define DH     64
#define BATCH  4
#define SEQ    4096
#define ROWS   (BATCH * SEQ)   // 16384
#define KSPLIT 8
#define EPSV   1e-6f

// GEMM tiling (HMMA mma.sync; tcgen05 unavailable on compute_103 virtual arch)
#define BM 128
#define BN 128
#define BK 64                   // k-values per chunk (fp16) = 128B rows
#define NCH (DMODEL / BK)       // 16 chunks
#define GTHREADS 256
#define STAGES 3

// smem stage layout (bytes): two 16KB planes of fp16 [128 rows][128B]
#define A_PL 0
#define B_PL 16384
#define STAGE 32768
#define SMEM_BYTES (STAGES * STAGE)   // 96KB dynamic

// ---------------- scratch (device globals; no allocation allowed) ------------
__device__ float g_Q[ROWS * DMODEL];
__device__ float g_K[ROWS * DMODEL];
__device__ float g_V[ROWS * DMODEL];
__device__ __half g_A[ROWS * DMODEL];               // activation fp16 plane (reused; also S)
__device__ __half g_W[4 * DMODEL * DMODEL];         // wq,wk,wv,wo fp16
__device__ float g_kvp[BATCH * HEADS * KSPLIT * DH * DH];
__device__ float g_zp [BATCH * HEADS * KSPLIT * DH];
__device__ float g_kv [BATCH * HEADS * DH * DH];
__device__ float g_z  [BATCH * HEADS * DH];

// =============================== helpers ====================================
__device__ __forceinline__ uint32_t smem_u32(const void* p) {
    uint32_t a;
    asm("{ .reg .u64 t; cvta.to.shared.u64 t, %1; cvt.u32.u64 %0, t; }"
        : "=r"(a) : "l"(p));
    return a;
}
__device__ __forceinline__ void ldsm4(uint32_t& r0, uint32_t& r1, uint32_t& r2,
                                      uint32_t& r3, uint32_t addr) {
    asm volatile("ldmatrix.sync.aligned.m8n8.x4.shared.b16 {%0,%1,%2,%3}, [%4];"
                 : "=r"(r0), "=r"(r1), "=r"(r2), "=r"(r3) : "r"(addr));
}
__device__ __forceinline__ void mma_fp16(float* c, const uint32_t* a, const uint32_t* b) {
    asm volatile(
        "mma.sync.aligned.m16n8k16.row.col.f32.f16.f16.f32 "
        "{%0,%1,%2,%3}, {%4,%5,%6,%7}, {%8,%9}, {%0,%1,%2,%3};"
        : "+f"(c[0]), "+f"(c[1]), "+f"(c[2]), "+f"(c[3])
        : "r"(a[0]), "r"(a[1]), "r"(a[2]), "r"(a[3]), "r"(b[0]), "r"(b[1]));
}
__device__ __forceinline__ void cp16(uint32_t smem_dst, const void* gsrc) {
    asm volatile("cp.async.cg.shared.global [%0], [%1], 16;"
                 :: "r"(smem_dst), "l"(gsrc));
}
__device__ __forceinline__ void cp_commit() {
    asm volatile("cp.async.commit_group;" ::: "memory");
}
template<int N>
__device__ __forceinline__ void cp_wait() {
    asm volatile("cp.async.wait_group %0;" :: "n"(N) : "memory");
}

// float4 -> packed fp16 (uint2)
__device__ __forceinline__ uint2 cvt_f16x4(float4 v) {
    __half2 p01 = __floats2half2_rn(v.x, v.y);
    __half2 p23 = __floats2half2_rn(v.z, v.w);
    return make_uint2(*(uint32_t*)&p01, *(uint32_t*)&p23);
}

// =============================================================================
// fp32 -> fp16 conversion, vectorized, grid-stride
// =============================================================================
__global__ __launch_bounds__(256)
void cvt_f16(const float* __restrict__ src, __half* __restrict__ dst, int n4) {
    for (int i = blockIdx.x * 256 + threadIdx.x; i < n4; i += gridDim.x * 256)
        ((uint2*)dst)[i] = cvt_f16x4(((const float4*)src)[i]);
}

// =============================================================================
// GEMM (NT) via HMMA fp16:  Y[r][c] = sum_k A[r][k]*B[c][k] + bias[c].
// CTA 128x128, 8 warps (4m x 2n), warp tile 32x64. 3-stage cp.async pipeline.
// =============================================================================
template<bool PHI>
__global__ __launch_bounds__(GTHREADS, 1)
void gemm_f16(const __half* __restrict__ A, const __half* __restrict__ B,
              const float* __restrict__ bias, float* __restrict__ Y) {
    extern __shared__ char sm[];
    const uint32_t sbase = smem_u32(sm);
    const int tid = threadIdx.x;
    const int lane = tid & 31;
    const int wid = tid >> 5;
    const int wm = wid & 3;          // m group of 32 rows
    const int wn = wid >> 2;         // n group of 64 cols
    const int bm = blockIdx.y;
    const int bn = blockIdx.x;

    // ---- cp.async loader mapping: 2 threads/row, each 4x16B per plane ----
    const int srow = tid >> 1;                 // 0..127
    const int half = tid & 1;
    const char* gA = (const char*)(A + (size_t)(bm * BM + srow) * DMODEL) + half * 64;
    const char* gB = (const char*)(B + (size_t)(bn * BN + srow) * DMODEL) + half * 64;
    uint32_t so[4];
    const uint32_t smask = (uint32_t)((srow & 7) << 4);
    #pragma unroll
    for (int j = 0; j < 4; j++)
        so[j] = (uint32_t)(srow * 128) + (((uint32_t)(half * 64 + j * 16)) ^ smask);

    // ---- ldmatrix address precompute (proven layout) ----
    int row_a[2];
    row_a[0] = wm * 32 + (lane & 15);
    row_a[1] = row_a[0] + 16;
    const uint32_t a_colb = (uint32_t)((lane >> 4) << 4);
    uint32_t a_base[2], a_mask[2];
    #pragma unroll
    for (int mt = 0; mt < 2; mt++) {
        a_base[mt] = (uint32_t)(row_a[mt] * 128);
        a_mask[mt] = (uint32_t)((row_a[mt] & 7) << 4);
    }
    int nrow[4];
    #pragma unroll
    for (int ntp = 0; ntp < 4; ntp++)
        nrow[ntp] = wn * 64 + ntp * 16 + (lane & 7) + ((lane >> 4) << 3);
    const uint32_t b_colb = (lane & 8) ? 16u : 0u;
    uint32_t b_base[4], b_mask[4];
    #pragma unroll
    for (int ntp = 0; ntp < 4; ntp++) {
        b_base[ntp] = (uint32_t)(nrow[ntp] * 128);
        b_mask[ntp] = (uint32_t)((nrow[ntp] & 7) << 4);
    }

    float acc[2][8][4];
    #pragma unroll
    for (int mt = 0; mt < 2; mt++)
        #pragma unroll
        for (int nt = 0; nt < 8; nt++)
            #pragma unroll
            for (int i = 0; i < 4; i++) acc[mt][nt][i] = 0.f;

    auto issue = [&](int c, int s) {
        const uint32_t stg = sbase + (uint32_t)(s * STAGE);
        const int gb = c * 128;   // byte offset along k
        #pragma unroll
        for (int j = 0; j < 4; j++) cp16(stg + A_PL + so[j], gA + gb + j * 16);
        #pragma unroll
        for (int j = 0; j < 4; j++) cp16(stg + B_PL + so[j], gB + gb + j * 16);
        cp_commit();
    };

    issue(0, 0);
    issue(1, 1);

    for (int c = 0; c < NCH; c++) {
        if (c + 2 < NCH) cp_wait<1>(); else cp_wait<0>();
        __syncthreads();
        if (c + 2 < NCH) issue(c + 2, (c + 2) % STAGES);

        const uint32_t stg = sbase + (uint32_t)((c % STAGES) * STAGE);
        #pragma unroll
        for (int ks = 0; ks < 4; ks++) {
            const uint32_t kb = (uint32_t)(ks * 32);
            uint32_t Ar[2][4];
            #pragma unroll
            for (int mt = 0; mt < 2; mt++) {
                uint32_t off = a_base[mt] + ((kb + a_colb) ^ a_mask[mt]);
                ldsm4(Ar[mt][0], Ar[mt][1], Ar[mt][2], Ar[mt][3], stg + A_PL + off);
            }
            uint32_t Br[8][2];
            #pragma unroll
            for (int ntp = 0; ntp < 4; ntp++) {
                uint32_t off = b_base[ntp] + ((kb + b_colb) ^ b_mask[ntp]);
                ldsm4(Br[2 * ntp][0], Br[2 * ntp][1], Br[2 * ntp + 1][0], Br[2 * ntp + 1][1],
                      stg + B_PL + off);
            }
            #pragma unroll
            for (int mt = 0; mt < 2; mt++)
                #pragma unroll
                for (int nt = 0; nt < 8; nt++)
                    mma_fp16(acc[mt][nt], Ar[mt], Br[nt]);
        }
        __syncthreads();
    }

    // ---- epilogue ----
    const int lr = lane >> 2;
    const int lc = lane & 3;
    #pragma unroll
    for (int mt = 0; mt < 2; mt++) {
        const int gr0 = bm * BM + wm * 32 + mt * 16 + lr;
        #pragma unroll
        for (int nt = 0; nt < 8; nt++) {
            const int gc = bn * BN + wn * 64 + nt * 8 + lc * 2;
            const float b0 = __ldg(&bias[gc]);
            const float b1 = __ldg(&bias[gc + 1]);
            float o00 = acc[mt][nt][0] + b0;
            float o01 = acc[mt][nt][1] + b1;
            float o10 = acc[mt][nt][2] + b0;
            float o11 = acc[mt][nt][3] + b1;
            if (PHI) {
                o00 = (o00 > 0.f) ? (o00 + 1.f) : __expf(o00);
                o01 = (o01 > 0.f) ? (o01 + 1.f) : __expf(o01);
                o10 = (o10 > 0.f) ? (o10 + 1.f) : __expf(o10);
                o11 = (o11 > 0.f) ? (o11 + 1.f) : __expf(o11);
            }
            *(float2*)(Y + (size_t)gr0 * DMODEL + gc)       = make_float2(o00, o01);
            *(float2*)(Y + (size_t)(gr0 + 8) * DMODEL + gc) = make_float2(o10, o11);
        }
    }
}

// =============================================================================
// kv partial:  per (b,h,split) block: KV[d][e] += K[m][d]*V[m][e], z[d] += K[m][d]
// =============================================================================
__global__ __launch_bounds__(256)
void kv_partial(const float* __restrict__ K, const float* __restrict__ V,
                float* __restrict__ kvp, float* __restrict__ zp) {
    const int tid = threadIdx.x;
    const int s  = blockIdx.x % KSPLIT;
    const int bh = blockIdx.x / KSPLIT;
    const int b = bh / HEADS, h = bh % HEADS;

    __shared__ __align__(16) float Ks[64][64];
    __shared__ __align__(16) float Vs[64][64];

    const int d0 = (tid >> 4) * 4;
    const int e0 = (tid & 15) * 4;
    float acc[4][4] = {};
    float zacc[4] = {};

    const size_t base = (size_t)b * SEQ * DMODEL + (size_t)h * DH;
    const int m_begin = s * (SEQ / KSPLIT);
    const int m_end   = m_begin + (SEQ / KSPLIT);

    for (int m0 = m_begin; m0 < m_end; m0 += 64) {
        float4 kreg[4], vreg[4];
        #pragma unroll
        for (int t = 0; t < 4; t++) {
            int lin = tid + t * 256;
            int r = lin >> 4, c4 = (lin & 15) * 4;
            kreg[t] = *(const float4*)&K[base + (size_t)(m0 + r) * DMODEL + c4];
            vreg[t] = *(const float4*)&V[base + (size_t)(m0 + r) * DMODEL + c4];
        }
        __syncthreads();
        #pragma unroll
        for (int t = 0; t < 4; t++) {
            int lin = tid + t * 256;
            int r = lin >> 4, c4 = (lin & 15) * 4;
            *(float4*)&Ks[r][c4] = kreg[t];
            *(float4*)&Vs[r][c4] = vreg[t];
        }
        __syncthreads();

        #pragma unroll 4
        for (int mm = 0; mm < 64; mm++) {
            float4 k4 = *(const float4*)&Ks[mm][d0];
            float4 v4 = *(const float4*)&Vs[mm][e0];
            float kk[4] = {k4.x, k4.y, k4.z, k4.w};
            float vv[4] = {v4.x, v4.y, v4.z, v4.w};
            #pragma unroll
            for (int i = 0; i < 4; i++)
                #pragma unroll
                for (int j = 0; j < 4; j++)
                    acc[i][j] += kk[i] * vv[j];
            if ((tid & 15) == 0) {
                #pragma unroll
                for (int i = 0; i < 4; i++) zacc[i] += kk[i];
            }
        }
    }

    float* kout = kvp + (size_t)blockIdx.x * (DH * DH);
    #pragma unroll
    for (int i = 0; i < 4; i++)
        *(float4*)&kout[(d0 + i) * DH + e0] = make_float4(acc[i][0], acc[i][1], acc[i][2], acc[i][3]);
    if ((tid & 15) == 0) {
        #pragma unroll
        for (int i = 0; i < 4; i++) zp[(size_t)blockIdx.x * DH + d0 + i] = zacc[i];
    }
}

__global__ __launch_bounds__(256)
void kv_reduce(const float* __restrict__ kvp, const float* __restrict__ zp,
               float* __restrict__ kvo, float* __restrict__ zo) {
    const int bh = blockIdx.x;
    const int tid = threadIdx.x;
    for (int i = tid; i < DH * DH; i += 256) {
        float sum = 0.f;
        #pragma unroll
        for (int s = 0; s < KSPLIT; s++)
            sum += kvp[((size_t)bh * KSPLIT + s) * (DH * DH) + i];
        kvo[(size_t)bh * (DH * DH) + i] = sum;
    }
    if (tid < DH) {
        float sum = 0.f;
        #pragma unroll
        for (int s = 0; s < KSPLIT; s++)
            sum += zp[((size_t)bh * KSPLIT + s) * DH + tid];
        zo[(size_t)bh * DH + tid] = sum;
    }
}

// =============================================================================
// attn: S[n][h*64+e] = (sum_d Q[n][h*64+d]*kv[bh][d][e]) / (sum_d Q*z + eps)
// Writes S directly as a single fp16 plane (feeds output-projection GEMM).
// =============================================================================
__global__ __launch_bounds__(256)
void attn(const float* __restrict__ Q, const float* __restrict__ kv,
          const float* __restrict__ z, __half* __restrict__ Sp) {
    const int tid = threadIdx.x;
    const int row0 = blockIdx.x * 64;
    const int b = row0 / SEQ;

    __shared__ __align__(16) float qs[64][64];
    __shared__ __align__(16) float kvs[64][64];
    __shared__ __align__(16) float zs[64];
    __shared__ float dens[64];

    const int r0 = (tid >> 4) * 4;
    const int e0 = (tid & 15) * 4;

    for (int h = 0; h < HEADS; h++) {
        const int bh = b * HEADS + h;
        __syncthreads();
        #pragma unroll
        for (int t = 0; t < 4; t++) {
            int lin = tid + t * 256;
            int r = lin >> 4, c4 = (lin & 15) * 4;
            *(float4*)&qs[r][c4] =
                *(const float4*)&Q[(size_t)(row0 + r) * DMODEL + h * DH + c4];
            ((float4*)&kvs[0][0])[lin] =
                ((const float4*)(kv + (size_t)bh * DH * DH))[lin];
        }
        if (tid < 16)
            ((float4*)zs)[tid] = ((const float4*)(z + (size_t)bh * DH))[tid];
        __syncthreads();

        if (tid < 64) {
            float sden = 0.f;
            #pragma unroll 8
            for (int d = 0; d < 64; d++) sden += qs[tid][d] * zs[d];
            dens[tid] = sden + EPSV;
        }
        __syncthreads();

        float acc[4][4] = {};
        #pragma unroll 4
        for (int d = 0; d < 64; d++) {
            float4 k4 = *(const float4*)&kvs[d][e0];
            float kk[4] = {k4.x, k4.y, k4.z, k4.w};
            #pragma unroll
            for (int i = 0; i < 4; i++) {
                float qv = qs[r0 + i][d];
                #pragma unroll
                for (int j = 0; j < 4; j++) acc[i][j] += qv * kk[j];
            }
        }
        #pragma unroll
        for (int i = 0; i < 4; i++) {
            float rinv = 1.0f / dens[r0 + i];
            float4 v = make_float4(acc[i][0] * rinv, acc[i][1] * rinv,
                                   acc[i][2] * rinv, acc[i][3] * rinv);
            const size_t idx = (size_t)(row0 + r0 + i) * DMODEL + h * DH + e0;
            *(uint2*)(Sp + idx) = cvt_f16x4(v);
        }
    }
}

// =============================================================================
extern "C" void kernel_launch(void* const* d_in, const int* in_sizes, int n_in,
                              void* d_out, int out_size) {
    const float* queries = (const float*)d_in[0];
    const float* keys    = (const float*)d_in[1];
    const float* values  = (const float*)d_in[2];
    const float* wq = (const float*)d_in[3];
    const float* bq = (const float*)d_in[4];
    const float* wk = (const float*)d_in[5];
    const float* bk = (const float*)d_in[6];
    const float* wv = (const float*)d_in[7];
    const float* bv = (const float*)d_in[8];
    const float* wo = (const float*)d_in[9];
    const float* bo = (const float*)d_in[10];
    float* out = (float*)d_out;

    float *Q, *K, *V, *kvp, *zp, *kvb, *zb;
    __half *Ap, *Wp;
    cudaGetSymbolAddress((void**)&Q,   g_Q);
    cudaGetSymbolAddress((void**)&K,   g_K);
    cudaGetSymbolAddress((void**)&V,   g_V);
    cudaGetSymbolAddress((void**)&Ap,  g_A);
    cudaGetSymbolAddress((void**)&Wp,  g_W);
    cudaGetSymbolAddress((void**)&kvp, g_kvp);
    cudaGetSymbolAddress((void**)&zp,  g_zp);
    cudaGetSymbolAddress((void**)&kvb, g_kv);
    cudaGetSymbolAddress((void**)&zb,  g_z);

    cudaFuncSetAttribute(gemm_f16<true >, cudaFuncAttributeMaxDynamicSharedMemorySize, SMEM_BYTES);
    cudaFuncSetAttribute(gemm_f16<false>, cudaFuncAttributeMaxDynamicSharedMemorySize, SMEM_BYTES);

    const int WSZ = DMODEL * DMODEL;       // 1M elems per weight
    const int XN4 = ROWS * DMODEL / 4;
    const int WN4 = WSZ / 4;

    dim3 gg(DMODEL / BN, ROWS / BM);       // (8, 128)
    dim3 gb(GTHREADS);

    // weights -> fp16 (once)
    cvt_f16<<<512, 256>>>(wq, Wp + 0 * WSZ, WN4);
    cvt_f16<<<512, 256>>>(wk, Wp + 1 * WSZ, WN4);
    cvt_f16<<<512, 256>>>(wv, Wp + 2 * WSZ, WN4);
    cvt_f16<<<512, 256>>>(wo, Wp + 3 * WSZ, WN4);

    // Q projection
    cvt_f16<<<2048, 256>>>(queries, Ap, XN4);
    gemm_f16<true ><<<gg, gb, SMEM_BYTES>>>(Ap, Wp + 0 * WSZ, bq, Q);
    // K projection
    cvt_f16<<<2048, 256>>>(keys, Ap, XN4);
    gemm_f16<true ><<<gg, gb, SMEM_BYTES>>>(Ap, Wp + 1 * WSZ, bk, K);
    // V projection
    cvt_f16<<<2048, 256>>>(values, Ap, XN4);
    gemm_f16<false><<<gg, gb, SMEM_BYTES>>>(Ap, Wp + 2 * WSZ, bv, V);

    kv_partial<<<BATCH * HEADS * KSPLIT, 256>>>(K, V, kvp, zp);
    kv_reduce <<<BATCH * HEADS, 256>>>(kvp, zp, kvb, zb);
    attn      <<<ROWS / 64, 256>>>(Q, kvb, zb, Ap);   // S -> fp16 plane

    // output projection
    gemm_f16<false><<<gg, gb, SMEM_BYTES>>>(Ap, Wp + 3 * WSZ, bo, out);
}

// round 7
// speedup vs baseline: 6.2485x; 1.2646x over previous
#include <cuda_runtime.h>
#include <cuda_fp16.h>
#include <cstdint>

// Problem constants (fixed by reference)
#define DMODEL 1024
#define HEADS  16
#define DH     64
#define BATCH  4
#define SEQ    4096
#define ROWS   (BATCH * SEQ)   // 16384
#define KSPLIT 8
#define EPSV   1e-6f

// GEMM tiling (HMMA mma.sync; tcgen05 unavailable on compute_103 virtual arch)
#define BM 128
#define BN 128
#define BK 64                   // k-values per chunk (fp16) = 128B rows
#define NCH (DMODEL / BK)       // 16 chunks
#define GTHREADS 256
#define STAGES 4

// Blocked-swizzled operand layout in gmem: 16KB block per (row-tile, k-chunk).
// Within a block: 128 rows x 128B, byte col ^ ((row&7)<<4)  (same as smem image)
#define BLK_BYTES 16384

// smem: 4 mbarriers @ [0..32), stages of 32KB at 1024 + s*32768
#define A_PL 0
#define B_PL 16384
#define STAGE 32768
#define SMEM_BYTES (1024 + STAGES * STAGE)   // 132096

// ---------------- scratch (device globals; no allocation allowed) ------------
__device__ float g_Q[ROWS * DMODEL];
__device__ float g_K[ROWS * DMODEL];
__device__ float g_V[ROWS * DMODEL];
__device__ __half g_Ab[ROWS * DMODEL];              // blocked-swizzled activations / S
__device__ __half g_Wb[4 * DMODEL * DMODEL];        // blocked-swizzled wq,wk,wv,wo
__device__ float g_kvp[BATCH * HEADS * KSPLIT * DH * DH];
__device__ float g_zp [BATCH * HEADS * KSPLIT * DH];
__device__ float g_kv [BATCH * HEADS * DH * DH];
__device__ float g_z  [BATCH * HEADS * DH];

// =============================== helpers ====================================
__device__ __forceinline__ uint32_t smem_u32(const void* p) {
    uint32_t a;
    asm("{ .reg .u64 t; cvta.to.shared.u64 t, %1; cvt.u32.u64 %0, t; }"
        : "=r"(a) : "l"(p));
    return a;
}
__device__ __forceinline__ void ldsm4(uint32_t& r0, uint32_t& r1, uint32_t& r2,
                                      uint32_t& r3, uint32_t addr) {
    asm volatile("ldmatrix.sync.aligned.m8n8.x4.shared.b16 {%0,%1,%2,%3}, [%4];"
                 : "=r"(r0), "=r"(r1), "=r"(r2), "=r"(r3) : "r"(addr));
}
__device__ __forceinline__ void mma_fp16(float* c, const uint32_t* a, const uint32_t* b) {
    asm volatile(
        "mma.sync.aligned.m16n8k16.row.col.f32.f16.f16.f32 "
        "{%0,%1,%2,%3}, {%4,%5,%6,%7}, {%8,%9}, {%0,%1,%2,%3};"
        : "+f"(c[0]), "+f"(c[1]), "+f"(c[2]), "+f"(c[3])
        : "r"(a[0]), "r"(a[1]), "r"(a[2]), "r"(a[3]), "r"(b[0]), "r"(b[1]));
}
__device__ __forceinline__ void mbar_init(uint32_t addr, uint32_t cnt) {
    asm volatile("mbarrier.init.shared.b64 [%0], %1;" :: "r"(addr), "r"(cnt) : "memory");
}
__device__ __forceinline__ void mbar_expect_tx(uint32_t addr, uint32_t bytes) {
    asm volatile("mbarrier.arrive.expect_tx.shared.b64 _, [%0], %1;"
                 :: "r"(addr), "r"(bytes) : "memory");
}
__device__ __forceinline__ void mbar_wait(uint32_t addr, uint32_t parity) {
    asm volatile(
        "{\n\t.reg .pred P;\n"
        "W%=:\n\t"
        "mbarrier.try_wait.parity.acquire.cta.shared::cta.b64 P, [%0], %1, 0x989680;\n\t"
        "@!P bra W%=;\n\t"
        "}"
        :: "r"(addr), "r"(parity) : "memory");
}
__device__ __forceinline__ void bulk_cp(uint32_t sdst, const void* gsrc,
                                        uint32_t bytes, uint32_t mbar) {
    asm volatile(
        "cp.async.bulk.shared::cta.global.mbarrier::complete_tx::bytes [%0], [%1], %2, [%3];"
        :: "r"(sdst), "l"(gsrc), "r"(bytes), "r"(mbar) : "memory");
}

// float4 -> packed fp16 (uint2)
__device__ __forceinline__ uint2 cvt_f16x4(float4 v) {
    __half2 p01 = __floats2half2_rn(v.x, v.y);
    __half2 p23 = __floats2half2_rn(v.z, v.w);
    return make_uint2(*(uint32_t*)&p01, *(uint32_t*)&p23);
}

// =============================================================================
// fp32 [rows][1024] -> blocked-swizzled fp16 (the smem image), grid-stride
// =============================================================================
__global__ __launch_bounds__(256)
void cvt_swz(const float* __restrict__ src, __half* __restrict__ dst, int n4) {
    for (int i = blockIdx.x * 256 + threadIdx.x; i < n4; i += gridDim.x * 256) {
        const int grow = i >> 8;             // 256 float4 per row
        const int gcol = (i & 255) * 4;
        const int blk  = grow >> 7;
        const int r    = grow & 127;
        const int c    = gcol >> 6;
        const uint32_t colb = (uint32_t)((gcol & 63) * 2);
        const size_t off = ((size_t)(blk * NCH + c) << 14)
                         + (uint32_t)(r * 128) + (colb ^ ((uint32_t)(r & 7) << 4));
        *(uint2*)((char*)dst + off) = cvt_f16x4(((const float4*)src)[i]);
    }
}

// =============================================================================
// GEMM (NT) via HMMA fp16 on blocked-swizzled operands:
//   Y[r][c] = sum_k A[r][k]*B[c][k] + bias[c], optional phi.
// CTA 128x128, 8 warps (4m x 2n), warp tile 32x64.
// Loader: 2 cp.async.bulk per chunk (one elected thread) + per-stage mbarrier.
// =============================================================================
template<bool PHI>
__global__ __launch_bounds__(GTHREADS, 1)
void gemm_f16(const __half* __restrict__ Ab, const __half* __restrict__ Bb,
              const float* __restrict__ bias, float* __restrict__ Y) {
    extern __shared__ char sm[];
    const uint32_t sbase = smem_u32(sm);
    const int tid = threadIdx.x;
    const int lane = tid & 31;
    const int wid = tid >> 5;
    const int wm = wid & 3;          // m group of 32 rows
    const int wn = wid >> 2;         // n group of 64 cols
    const int bm = blockIdx.y;
    const int bn = blockIdx.x;

    if (tid == 0) {
        #pragma unroll
        for (int s = 0; s < STAGES; s++) mbar_init(sbase + s * 8, 1);
    }
    __syncthreads();

    const char* gAb = (const char*)Ab + ((size_t)(bm * NCH) << 14);
    const char* gBb = (const char*)Bb + ((size_t)(bn * NCH) << 14);

    // ---- ldmatrix address precompute (proven layout) ----
    int row_a[2];
    row_a[0] = wm * 32 + (lane & 15);
    row_a[1] = row_a[0] + 16;
    const uint32_t a_colb = (uint32_t)((lane >> 4) << 4);
    uint32_t a_base[2], a_mask[2];
    #pragma unroll
    for (int mt = 0; mt < 2; mt++) {
        a_base[mt] = (uint32_t)(row_a[mt] * 128);
        a_mask[mt] = (uint32_t)((row_a[mt] & 7) << 4);
    }
    int nrow[4];
    #pragma unroll
    for (int ntp = 0; ntp < 4; ntp++)
        nrow[ntp] = wn * 64 + ntp * 16 + (lane & 7) + ((lane >> 4) << 3);
    const uint32_t b_colb = (lane & 8) ? 16u : 0u;
    uint32_t b_base[4], b_mask[4];
    #pragma unroll
    for (int ntp = 0; ntp < 4; ntp++) {
        b_base[ntp] = (uint32_t)(nrow[ntp] * 128);
        b_mask[ntp] = (uint32_t)((nrow[ntp] & 7) << 4);
    }

    float acc[2][8][4];
    #pragma unroll
    for (int mt = 0; mt < 2; mt++)
        #pragma unroll
        for (int nt = 0; nt < 8; nt++)
            #pragma unroll
            for (int i = 0; i < 4; i++) acc[mt][nt][i] = 0.f;

    auto issue = [&](int c) {
        const int s = c & (STAGES - 1);
        const uint32_t mb = sbase + s * 8;
        const uint32_t st = sbase + 1024 + s * STAGE;
        mbar_expect_tx(mb, 2 * BLK_BYTES);
        bulk_cp(st + A_PL, gAb + ((size_t)c << 14), BLK_BYTES, mb);
        bulk_cp(st + B_PL, gBb + ((size_t)c << 14), BLK_BYTES, mb);
    };

    if (tid == 0) { issue(0); issue(1); issue(2); }

    for (int c = 0; c < NCH; c++) {
        mbar_wait(sbase + (c & (STAGES - 1)) * 8, (c >> 2) & 1);
        if (tid == 0 && c + 3 < NCH) issue(c + 3);

        const uint32_t stg = sbase + 1024 + (uint32_t)((c & (STAGES - 1)) * STAGE);
        #pragma unroll
        for (int ks = 0; ks < 4; ks++) {
            const uint32_t kb = (uint32_t)(ks * 32);
            uint32_t Ar[2][4];
            #pragma unroll
            for (int mt = 0; mt < 2; mt++) {
                uint32_t off = a_base[mt] + ((kb + a_colb) ^ a_mask[mt]);
                ldsm4(Ar[mt][0], Ar[mt][1], Ar[mt][2], Ar[mt][3], stg + A_PL + off);
            }
            uint32_t Br[8][2];
            #pragma unroll
            for (int ntp = 0; ntp < 4; ntp++) {
                uint32_t off = b_base[ntp] + ((kb + b_colb) ^ b_mask[ntp]);
                ldsm4(Br[2 * ntp][0], Br[2 * ntp][1], Br[2 * ntp + 1][0], Br[2 * ntp + 1][1],
                      stg + B_PL + off);
            }
            #pragma unroll
            for (int mt = 0; mt < 2; mt++)
                #pragma unroll
                for (int nt = 0; nt < 8; nt++)
                    mma_fp16(acc[mt][nt], Ar[mt], Br[nt]);
        }
        __syncthreads();
    }

    // ---- epilogue ----
    const int lr = lane >> 2;
    const int lc = lane & 3;
    #pragma unroll
    for (int mt = 0; mt < 2; mt++) {
        const int gr0 = bm * BM + wm * 32 + mt * 16 + lr;
        #pragma unroll
        for (int nt = 0; nt < 8; nt++) {
            const int gc = bn * BN + wn * 64 + nt * 8 + lc * 2;
            const float b0 = __ldg(&bias[gc]);
            const float b1 = __ldg(&bias[gc + 1]);
            float o00 = acc[mt][nt][0] + b0;
            float o01 = acc[mt][nt][1] + b1;
            float o10 = acc[mt][nt][2] + b0;
            float o11 = acc[mt][nt][3] + b1;
            if (PHI) {
                o00 = (o00 > 0.f) ? (o00 + 1.f) : __expf(o00);
                o01 = (o01 > 0.f) ? (o01 + 1.f) : __expf(o01);
                o10 = (o10 > 0.f) ? (o10 + 1.f) : __expf(o10);
                o11 = (o11 > 0.f) ? (o11 + 1.f) : __expf(o11);
            }
            *(float2*)(Y + (size_t)gr0 * DMODEL + gc)       = make_float2(o00, o01);
            *(float2*)(Y + (size_t)(gr0 + 8) * DMODEL + gc) = make_float2(o10, o11);
        }
    }
}

// =============================================================================
// kv partial:  per (b,h,split) block: KV[d][e] += K[m][d]*V[m][e], z[d] += K[m][d]
// =============================================================================
__global__ __launch_bounds__(256)
void kv_partial(const float* __restrict__ K, const float* __restrict__ V,
                float* __restrict__ kvp, float* __restrict__ zp) {
    const int tid = threadIdx.x;
    const int s  = blockIdx.x % KSPLIT;
    const int bh = blockIdx.x / KSPLIT;
    const int b = bh / HEADS, h = bh % HEADS;

    __shared__ __align__(16) float Ks[64][64];
    __shared__ __align__(16) float Vs[64][64];

    const int d0 = (tid >> 4) * 4;
    const int e0 = (tid & 15) * 4;
    float acc[4][4] = {};
    float zacc[4] = {};

    const size_t base = (size_t)b * SEQ * DMODEL + (size_t)h * DH;
    const int m_begin = s * (SEQ / KSPLIT);
    const int m_end   = m_begin + (SEQ / KSPLIT);

    for (int m0 = m_begin; m0 < m_end; m0 += 64) {
        float4 kreg[4], vreg[4];
        #pragma unroll
        for (int t = 0; t < 4; t++) {
            int lin = tid + t * 256;
            int r = lin >> 4, c4 = (lin & 15) * 4;
            kreg[t] = *(const float4*)&K[base + (size_t)(m0 + r) * DMODEL + c4];
            vreg[t] = *(const float4*)&V[base + (size_t)(m0 + r) * DMODEL + c4];
        }
        __syncthreads();
        #pragma unroll
        for (int t = 0; t < 4; t++) {
            int lin = tid + t * 256;
            int r = lin >> 4, c4 = (lin & 15) * 4;
            *(float4*)&Ks[r][c4] = kreg[t];
            *(float4*)&Vs[r][c4] = vreg[t];
        }
        __syncthreads();

        #pragma unroll 4
        for (int mm = 0; mm < 64; mm++) {
            float4 k4 = *(const float4*)&Ks[mm][d0];
            float4 v4 = *(const float4*)&Vs[mm][e0];
            float kk[4] = {k4.x, k4.y, k4.z, k4.w};
            float vv[4] = {v4.x, v4.y, v4.z, v4.w};
            #pragma unroll
            for (int i = 0; i < 4; i++)
                #pragma unroll
                for (int j = 0; j < 4; j++)
                    acc[i][j] += kk[i] * vv[j];
            if ((tid & 15) == 0) {
                #pragma unroll
                for (int i = 0; i < 4; i++) zacc[i] += kk[i];
            }
        }
    }

    float* kout = kvp + (size_t)blockIdx.x * (DH * DH);
    #pragma unroll
    for (int i = 0; i < 4; i++)
        *(float4*)&kout[(d0 + i) * DH + e0] = make_float4(acc[i][0], acc[i][1], acc[i][2], acc[i][3]);
    if ((tid & 15) == 0) {
        #pragma unroll
        for (int i = 0; i < 4; i++) zp[(size_t)blockIdx.x * DH + d0 + i] = zacc[i];
    }
}

__global__ __launch_bounds__(256)
void kv_reduce(const float* __restrict__ kvp, const float* __restrict__ zp,
               float* __restrict__ kvo, float* __restrict__ zo) {
    const int bh = blockIdx.x;
    const int tid = threadIdx.x;
    for (int i = tid; i < DH * DH; i += 256) {
        float sum = 0.f;
        #pragma unroll
        for (int s = 0; s < KSPLIT; s++)
            sum += kvp[((size_t)bh * KSPLIT + s) * (DH * DH) + i];
        kvo[(size_t)bh * (DH * DH) + i] = sum;
    }
    if (tid < DH) {
        float sum = 0.f;
        #pragma unroll
        for (int s = 0; s < KSPLIT; s++)
            sum += zp[((size_t)bh * KSPLIT + s) * DH + tid];
        zo[(size_t)bh * DH + tid] = sum;
    }
}

// =============================================================================
// attn: S[n][h*64+e] = (sum_d Q[n][h*64+d]*kv[bh][d][e]) / (sum_d Q*z + eps)
// Writes S directly into the blocked-swizzled fp16 layout (head h == k-chunk h).
// =============================================================================
__global__ __launch_bounds__(256)
void attn(const float* __restrict__ Q, const float* __restrict__ kv,
          const float* __restrict__ z, __half* __restrict__ Sb) {
    const int tid = threadIdx.x;
    const int row0 = blockIdx.x * 64;
    const int b = row0 / SEQ;

    __shared__ __align__(16) float qs[64][64];
    __shared__ __align__(16) float kvs[64][64];
    __shared__ __align__(16) float zs[64];
    __shared__ float dens[64];

    const int r0 = (tid >> 4) * 4;
    const int e0 = (tid & 15) * 4;

    for (int h = 0; h < HEADS; h++) {
        const int bh = b * HEADS + h;
        __syncthreads();
        #pragma unroll
        for (int t = 0; t < 4; t++) {
            int lin = tid + t * 256;
            int r = lin >> 4, c4 = (lin & 15) * 4;
            *(float4*)&qs[r][c4] =
                *(const float4*)&Q[(size_t)(row0 + r) * DMODEL + h * DH + c4];
            ((float4*)&kvs[0][0])[lin] =
                ((const float4*)(kv + (size_t)bh * DH * DH))[lin];
        }
        if (tid < 16)
            ((float4*)zs)[tid] = ((const float4*)(z + (size_t)bh * DH))[tid];
        __syncthreads();

        if (tid < 64) {
            float sden = 0.f;
            #pragma unroll 8
            for (int d = 0; d < 64; d++) sden += qs[tid][d] * zs[d];
            dens[tid] = sden + EPSV;
        }
        __syncthreads();

        float acc[4][4] = {};
        #pragma unroll 4
        for (int d = 0; d < 64; d++) {
            float4 k4 = *(const float4*)&kvs[d][e0];
            float kk[4] = {k4.x, k4.y, k4.z, k4.w};
            #pragma unroll
            for (int i = 0; i < 4; i++) {
                float qv = qs[r0 + i][d];
                #pragma unroll
                for (int j = 0; j < 4; j++) acc[i][j] += qv * kk[j];
            }
        }
        #pragma unroll
        for (int i = 0; i < 4; i++) {
            float rinv = 1.0f / dens[r0 + i];
            float4 v = make_float4(acc[i][0] * rinv, acc[i][1] * rinv,
                                   acc[i][2] * rinv, acc[i][3] * rinv);
            const int grow = row0 + r0 + i;
            const int blk = grow >> 7;
            const int r   = grow & 127;
            const uint32_t colb = (uint32_t)(e0 * 2);
            const size_t off = ((size_t)(blk * NCH + h) << 14)
                             + (uint32_t)(r * 128) + (colb ^ ((uint32_t)(r & 7) << 4));
            *(uint2*)((char*)Sb + off) = cvt_f16x4(v);
        }
    }
}

// =============================================================================
extern "C" void kernel_launch(void* const* d_in, const int* in_sizes, int n_in,
                              void* d_out, int out_size) {
    const float* queries = (const float*)d_in[0];
    const float* keys    = (const float*)d_in[1];
    const float* values  = (const float*)d_in[2];
    const float* wq = (const float*)d_in[3];
    const float* bq = (const float*)d_in[4];
    const float* wk = (const float*)d_in[5];
    const float* bk = (const float*)d_in[6];
    const float* wv = (const float*)d_in[7];
    const float* bv = (const float*)d_in[8];
    const float* wo = (const float*)d_in[9];
    const float* bo = (const float*)d_in[10];
    float* out = (float*)d_out;

    float *Q, *K, *V, *kvp, *zp, *kvb, *zb;
    __half *Abp, *Wbp;
    cudaGetSymbolAddress((void**)&Q,   g_Q);
    cudaGetSymbolAddress((void**)&K,   g_K);
    cudaGetSymbolAddress((void**)&V,   g_V);
    cudaGetSymbolAddress((void**)&Abp, g_Ab);
    cudaGetSymbolAddress((void**)&Wbp, g_Wb);
    cudaGetSymbolAddress((void**)&kvp, g_kvp);
    cudaGetSymbolAddress((void**)&zp,  g_zp);
    cudaGetSymbolAddress((void**)&kvb, g_kv);
    cudaGetSymbolAddress((void**)&zb,  g_z);

    cudaFuncSetAttribute(gemm_f16<true >, cudaFuncAttributeMaxDynamicSharedMemorySize, SMEM_BYTES);
    cudaFuncSetAttribute(gemm_f16<false>, cudaFuncAttributeMaxDynamicSharedMemorySize, SMEM_BYTES);

    const int WSZ = DMODEL * DMODEL;       // 1M elems per weight
    const int XN4 = ROWS * DMODEL / 4;
    const int WN4 = WSZ / 4;

    dim3 gg(DMODEL / BN, ROWS / BM);       // (8, 128)
    dim3 gb(GTHREADS);

    // weights -> blocked-swizzled fp16 (once)
    cvt_swz<<<512, 256>>>(wq, Wbp + 0 * WSZ, WN4);
    cvt_swz<<<512, 256>>>(wk, Wbp + 1 * WSZ, WN4);
    cvt_swz<<<512, 256>>>(wv, Wbp + 2 * WSZ, WN4);
    cvt_swz<<<512, 256>>>(wo, Wbp + 3 * WSZ, WN4);

    // Q projection
    cvt_swz<<<2048, 256>>>(queries, Abp, XN4);
    gemm_f16<true ><<<gg, gb, SMEM_BYTES>>>(Abp, Wbp + 0 * WSZ, bq, Q);
    // K projection
    cvt_swz<<<2048, 256>>>(keys, Abp, XN4);
    gemm_f16<true ><<<gg, gb, SMEM_BYTES>>>(Abp, Wbp + 1 * WSZ, bk, K);
    // V projection
    cvt_swz<<<2048, 256>>>(values, Abp, XN4);
    gemm_f16<false><<<gg, gb, SMEM_BYTES>>>(Abp, Wbp + 2 * WSZ, bv, V);

    kv_partial<<<BATCH * HEADS * KSPLIT, 256>>>(K, V, kvp, zp);
    kv_reduce <<<BATCH * HEADS, 256>>>(kvp, zp, kvb, zb);
    attn      <<<ROWS / 64, 256>>>(Q, kvb, zb, Abp);   // S -> blocked planes

    // output projection
    gemm_f16<false><<<gg, gb, SMEM_BYTES>>>(Abp, Wbp + 3 * WSZ, bo, out);
}

// round 8
// speedup vs baseline: 7.8813x; 1.2613x over previous
#include <cuda_runtime.h>
#include <cuda_fp16.h>
#include <cstdint>

// Problem constants (fixed by reference)
#define DMODEL 1024
#define HEADS  16
#define DH     64
#define BATCH  4
#define SEQ    4096
#define ROWS   (BATCH * SEQ)   // 16384
#define KSPLIT 8
#define EPSV   1e-6f

// GEMM tiling (HMMA mma.sync; tcgen05 unavailable on compute_103 virtual arch)
#define BM 128
#define BN 128
#define NCH (DMODEL / 64)       // 16 chunks of 64 fp16 per 1024-row
#define GTHREADS 256
#define STAGES 4

// Blocked-swizzled fp16 layout: 16KB block per (row-tile of 128, 64-col chunk).
// Within a block: 128 rows x 128B, byte col ^ ((row&7)<<4)  (the smem image).
#define BLK_BYTES 16384

#define A_PL 0
#define B_PL 16384
#define STAGE 32768
#define SMEM_BYTES (1024 + STAGES * STAGE)   // 132096 (gemm)

#define KV_STAGE 32768                        // K 16KB + V 16KB
#define KV_SMEM  (1024 + 2 * KV_STAGE)        // 66560
#define AT_STAGE 24576                        // Q 16KB + kvT 8KB
#define AT_SMEM  (1024 + 2 * AT_STAGE)        // 50176

// ---------------- scratch (device globals; no allocation allowed) ------------
__device__ __half g_Ab[ROWS * DMODEL];              // input acts / S (blocked)
__device__ __half g_Wb[4 * DMODEL * DMODEL];        // blocked wq,wk,wv,wo
__device__ __half g_Qb[ROWS * DMODEL];              // Q fp16 blocked
__device__ __half g_Kb[ROWS * DMODEL];              // K fp16 blocked
__device__ __half g_Vb[ROWS * DMODEL];              // V fp16 blocked
__device__ float g_kvp[BATCH * HEADS * KSPLIT * DH * DH];
__device__ float g_zp [BATCH * HEADS * KSPLIT * DH];
__device__ __half g_kvT[BATCH * HEADS * DH * DH];   // kv^T fp16 swizzled [e][d]
__device__ float g_z  [BATCH * HEADS * DH];

// =============================== helpers ====================================
__device__ __forceinline__ uint32_t smem_u32(const void* p) {
    uint32_t a;
    asm("{ .reg .u64 t; cvta.to.shared.u64 t, %1; cvt.u32.u64 %0, t; }"
        : "=r"(a) : "l"(p));
    return a;
}
__device__ __forceinline__ void ldsm4(uint32_t& r0, uint32_t& r1, uint32_t& r2,
                                      uint32_t& r3, uint32_t addr) {
    asm volatile("ldmatrix.sync.aligned.m8n8.x4.shared.b16 {%0,%1,%2,%3}, [%4];"
                 : "=r"(r0), "=r"(r1), "=r"(r2), "=r"(r3) : "r"(addr));
}
__device__ __forceinline__ void ldsm4t(uint32_t& r0, uint32_t& r1, uint32_t& r2,
                                       uint32_t& r3, uint32_t addr) {
    asm volatile("ldmatrix.sync.aligned.m8n8.x4.trans.shared.b16 {%0,%1,%2,%3}, [%4];"
                 : "=r"(r0), "=r"(r1), "=r"(r2), "=r"(r3) : "r"(addr));
}
__device__ __forceinline__ void mma_fp16(float* c, const uint32_t* a, const uint32_t* b) {
    asm volatile(
        "mma.sync.aligned.m16n8k16.row.col.f32.f16.f16.f32 "
        "{%0,%1,%2,%3}, {%4,%5,%6,%7}, {%8,%9}, {%0,%1,%2,%3};"
        : "+f"(c[0]), "+f"(c[1]), "+f"(c[2]), "+f"(c[3])
        : "r"(a[0]), "r"(a[1]), "r"(a[2]), "r"(a[3]), "r"(b[0]), "r"(b[1]));
}
__device__ __forceinline__ void mbar_init(uint32_t addr, uint32_t cnt) {
    asm volatile("mbarrier.init.shared.b64 [%0], %1;" :: "r"(addr), "r"(cnt) : "memory");
}
__device__ __forceinline__ void mbar_expect_tx(uint32_t addr, uint32_t bytes) {
    asm volatile("mbarrier.arrive.expect_tx.shared.b64 _, [%0], %1;"
                 :: "r"(addr), "r"(bytes) : "memory");
}
__device__ __forceinline__ void mbar_wait(uint32_t addr, uint32_t parity) {
    asm volatile(
        "{\n\t.reg .pred P;\n"
        "W%=:\n\t"
        "mbarrier.try_wait.parity.acquire.cta.shared::cta.b64 P, [%0], %1, 0x989680;\n\t"
        "@!P bra W%=;\n\t"
        "}"
        :: "r"(addr), "r"(parity) : "memory");
}
__device__ __forceinline__ void bulk_cp(uint32_t sdst, const void* gsrc,
                                        uint32_t bytes, uint32_t mbar) {
    asm volatile(
        "cp.async.bulk.shared::cta.global.mbarrier::complete_tx::bytes [%0], [%1], %2, [%3];"
        :: "r"(sdst), "l"(gsrc), "r"(bytes), "r"(mbar) : "memory");
}
__device__ __forceinline__ uint2 cvt_f16x4(float4 v) {
    __half2 p01 = __floats2half2_rn(v.x, v.y);
    __half2 p23 = __floats2half2_rn(v.z, v.w);
    return make_uint2(*(uint32_t*)&p01, *(uint32_t*)&p23);
}
__device__ __forceinline__ float h2sum(uint32_t r) {
    float2 f = __half22float2(*(__half2*)&r);
    return f.x + f.y;
}

// =============================================================================
// fp32 [rows][1024] -> blocked-swizzled fp16 (the smem image), grid-stride
// =============================================================================
__global__ __launch_bounds__(256)
void cvt_swz(const float* __restrict__ src, __half* __restrict__ dst, int n4) {
    for (int i = blockIdx.x * 256 + threadIdx.x; i < n4; i += gridDim.x * 256) {
        const int grow = i >> 8;
        const int gcol = (i & 255) * 4;
        const int blk  = grow >> 7;
        const int r    = grow & 127;
        const int c    = gcol >> 6;
        const uint32_t colb = (uint32_t)((gcol & 63) * 2);
        const size_t off = ((size_t)(blk * NCH + c) << 14)
                         + (uint32_t)(r * 128) + (colb ^ ((uint32_t)(r & 7) << 4));
        *(uint2*)((char*)dst + off) = cvt_f16x4(((const float4*)src)[i]);
    }
}

// =============================================================================
// GEMM (NT) via HMMA fp16 on blocked-swizzled operands.
// F16OUT: write fp16 blocked-swizzled (for Q/K/V); else fp32 row-major.
// =============================================================================
template<bool PHI, bool F16OUT>
__global__ __launch_bounds__(GTHREADS, 1)
void gemm_f16(const __half* __restrict__ Ab, const __half* __restrict__ Bb,
              const float* __restrict__ bias, void* __restrict__ Yv) {
    extern __shared__ char sm[];
    const uint32_t sbase = smem_u32(sm);
    const int tid = threadIdx.x;
    const int lane = tid & 31;
    const int wid = tid >> 5;
    const int wm = wid & 3;
    const int wn = wid >> 2;
    const int bm = blockIdx.y;
    const int bn = blockIdx.x;

    if (tid == 0) {
        #pragma unroll
        for (int s = 0; s < STAGES; s++) mbar_init(sbase + s * 8, 1);
    }
    __syncthreads();

    const char* gAb = (const char*)Ab + ((size_t)(bm * NCH) << 14);
    const char* gBb = (const char*)Bb + ((size_t)(bn * NCH) << 14);

    int row_a[2];
    row_a[0] = wm * 32 + (lane & 15);
    row_a[1] = row_a[0] + 16;
    const uint32_t a_colb = (uint32_t)((lane >> 4) << 4);
    uint32_t a_base[2], a_mask[2];
    #pragma unroll
    for (int mt = 0; mt < 2; mt++) {
        a_base[mt] = (uint32_t)(row_a[mt] * 128);
        a_mask[mt] = (uint32_t)((row_a[mt] & 7) << 4);
    }
    int nrow[4];
    #pragma unroll
    for (int ntp = 0; ntp < 4; ntp++)
        nrow[ntp] = wn * 64 + ntp * 16 + (lane & 7) + ((lane >> 4) << 3);
    const uint32_t b_colb = (lane & 8) ? 16u : 0u;
    uint32_t b_base[4], b_mask[4];
    #pragma unroll
    for (int ntp = 0; ntp < 4; ntp++) {
        b_base[ntp] = (uint32_t)(nrow[ntp] * 128);
        b_mask[ntp] = (uint32_t)((nrow[ntp] & 7) << 4);
    }

    float acc[2][8][4];
    #pragma unroll
    for (int mt = 0; mt < 2; mt++)
        #pragma unroll
        for (int nt = 0; nt < 8; nt++)
            #pragma unroll
            for (int i = 0; i < 4; i++) acc[mt][nt][i] = 0.f;

    auto issue = [&](int c) {
        const int s = c & (STAGES - 1);
        const uint32_t mb = sbase + s * 8;
        const uint32_t st = sbase + 1024 + s * STAGE;
        mbar_expect_tx(mb, 2 * BLK_BYTES);
        bulk_cp(st + A_PL, gAb + ((size_t)c << 14), BLK_BYTES, mb);
        bulk_cp(st + B_PL, gBb + ((size_t)c << 14), BLK_BYTES, mb);
    };

    if (tid == 0) { issue(0); issue(1); issue(2); }

    for (int c = 0; c < NCH; c++) {
        mbar_wait(sbase + (c & (STAGES - 1)) * 8, (c >> 2) & 1);
        if (tid == 0 && c + 3 < NCH) issue(c + 3);

        const uint32_t stg = sbase + 1024 + (uint32_t)((c & (STAGES - 1)) * STAGE);
        #pragma unroll
        for (int ks = 0; ks < 4; ks++) {
            const uint32_t kb = (uint32_t)(ks * 32);
            uint32_t Ar[2][4];
            #pragma unroll
            for (int mt = 0; mt < 2; mt++) {
                uint32_t off = a_base[mt] + ((kb + a_colb) ^ a_mask[mt]);
                ldsm4(Ar[mt][0], Ar[mt][1], Ar[mt][2], Ar[mt][3], stg + A_PL + off);
            }
            uint32_t Br[8][2];
            #pragma unroll
            for (int ntp = 0; ntp < 4; ntp++) {
                uint32_t off = b_base[ntp] + ((kb + b_colb) ^ b_mask[ntp]);
                ldsm4(Br[2 * ntp][0], Br[2 * ntp][1], Br[2 * ntp + 1][0], Br[2 * ntp + 1][1],
                      stg + B_PL + off);
            }
            #pragma unroll
            for (int mt = 0; mt < 2; mt++)
                #pragma unroll
                for (int nt = 0; nt < 8; nt++)
                    mma_fp16(acc[mt][nt], Ar[mt], Br[nt]);
        }
        __syncthreads();
    }

    // ---- epilogue ----
    const int lr = lane >> 2;
    const int lc = lane & 3;
    #pragma unroll
    for (int mt = 0; mt < 2; mt++) {
        const int r0l = wm * 32 + mt * 16 + lr;         // local row in tile
        #pragma unroll
        for (int nt = 0; nt < 8; nt++) {
            const int gc = bn * BN + wn * 64 + nt * 8 + lc * 2;
            const float b0 = __ldg(&bias[gc]);
            const float b1 = __ldg(&bias[gc + 1]);
            float o00 = acc[mt][nt][0] + b0;
            float o01 = acc[mt][nt][1] + b1;
            float o10 = acc[mt][nt][2] + b0;
            float o11 = acc[mt][nt][3] + b1;
            if (PHI) {
                o00 = (o00 > 0.f) ? (o00 + 1.f) : __expf(o00);
                o01 = (o01 > 0.f) ? (o01 + 1.f) : __expf(o01);
                o10 = (o10 > 0.f) ? (o10 + 1.f) : __expf(o10);
                o11 = (o11 > 0.f) ? (o11 + 1.f) : __expf(o11);
            }
            if (F16OUT) {
                __half* Yh = (__half*)Yv;
                const int cch = gc >> 6;
                const uint32_t colb = (uint32_t)((gc & 63) * 2);
                const size_t blkb = ((size_t)(bm * NCH + cch)) << 14;
                __half2 p0 = __floats2half2_rn(o00, o01);
                __half2 p1 = __floats2half2_rn(o10, o11);
                const uint32_t ra = (uint32_t)r0l, rb = (uint32_t)(r0l + 8);
                *(uint32_t*)((char*)Yh + blkb + ra * 128 + (colb ^ ((ra & 7) << 4))) =
                    *(uint32_t*)&p0;
                *(uint32_t*)((char*)Yh + blkb + rb * 128 + (colb ^ ((rb & 7) << 4))) =
                    *(uint32_t*)&p1;
            } else {
                float* Y = (float*)Yv;
                const int gr0 = bm * BM + r0l;
                *(float2*)(Y + (size_t)gr0 * DMODEL + gc)       = make_float2(o00, o01);
                *(float2*)(Y + (size_t)(gr0 + 8) * DMODEL + gc) = make_float2(o10, o11);
            }
        }
    }
}

// =============================================================================
// kv partial via HMMA:  C[d][e] = sum_m K[m][d]*V[m][e]  over 512-m split,
// z[d] = sum_m K[m][d] extracted from A fragments.
// Block: 128 threads (4 warps, warp w -> d in [16w,16w+16)). K,V fp16 blocked.
// =============================================================================
__global__ __launch_bounds__(128, 1)
void kv_hmma(const __half* __restrict__ Kb, const __half* __restrict__ Vb,
             float* __restrict__ kvp, float* __restrict__ zp) {
    extern __shared__ char sm[];
    const uint32_t sbase = smem_u32(sm);
    const int tid = threadIdx.x;
    const int lane = tid & 31;
    const int wid = tid >> 5;

    const int s  = blockIdx.x % KSPLIT;
    const int bh = blockIdx.x / KSPLIT;
    const int b = bh / HEADS, h = bh % HEADS;
    const int blkbase = b * (SEQ / 128) + s * 4;

    if (tid == 0) { mbar_init(sbase, 1); mbar_init(sbase + 8, 1); }
    __syncthreads();

    auto issue = [&](int j) {
        const int st = j & 1;
        const uint32_t mb = sbase + st * 8;
        const uint32_t dst = sbase + 1024 + st * KV_STAGE;
        mbar_expect_tx(mb, 2 * BLK_BYTES);
        const size_t off = ((size_t)((blkbase + j) * NCH + h)) << 14;
        bulk_cp(dst,         (const char*)Kb + off, BLK_BYTES, mb);
        bulk_cp(dst + 16384, (const char*)Vb + off, BLK_BYTES, mb);
    };
    if (tid == 0) { issue(0); issue(1); }

    const int d0 = wid * 16;
    // A (K^T, trans): lanes 0-7 m0-7/cb0, 8-15 m0-7/cb16, 16-23 m8-15/cb0, 24-31 m8-15/cb16
    const int a_rloc = (lane & 7) + ((lane >> 4) << 3);
    const uint32_t a_cb = (uint32_t)(d0 * 2) + (uint32_t)(((lane >> 3) & 1) << 4);
    const uint32_t a_off = (uint32_t)(a_rloc * 128) + (a_cb ^ ((uint32_t)(a_rloc & 7) << 4));
    // B (V trans): lanes 0-7 m0-7/e0, 8-15 m8-15/e0, 16-23 m0-7/e0+8, 24-31 m8-15/e0+8
    const int b_rloc = (lane & 7) + (((lane >> 3) & 1) << 3);
    const uint32_t b_cb0 = (uint32_t)((lane >> 4) << 4);
    uint32_t b_off[4];
    #pragma unroll
    for (int e4 = 0; e4 < 4; e4++)
        b_off[e4] = (uint32_t)(b_rloc * 128)
                  + (((uint32_t)(e4 * 32) + b_cb0) ^ ((uint32_t)(b_rloc & 7) << 4));

    float acc[8][4];
    #pragma unroll
    for (int nt = 0; nt < 8; nt++)
        #pragma unroll
        for (int i = 0; i < 4; i++) acc[nt][i] = 0.f;
    float zs0 = 0.f, zs1 = 0.f;

    for (int j = 0; j < 4; j++) {
        mbar_wait(sbase + (j & 1) * 8, (j >> 1) & 1);
        const uint32_t bK = sbase + 1024 + (j & 1) * KV_STAGE;
        const uint32_t bV = bK + 16384;
        #pragma unroll
        for (int ks = 0; ks < 8; ks++) {
            uint32_t Ar[4];
            ldsm4t(Ar[0], Ar[1], Ar[2], Ar[3], bK + (uint32_t)(ks * 2048) + a_off);
            uint32_t Br[8][2];
            #pragma unroll
            for (int e4 = 0; e4 < 4; e4++) {
                uint32_t r0, r1, r2, r3;
                ldsm4t(r0, r1, r2, r3, bV + (uint32_t)(ks * 2048) + b_off[e4]);
                Br[2 * e4][0] = r0; Br[2 * e4][1] = r1;
                Br[2 * e4 + 1][0] = r2; Br[2 * e4 + 1][1] = r3;
            }
            #pragma unroll
            for (int nt = 0; nt < 8; nt++) mma_fp16(acc[nt], Ar, Br[nt]);
            zs0 += h2sum(Ar[0]) + h2sum(Ar[2]);
            zs1 += h2sum(Ar[1]) + h2sum(Ar[3]);
        }
        __syncthreads();
        if (tid == 0 && j + 2 < 4) issue(j + 2);
    }

    // z reduce over the 4 lanes of each group
    zs0 += __shfl_xor_sync(0xFFFFFFFF, zs0, 1);
    zs0 += __shfl_xor_sync(0xFFFFFFFF, zs0, 2);
    zs1 += __shfl_xor_sync(0xFFFFFFFF, zs1, 1);
    zs1 += __shfl_xor_sync(0xFFFFFFFF, zs1, 2);

    const int g = lane >> 2;
    const int ec = 2 * (lane & 3);
    float* kout = kvp + (size_t)blockIdx.x * (DH * DH);
    #pragma unroll
    for (int nt = 0; nt < 8; nt++) {
        *(float2*)&kout[(d0 + g) * DH + nt * 8 + ec]     = make_float2(acc[nt][0], acc[nt][1]);
        *(float2*)&kout[(d0 + g + 8) * DH + nt * 8 + ec] = make_float2(acc[nt][2], acc[nt][3]);
    }
    if ((lane & 3) == 0) {
        zp[(size_t)blockIdx.x * DH + d0 + g]     = zs0;
        zp[(size_t)blockIdx.x * DH + d0 + g + 8] = zs1;
    }
}

// =============================================================================
// reduce partials -> kvT fp16 swizzled [e][d] + z fp32
// =============================================================================
__global__ __launch_bounds__(256)
void kv_reduce(const float* __restrict__ kvp, const float* __restrict__ zp,
               __half* __restrict__ kvT, float* __restrict__ zo) {
    const int bh = blockIdx.x;
    const int tid = threadIdx.x;
    for (int i = tid; i < DH * DH; i += 256) {
        float sum = 0.f;
        #pragma unroll
        for (int s = 0; s < KSPLIT; s++)
            sum += kvp[((size_t)bh * KSPLIT + s) * (DH * DH) + i];
        const int d = i >> 6, e = i & 63;
        const size_t off = (size_t)bh * 8192 + (uint32_t)(e * 128)
                         + (((uint32_t)(d * 2)) ^ ((uint32_t)(e & 7) << 4));
        *(__half*)((char*)kvT + off) = __float2half_rn(sum);
    }
    if (tid < DH) {
        float sum = 0.f;
        #pragma unroll
        for (int s = 0; s < KSPLIT; s++)
            sum += zp[((size_t)bh * KSPLIT + s) * DH + tid];
        zo[(size_t)bh * DH + tid] = sum;
    }
}

// =============================================================================
// attn via HMMA: out[n][e] = (sum_d Q[n][d] kvT[e][d]) / (q.z + eps), fp16 in/out.
// Block: 256 threads (8 warps, warp w -> rows 16w..16w+16), loops 16 heads.
// =============================================================================
__global__ __launch_bounds__(256, 1)
void attn_hmma(const __half* __restrict__ Qb, const __half* __restrict__ kvT,
               const float* __restrict__ z, __half* __restrict__ Sb) {
    extern __shared__ char sm[];
    __shared__ float zsm[2][64];
    const uint32_t sbase = smem_u32(sm);
    const int tid = threadIdx.x;
    const int lane = tid & 31;
    const int wid = tid >> 5;
    const int blk = blockIdx.x;
    const int b = blk >> 5;                    // 32 row-blocks per batch

    if (tid == 0) { mbar_init(sbase, 1); mbar_init(sbase + 8, 1); }

    auto issue = [&](int h) {
        const int st = h & 1;
        const uint32_t mb = sbase + st * 8;
        const uint32_t dst = sbase + 1024 + st * AT_STAGE;
        mbar_expect_tx(mb, 16384 + 8192);
        bulk_cp(dst, (const char*)Qb + (((size_t)(blk * NCH + h)) << 14), 16384, mb);
        bulk_cp(dst + 16384, (const char*)kvT + (((size_t)(b * HEADS + h)) << 13), 8192, mb);
    };
    __syncthreads();
    if (tid == 0) { issue(0); issue(1); }
    if (tid < 64) {
        zsm[0][tid] = z[(size_t)(b * HEADS + 0) * DH + tid];
        zsm[1][tid] = z[(size_t)(b * HEADS + 1) * DH + tid];
    }
    __syncthreads();

    // A (Q, normal): row = wid*16 + (lane&15), colb base = (lane>>4)<<4
    const int row_a = wid * 16 + (lane & 15);
    const uint32_t a_base = (uint32_t)(row_a * 128);
    const uint32_t a_mask = (uint32_t)((row_a & 7) << 4);
    const uint32_t a_colb = (uint32_t)((lane >> 4) << 4);
    // B (kvT, normal; same pattern as main GEMM)
    int nrow[4];
    #pragma unroll
    for (int ntp = 0; ntp < 4; ntp++)
        nrow[ntp] = ntp * 16 + (lane & 7) + ((lane >> 4) << 3);
    const uint32_t b_colb = (lane & 8) ? 16u : 0u;
    uint32_t b_base[4], b_mask[4];
    #pragma unroll
    for (int ntp = 0; ntp < 4; ntp++) {
        b_base[ntp] = (uint32_t)(nrow[ntp] * 128);
        b_mask[ntp] = (uint32_t)((nrow[ntp] & 7) << 4);
    }

    const int g = lane >> 2;
    const int ec = 2 * (lane & 3);

    for (int h = 0; h < HEADS; h++) {
        const int st = h & 1;
        mbar_wait(sbase + st * 8, (h >> 1) & 1);
        const uint32_t bQ = sbase + 1024 + st * AT_STAGE;
        const uint32_t bKV = bQ + 16384;

        float acc[8][4];
        #pragma unroll
        for (int nt = 0; nt < 8; nt++)
            #pragma unroll
            for (int i = 0; i < 4; i++) acc[nt][i] = 0.f;
        float den0 = 0.f, den1 = 0.f;

        #pragma unroll
        for (int ks = 0; ks < 4; ks++) {
            const uint32_t kb = (uint32_t)(ks * 32);
            uint32_t Ar[4];
            ldsm4(Ar[0], Ar[1], Ar[2], Ar[3], bQ + a_base + ((kb + a_colb) ^ a_mask));
            uint32_t Br[8][2];
            #pragma unroll
            for (int ntp = 0; ntp < 4; ntp++) {
                uint32_t off = b_base[ntp] + ((kb + b_colb) ^ b_mask[ntp]);
                ldsm4(Br[2 * ntp][0], Br[2 * ntp][1], Br[2 * ntp + 1][0], Br[2 * ntp + 1][1],
                      bKV + off);
            }
            #pragma unroll
            for (int nt = 0; nt < 8; nt++) mma_fp16(acc[nt], Ar, Br[nt]);

            // den from A fragments
            const int dbase = ks * 16 + ec;
            const float z0 = zsm[st][dbase],     z1 = zsm[st][dbase + 1];
            const float z8 = zsm[st][dbase + 8], z9 = zsm[st][dbase + 9];
            float2 a0 = __half22float2(*(__half2*)&Ar[0]);
            float2 a1 = __half22float2(*(__half2*)&Ar[1]);
            float2 a2 = __half22float2(*(__half2*)&Ar[2]);
            float2 a3 = __half22float2(*(__half2*)&Ar[3]);
            den0 += a0.x * z0 + a0.y * z1 + a2.x * z8 + a2.y * z9;
            den1 += a1.x * z0 + a1.y * z1 + a3.x * z8 + a3.y * z9;
        }
        den0 += __shfl_xor_sync(0xFFFFFFFF, den0, 1);
        den0 += __shfl_xor_sync(0xFFFFFFFF, den0, 2);
        den1 += __shfl_xor_sync(0xFFFFFFFF, den1, 1);
        den1 += __shfl_xor_sync(0xFFFFFFFF, den1, 2);
        const float rinv0 = 1.0f / (den0 + EPSV);
        const float rinv1 = 1.0f / (den1 + EPSV);

        // store S block (blk, chunk h)
        const size_t blkb = ((size_t)(blk * NCH + h)) << 14;
        const uint32_t ra = (uint32_t)(wid * 16 + g);
        const uint32_t rb = ra + 8;
        #pragma unroll
        for (int nt = 0; nt < 8; nt++) {
            const uint32_t colb = (uint32_t)((nt * 8 + ec) * 2);
            __half2 p0 = __floats2half2_rn(acc[nt][0] * rinv0, acc[nt][1] * rinv0);
            __half2 p1 = __floats2half2_rn(acc[nt][2] * rinv1, acc[nt][3] * rinv1);
            *(uint32_t*)((char*)Sb + blkb + ra * 128 + (colb ^ ((ra & 7) << 4))) =
                *(uint32_t*)&p0;
            *(uint32_t*)((char*)Sb + blkb + rb * 128 + (colb ^ ((rb & 7) << 4))) =
                *(uint32_t*)&p1;
        }
        __syncthreads();
        if (tid == 0 && h + 2 < HEADS) issue(h + 2);
        if (tid < 64 && h + 2 < HEADS)
            zsm[st][tid] = z[(size_t)(b * HEADS + h + 2) * DH + tid];
    }
}

// =============================================================================
extern "C" void kernel_launch(void* const* d_in, const int* in_sizes, int n_in,
                              void* d_out, int out_size) {
    const float* queries = (const float*)d_in[0];
    const float* keys    = (const float*)d_in[1];
    const float* values  = (const float*)d_in[2];
    const float* wq = (const float*)d_in[3];
    const float* bq = (const float*)d_in[4];
    const float* wk = (const float*)d_in[5];
    const float* bk = (const float*)d_in[6];
    const float* wv = (const float*)d_in[7];
    const float* bv = (const float*)d_in[8];
    const float* wo = (const float*)d_in[9];
    const float* bo = (const float*)d_in[10];
    float* out = (float*)d_out;

    __half *Abp, *Wbp, *Qbp, *Kbp, *Vbp, *kvTp;
    float *kvp, *zp, *zb;
    cudaGetSymbolAddress((void**)&Abp, g_Ab);
    cudaGetSymbolAddress((void**)&Wbp, g_Wb);
    cudaGetSymbolAddress((void**)&Qbp, g_Qb);
    cudaGetSymbolAddress((void**)&Kbp, g_Kb);
    cudaGetSymbolAddress((void**)&Vbp, g_Vb);
    cudaGetSymbolAddress((void**)&kvTp, g_kvT);
    cudaGetSymbolAddress((void**)&kvp, g_kvp);
    cudaGetSymbolAddress((void**)&zp,  g_zp);
    cudaGetSymbolAddress((void**)&zb,  g_z);

    cudaFuncSetAttribute(gemm_f16<true , true >, cudaFuncAttributeMaxDynamicSharedMemorySize, SMEM_BYTES);
    cudaFuncSetAttribute(gemm_f16<false, true >, cudaFuncAttributeMaxDynamicSharedMemorySize, SMEM_BYTES);
    cudaFuncSetAttribute(gemm_f16<false, false>, cudaFuncAttributeMaxDynamicSharedMemorySize, SMEM_BYTES);
    cudaFuncSetAttribute(kv_hmma,   cudaFuncAttributeMaxDynamicSharedMemorySize, KV_SMEM);
    cudaFuncSetAttribute(attn_hmma, cudaFuncAttributeMaxDynamicSharedMemorySize, AT_SMEM);

    const int WSZ = DMODEL * DMODEL;
    const int XN4 = ROWS * DMODEL / 4;
    const int WN4 = WSZ / 4;

    dim3 gg(DMODEL / BN, ROWS / BM);       // (8, 128)
    dim3 gb(GTHREADS);

    // weights -> blocked-swizzled fp16 (once)
    cvt_swz<<<512, 256>>>(wq, Wbp + 0 * WSZ, WN4);
    cvt_swz<<<512, 256>>>(wk, Wbp + 1 * WSZ, WN4);
    cvt_swz<<<512, 256>>>(wv, Wbp + 2 * WSZ, WN4);
    cvt_swz<<<512, 256>>>(wo, Wbp + 3 * WSZ, WN4);

    // projections (fp16 blocked outputs)
    cvt_swz<<<2048, 256>>>(queries, Abp, XN4);
    gemm_f16<true , true ><<<gg, gb, SMEM_BYTES>>>(Abp, Wbp + 0 * WSZ, bq, Qbp);
    cvt_swz<<<2048, 256>>>(keys, Abp, XN4);
    gemm_f16<true , true ><<<gg, gb, SMEM_BYTES>>>(Abp, Wbp + 1 * WSZ, bk, Kbp);
    cvt_swz<<<2048, 256>>>(values, Abp, XN4);
    gemm_f16<false, true ><<<gg, gb, SMEM_BYTES>>>(Abp, Wbp + 2 * WSZ, bv, Vbp);

    kv_hmma  <<<BATCH * HEADS * KSPLIT, 128, KV_SMEM>>>(Kbp, Vbp, kvp, zp);
    kv_reduce<<<BATCH * HEADS, 256>>>(kvp, zp, kvTp, zb);
    attn_hmma<<<ROWS / 128, 256, AT_SMEM>>>(Qbp, kvTp, zb, Abp);   // S -> blocked

    // output projection (fp32 out)
    gemm_f16<false, false><<<gg, gb, SMEM_BYTES>>>(Abp, Wbp + 3 * WSZ, bo, out);
}

// round 9
// speedup vs baseline: 8.9609x; 1.1370x over previous
#include <cuda_runtime.h>
#include <cuda_fp16.h>
#include <cstdint>

// Problem constants (fixed by reference)
#define DMODEL 1024
#define HEADS  16
#define DH     64
#define BATCH  4
#define SEQ    4096
#define ROWS   (BATCH * SEQ)   // 16384
#define KSPLIT 8
#define EPSV   1e-6f

// GEMM tiling (HMMA mma.sync; tcgen05 unavailable on compute_103 virtual arch)
#define BM 128
#define BN 128
#define NCH (DMODEL / 64)       // 16 chunks of 64 fp16 per 1024-row
#define GTHREADS 256
#define STAGES 3                // 99KB smem -> 2 CTAs/SM

// Blocked-swizzled fp16 layout: 16KB block per (row-tile of 128, 64-col chunk).
#define BLK_BYTES 16384

#define A_PL 0
#define B_PL 16384
#define STAGE 32768
#define SMEM_BYTES (1024 + STAGES * STAGE)   // 99328

#define KV_STAGE 32768                        // K 16KB + V 16KB
#define KV_SMEM  (1024 + 2 * KV_STAGE)        // 66560
#define AT_STAGE 24576                        // Q 16KB + kvT 8KB
#define AT_SMEM  (1024 + 2 * AT_STAGE)        // 50176

// ---------------- scratch (device globals; no allocation allowed) ------------
__device__ __half g_Ab[ROWS * DMODEL];              // input acts / S (blocked)
__device__ __half g_Wb[4 * DMODEL * DMODEL];        // blocked wq,wk,wv,wo
__device__ __half g_Qb[ROWS * DMODEL];              // Q fp16 blocked
__device__ __half g_Kb[ROWS * DMODEL];              // K fp16 blocked
__device__ __half g_Vb[ROWS * DMODEL];              // V fp16 blocked
__device__ float g_kvp[BATCH * HEADS * KSPLIT * DH * DH];
__device__ float g_zp [BATCH * HEADS * KSPLIT * DH];
__device__ __half g_kvT[BATCH * HEADS * DH * DH];   // kv^T fp16 swizzled [e][d]
__device__ float g_z  [BATCH * HEADS * DH];

// =============================== helpers ====================================
__device__ __forceinline__ uint32_t smem_u32(const void* p) {
    uint32_t a;
    asm("{ .reg .u64 t; cvta.to.shared.u64 t, %1; cvt.u32.u64 %0, t; }"
        : "=r"(a) : "l"(p));
    return a;
}
__device__ __forceinline__ void ldsm4(uint32_t& r0, uint32_t& r1, uint32_t& r2,
                                      uint32_t& r3, uint32_t addr) {
    asm volatile("ldmatrix.sync.aligned.m8n8.x4.shared.b16 {%0,%1,%2,%3}, [%4];"
                 : "=r"(r0), "=r"(r1), "=r"(r2), "=r"(r3) : "r"(addr));
}
__device__ __forceinline__ void ldsm4t(uint32_t& r0, uint32_t& r1, uint32_t& r2,
                                       uint32_t& r3, uint32_t addr) {
    asm volatile("ldmatrix.sync.aligned.m8n8.x4.trans.shared.b16 {%0,%1,%2,%3}, [%4];"
                 : "=r"(r0), "=r"(r1), "=r"(r2), "=r"(r3) : "r"(addr));
}
__device__ __forceinline__ void mma_fp16(float* c, const uint32_t* a, const uint32_t* b) {
    asm volatile(
        "mma.sync.aligned.m16n8k16.row.col.f32.f16.f16.f32 "
        "{%0,%1,%2,%3}, {%4,%5,%6,%7}, {%8,%9}, {%0,%1,%2,%3};"
        : "+f"(c[0]), "+f"(c[1]), "+f"(c[2]), "+f"(c[3])
        : "r"(a[0]), "r"(a[1]), "r"(a[2]), "r"(a[3]), "r"(b[0]), "r"(b[1]));
}
__device__ __forceinline__ void mbar_init(uint32_t addr, uint32_t cnt) {
    asm volatile("mbarrier.init.shared.b64 [%0], %1;" :: "r"(addr), "r"(cnt) : "memory");
}
__device__ __forceinline__ void mbar_expect_tx(uint32_t addr, uint32_t bytes) {
    asm volatile("mbarrier.arrive.expect_tx.shared.b64 _, [%0], %1;"
                 :: "r"(addr), "r"(bytes) : "memory");
}
__device__ __forceinline__ void mbar_wait(uint32_t addr, uint32_t parity) {
    asm volatile(
        "{\n\t.reg .pred P;\n"
        "W%=:\n\t"
        "mbarrier.try_wait.parity.acquire.cta.shared::cta.b64 P, [%0], %1, 0x989680;\n\t"
        "@!P bra W%=;\n\t"
        "}"
        :: "r"(addr), "r"(parity) : "memory");
}
__device__ __forceinline__ void bulk_cp(uint32_t sdst, const void* gsrc,
                                        uint32_t bytes, uint32_t mbar) {
    asm volatile(
        "cp.async.bulk.shared::cta.global.mbarrier::complete_tx::bytes [%0], [%1], %2, [%3];"
        :: "r"(sdst), "l"(gsrc), "r"(bytes), "r"(mbar) : "memory");
}
__device__ __forceinline__ uint2 cvt_f16x4(float4 v) {
    __half2 p01 = __floats2half2_rn(v.x, v.y);
    __half2 p23 = __floats2half2_rn(v.z, v.w);
    return make_uint2(*(uint32_t*)&p01, *(uint32_t*)&p23);
}
__device__ __forceinline__ float h2sum(uint32_t r) {
    float2 f = __half22float2(*(__half2*)&r);
    return f.x + f.y;
}

// =============================================================================
// fp32 [rows][1024] -> blocked-swizzled fp16 (the smem image), grid-stride
// =============================================================================
__global__ __launch_bounds__(256)
void cvt_swz(const float* __restrict__ src, __half* __restrict__ dst, int n4) {
    for (int i = blockIdx.x * 256 + threadIdx.x; i < n4; i += gridDim.x * 256) {
        const int grow = i >> 8;
        const int gcol = (i & 255) * 4;
        const int blk  = grow >> 7;
        const int r    = grow & 127;
        const int c    = gcol >> 6;
        const uint32_t colb = (uint32_t)((gcol & 63) * 2);
        const size_t off = ((size_t)(blk * NCH + c) << 14)
                         + (uint32_t)(r * 128) + (colb ^ ((uint32_t)(r & 7) << 4));
        *(uint2*)((char*)dst + off) = cvt_f16x4(((const float4*)src)[i]);
    }
}

// =============================================================================
// GEMM (NT) via HMMA fp16 on blocked-swizzled operands.
// F16OUT: write fp16 blocked-swizzled (for Q/K/V); else fp32 row-major.
// 3 stages / 99KB smem -> 2 CTAs per SM (cross-CTA latency hiding).
// =============================================================================
template<bool PHI, bool F16OUT>
__global__ __launch_bounds__(GTHREADS, 2)
void gemm_f16(const __half* __restrict__ Ab, const __half* __restrict__ Bb,
              const float* __restrict__ bias, void* __restrict__ Yv) {
    extern __shared__ char sm[];
    const uint32_t sbase = smem_u32(sm);
    const int tid = threadIdx.x;
    const int lane = tid & 31;
    const int wid = tid >> 5;
    const int wm = wid & 3;
    const int wn = wid >> 2;
    const int bm = blockIdx.y;
    const int bn = blockIdx.x;

    if (tid == 0) {
        #pragma unroll
        for (int s = 0; s < STAGES; s++) mbar_init(sbase + s * 8, 1);
    }
    __syncthreads();

    const char* gAb = (const char*)Ab + ((size_t)(bm * NCH) << 14);
    const char* gBb = (const char*)Bb + ((size_t)(bn * NCH) << 14);

    int row_a[2];
    row_a[0] = wm * 32 + (lane & 15);
    row_a[1] = row_a[0] + 16;
    const uint32_t a_colb = (uint32_t)((lane >> 4) << 4);
    uint32_t a_base[2], a_mask[2];
    #pragma unroll
    for (int mt = 0; mt < 2; mt++) {
        a_base[mt] = (uint32_t)(row_a[mt] * 128);
        a_mask[mt] = (uint32_t)((row_a[mt] & 7) << 4);
    }
    int nrow[4];
    #pragma unroll
    for (int ntp = 0; ntp < 4; ntp++)
        nrow[ntp] = wn * 64 + ntp * 16 + (lane & 7) + ((lane >> 4) << 3);
    const uint32_t b_colb = (lane & 8) ? 16u : 0u;
    uint32_t b_base[4], b_mask[4];
    #pragma unroll
    for (int ntp = 0; ntp < 4; ntp++) {
        b_base[ntp] = (uint32_t)(nrow[ntp] * 128);
        b_mask[ntp] = (uint32_t)((nrow[ntp] & 7) << 4);
    }

    float acc[2][8][4];
    #pragma unroll
    for (int mt = 0; mt < 2; mt++)
        #pragma unroll
        for (int nt = 0; nt < 8; nt++)
            #pragma unroll
            for (int i = 0; i < 4; i++) acc[mt][nt][i] = 0.f;

    auto issue = [&](int c) {
        const int s = c % STAGES;
        const uint32_t mb = sbase + s * 8;
        const uint32_t st = sbase + 1024 + s * STAGE;
        mbar_expect_tx(mb, 2 * BLK_BYTES);
        bulk_cp(st + A_PL, gAb + ((size_t)c << 14), BLK_BYTES, mb);
        bulk_cp(st + B_PL, gBb + ((size_t)c << 14), BLK_BYTES, mb);
    };

    if (tid == 0) { issue(0); issue(1); }

    for (int c = 0; c < NCH; c++) {
        mbar_wait(sbase + (c % STAGES) * 8, (c / STAGES) & 1);
        if (tid == 0 && c + 2 < NCH) issue(c + 2);

        const uint32_t stg = sbase + 1024 + (uint32_t)((c % STAGES) * STAGE);
        #pragma unroll
        for (int ks = 0; ks < 4; ks++) {
            const uint32_t kb = (uint32_t)(ks * 32);
            uint32_t Ar[2][4];
            #pragma unroll
            for (int mt = 0; mt < 2; mt++) {
                uint32_t off = a_base[mt] + ((kb + a_colb) ^ a_mask[mt]);
                ldsm4(Ar[mt][0], Ar[mt][1], Ar[mt][2], Ar[mt][3], stg + A_PL + off);
            }
            uint32_t Br[8][2];
            #pragma unroll
            for (int ntp = 0; ntp < 4; ntp++) {
                uint32_t off = b_base[ntp] + ((kb + b_colb) ^ b_mask[ntp]);
                ldsm4(Br[2 * ntp][0], Br[2 * ntp][1], Br[2 * ntp + 1][0], Br[2 * ntp + 1][1],
                      stg + B_PL + off);
            }
            #pragma unroll
            for (int mt = 0; mt < 2; mt++)
                #pragma unroll
                for (int nt = 0; nt < 8; nt++)
                    mma_fp16(acc[mt][nt], Ar[mt], Br[nt]);
        }
        __syncthreads();
    }

    // ---- epilogue ----
    const int lr = lane >> 2;
    const int lc = lane & 3;
    #pragma unroll
    for (int mt = 0; mt < 2; mt++) {
        const int r0l = wm * 32 + mt * 16 + lr;         // local row in tile
        #pragma unroll
        for (int nt = 0; nt < 8; nt++) {
            const int gc = bn * BN + wn * 64 + nt * 8 + lc * 2;
            const float b0 = __ldg(&bias[gc]);
            const float b1 = __ldg(&bias[gc + 1]);
            float o00 = acc[mt][nt][0] + b0;
            float o01 = acc[mt][nt][1] + b1;
            float o10 = acc[mt][nt][2] + b0;
            float o11 = acc[mt][nt][3] + b1;
            if (PHI) {
                o00 = (o00 > 0.f) ? (o00 + 1.f) : __expf(o00);
                o01 = (o01 > 0.f) ? (o01 + 1.f) : __expf(o01);
                o10 = (o10 > 0.f) ? (o10 + 1.f) : __expf(o10);
                o11 = (o11 > 0.f) ? (o11 + 1.f) : __expf(o11);
            }
            if (F16OUT) {
                __half* Yh = (__half*)Yv;
                const int cch = gc >> 6;
                const uint32_t colb = (uint32_t)((gc & 63) * 2);
                const size_t blkb = ((size_t)(bm * NCH + cch)) << 14;
                __half2 p0 = __floats2half2_rn(o00, o01);
                __half2 p1 = __floats2half2_rn(o10, o11);
                const uint32_t ra = (uint32_t)r0l, rb = (uint32_t)(r0l + 8);
                *(uint32_t*)((char*)Yh + blkb + ra * 128 + (colb ^ ((ra & 7) << 4))) =
                    *(uint32_t*)&p0;
                *(uint32_t*)((char*)Yh + blkb + rb * 128 + (colb ^ ((rb & 7) << 4))) =
                    *(uint32_t*)&p1;
            } else {
                float* Y = (float*)Yv;
                const int gr0 = bm * BM + r0l;
                *(float2*)(Y + (size_t)gr0 * DMODEL + gc)       = make_float2(o00, o01);
                *(float2*)(Y + (size_t)(gr0 + 8) * DMODEL + gc) = make_float2(o10, o11);
            }
        }
    }
}

// =============================================================================
// kv partial via HMMA:  C[d][e] = sum_m K[m][d]*V[m][e]  over 512-m split,
// z[d] = sum_m K[m][d] from A fragments.
// =============================================================================
__global__ __launch_bounds__(128, 1)
void kv_hmma(const __half* __restrict__ Kb, const __half* __restrict__ Vb,
             float* __restrict__ kvp, float* __restrict__ zp) {
    extern __shared__ char sm[];
    const uint32_t sbase = smem_u32(sm);
    const int tid = threadIdx.x;
    const int lane = tid & 31;
    const int wid = tid >> 5;

    const int s  = blockIdx.x % KSPLIT;
    const int bh = blockIdx.x / KSPLIT;
    const int b = bh / HEADS, h = bh % HEADS;
    const int blkbase = b * (SEQ / 128) + s * 4;

    if (tid == 0) { mbar_init(sbase, 1); mbar_init(sbase + 8, 1); }
    __syncthreads();

    auto issue = [&](int j) {
        const int st = j & 1;
        const uint32_t mb = sbase + st * 8;
        const uint32_t dst = sbase + 1024 + st * KV_STAGE;
        mbar_expect_tx(mb, 2 * BLK_BYTES);
        const size_t off = ((size_t)((blkbase + j) * NCH + h)) << 14;
        bulk_cp(dst,         (const char*)Kb + off, BLK_BYTES, mb);
        bulk_cp(dst + 16384, (const char*)Vb + off, BLK_BYTES, mb);
    };
    if (tid == 0) { issue(0); issue(1); }

    const int d0 = wid * 16;
    const int a_rloc = (lane & 7) + ((lane >> 4) << 3);
    const uint32_t a_cb = (uint32_t)(d0 * 2) + (uint32_t)(((lane >> 3) & 1) << 4);
    const uint32_t a_off = (uint32_t)(a_rloc * 128) + (a_cb ^ ((uint32_t)(a_rloc & 7) << 4));
    const int b_rloc = (lane & 7) + (((lane >> 3) & 1) << 3);
    const uint32_t b_cb0 = (uint32_t)((lane >> 4) << 4);
    uint32_t b_off[4];
    #pragma unroll
    for (int e4 = 0; e4 < 4; e4++)
        b_off[e4] = (uint32_t)(b_rloc * 128)
                  + (((uint32_t)(e4 * 32) + b_cb0) ^ ((uint32_t)(b_rloc & 7) << 4));

    float acc[8][4];
    #pragma unroll
    for (int nt = 0; nt < 8; nt++)
        #pragma unroll
        for (int i = 0; i < 4; i++) acc[nt][i] = 0.f;
    float zs0 = 0.f, zs1 = 0.f;

    for (int j = 0; j < 4; j++) {
        mbar_wait(sbase + (j & 1) * 8, (j >> 1) & 1);
        const uint32_t bK = sbase + 1024 + (j & 1) * KV_STAGE;
        const uint32_t bV = bK + 16384;
        #pragma unroll
        for (int ks = 0; ks < 8; ks++) {
            uint32_t Ar[4];
            ldsm4t(Ar[0], Ar[1], Ar[2], Ar[3], bK + (uint32_t)(ks * 2048) + a_off);
            uint32_t Br[8][2];
            #pragma unroll
            for (int e4 = 0; e4 < 4; e4++) {
                uint32_t r0, r1, r2, r3;
                ldsm4t(r0, r1, r2, r3, bV + (uint32_t)(ks * 2048) + b_off[e4]);
                Br[2 * e4][0] = r0; Br[2 * e4][1] = r1;
                Br[2 * e4 + 1][0] = r2; Br[2 * e4 + 1][1] = r3;
            }
            #pragma unroll
            for (int nt = 0; nt < 8; nt++) mma_fp16(acc[nt], Ar, Br[nt]);
            zs0 += h2sum(Ar[0]) + h2sum(Ar[2]);
            zs1 += h2sum(Ar[1]) + h2sum(Ar[3]);
        }
        __syncthreads();
        if (tid == 0 && j + 2 < 4) issue(j + 2);
    }

    zs0 += __shfl_xor_sync(0xFFFFFFFF, zs0, 1);
    zs0 += __shfl_xor_sync(0xFFFFFFFF, zs0, 2);
    zs1 += __shfl_xor_sync(0xFFFFFFFF, zs1, 1);
    zs1 += __shfl_xor_sync(0xFFFFFFFF, zs1, 2);

    const int g = lane >> 2;
    const int ec = 2 * (lane & 3);
    float* kout = kvp + (size_t)blockIdx.x * (DH * DH);
    #pragma unroll
    for (int nt = 0; nt < 8; nt++) {
        *(float2*)&kout[(d0 + g) * DH + nt * 8 + ec]     = make_float2(acc[nt][0], acc[nt][1]);
        *(float2*)&kout[(d0 + g + 8) * DH + nt * 8 + ec] = make_float2(acc[nt][2], acc[nt][3]);
    }
    if ((lane & 3) == 0) {
        zp[(size_t)blockIdx.x * DH + d0 + g]     = zs0;
        zp[(size_t)blockIdx.x * DH + d0 + g + 8] = zs1;
    }
}

// =============================================================================
// reduce partials -> kvT fp16 swizzled [e][d] + z fp32
// =============================================================================
__global__ __launch_bounds__(256)
void kv_reduce(const float* __restrict__ kvp, const float* __restrict__ zp,
               __half* __restrict__ kvT, float* __restrict__ zo) {
    const int bh = blockIdx.x;
    const int tid = threadIdx.x;
    for (int i = tid; i < DH * DH; i += 256) {
        float sum = 0.f;
        #pragma unroll
        for (int s = 0; s < KSPLIT; s++)
            sum += kvp[((size_t)bh * KSPLIT + s) * (DH * DH) + i];
        const int d = i >> 6, e = i & 63;
        const size_t off = (size_t)bh * 8192 + (uint32_t)(e * 128)
                         + (((uint32_t)(d * 2)) ^ ((uint32_t)(e & 7) << 4));
        *(__half*)((char*)kvT + off) = __float2half_rn(sum);
    }
    if (tid < DH) {
        float sum = 0.f;
        #pragma unroll
        for (int s = 0; s < KSPLIT; s++)
            sum += zp[((size_t)bh * KSPLIT + s) * DH + tid];
        zo[(size_t)bh * DH + tid] = sum;
    }
}

// =============================================================================
// attn via HMMA: out[n][e] = (sum_d Q[n][d] kvT[e][d]) / (q.z + eps), fp16 in/out.
// =============================================================================
__global__ __launch_bounds__(256, 1)
void attn_hmma(const __half* __restrict__ Qb, const __half* __restrict__ kvT,
               const float* __restrict__ z, __half* __restrict__ Sb) {
    extern __shared__ char sm[];
    __shared__ float zsm[2][64];
    const uint32_t sbase = smem_u32(sm);
    const int tid = threadIdx.x;
    const int lane = tid & 31;
    const int wid = tid >> 5;
    const int blk = blockIdx.x;
    const int b = blk >> 5;

    if (tid == 0) { mbar_init(sbase, 1); mbar_init(sbase + 8, 1); }

    auto issue = [&](int h) {
        const int st = h & 1;
        const uint32_t mb = sbase + st * 8;
        const uint32_t dst = sbase + 1024 + st * AT_STAGE;
        mbar_expect_tx(mb, 16384 + 8192);
        bulk_cp(dst, (const char*)Qb + (((size_t)(blk * NCH + h)) << 14), 16384, mb);
        bulk_cp(dst + 16384, (const char*)kvT + (((size_t)(b * HEADS + h)) << 13), 8192, mb);
    };
    __syncthreads();
    if (tid == 0) { issue(0); issue(1); }
    if (tid < 64) {
        zsm[0][tid] = z[(size_t)(b * HEADS + 0) * DH + tid];
        zsm[1][tid] = z[(size_t)(b * HEADS + 1) * DH + tid];
    }
    __syncthreads();

    const int row_a = wid * 16 + (lane & 15);
    const uint32_t a_base = (uint32_t)(row_a * 128);
    const uint32_t a_mask = (uint32_t)((row_a & 7) << 4);
    const uint32_t a_colb = (uint32_t)((lane >> 4) << 4);
    int nrow[4];
    #pragma unroll
    for (int ntp = 0; ntp < 4; ntp++)
        nrow[ntp] = ntp * 16 + (lane & 7) + ((lane >> 4) << 3);
    const uint32_t b_colb = (lane & 8) ? 16u : 0u;
    uint32_t b_base[4], b_mask[4];
    #pragma unroll
    for (int ntp = 0; ntp < 4; ntp++) {
        b_base[ntp] = (uint32_t)(nrow[ntp] * 128);
        b_mask[ntp] = (uint32_t)((nrow[ntp] & 7) << 4);
    }

    const int g = lane >> 2;
    const int ec = 2 * (lane & 3);

    for (int h = 0; h < HEADS; h++) {
        const int st = h & 1;
        mbar_wait(sbase + st * 8, (h >> 1) & 1);
        const uint32_t bQ = sbase + 1024 + st * AT_STAGE;
        const uint32_t bKV = bQ + 16384;

        float acc[8][4];
        #pragma unroll
        for (int nt = 0; nt < 8; nt++)
            #pragma unroll
            for (int i = 0; i < 4; i++) acc[nt][i] = 0.f;
        float den0 = 0.f, den1 = 0.f;

        #pragma unroll
        for (int ks = 0; ks < 4; ks++) {
            const uint32_t kb = (uint32_t)(ks * 32);
            uint32_t Ar[4];
            ldsm4(Ar[0], Ar[1], Ar[2], Ar[3], bQ + a_base + ((kb + a_colb) ^ a_mask));
            uint32_t Br[8][2];
            #pragma unroll
            for (int ntp = 0; ntp < 4; ntp++) {
                uint32_t off = b_base[ntp] + ((kb + b_colb) ^ b_mask[ntp]);
                ldsm4(Br[2 * ntp][0], Br[2 * ntp][1], Br[2 * ntp + 1][0], Br[2 * ntp + 1][1],
                      bKV + off);
            }
            #pragma unroll
            for (int nt = 0; nt < 8; nt++) mma_fp16(acc[nt], Ar, Br[nt]);

            const int dbase = ks * 16 + ec;
            const float z0 = zsm[st][dbase],     z1 = zsm[st][dbase + 1];
            const float z8 = zsm[st][dbase + 8], z9 = zsm[st][dbase + 9];
            float2 a0 = __half22float2(*(__half2*)&Ar[0]);
            float2 a1 = __half22float2(*(__half2*)&Ar[1]);
            float2 a2 = __half22float2(*(__half2*)&Ar[2]);
            float2 a3 = __half22float2(*(__half2*)&Ar[3]);
            den0 += a0.x * z0 + a0.y * z1 + a2.x * z8 + a2.y * z9;
            den1 += a1.x * z0 + a1.y * z1 + a3.x * z8 + a3.y * z9;
        }
        den0 += __shfl_xor_sync(0xFFFFFFFF, den0, 1);
        den0 += __shfl_xor_sync(0xFFFFFFFF, den0, 2);
        den1 += __shfl_xor_sync(0xFFFFFFFF, den1, 1);
        den1 += __shfl_xor_sync(0xFFFFFFFF, den1, 2);
        const float rinv0 = 1.0f / (den0 + EPSV);
        const float rinv1 = 1.0f / (den1 + EPSV);

        const size_t blkb = ((size_t)(blk * NCH + h)) << 14;
        const uint32_t ra = (uint32_t)(wid * 16 + g);
        const uint32_t rb = ra + 8;
        #pragma unroll
        for (int nt = 0; nt < 8; nt++) {
            const uint32_t colb = (uint32_t)((nt * 8 + ec) * 2);
            __half2 p0 = __floats2half2_rn(acc[nt][0] * rinv0, acc[nt][1] * rinv0);
            __half2 p1 = __floats2half2_rn(acc[nt][2] * rinv1, acc[nt][3] * rinv1);
            *(uint32_t*)((char*)Sb + blkb + ra * 128 + (colb ^ ((ra & 7) << 4))) =
                *(uint32_t*)&p0;
            *(uint32_t*)((char*)Sb + blkb + rb * 128 + (colb ^ ((rb & 7) << 4))) =
                *(uint32_t*)&p1;
        }
        __syncthreads();
        if (tid == 0 && h + 2 < HEADS) issue(h + 2);
        if (tid < 64 && h + 2 < HEADS)
            zsm[st][tid] = z[(size_t)(b * HEADS + h + 2) * DH + tid];
    }
}

// =============================================================================
extern "C" void kernel_launch(void* const* d_in, const int* in_sizes, int n_in,
                              void* d_out, int out_size) {
    const float* queries = (const float*)d_in[0];
    const float* keys    = (const float*)d_in[1];
    const float* values  = (const float*)d_in[2];
    const float* wq = (const float*)d_in[3];
    const float* bq = (const float*)d_in[4];
    const float* wk = (const float*)d_in[5];
    const float* bk = (const float*)d_in[6];
    const float* wv = (const float*)d_in[7];
    const float* bv = (const float*)d_in[8];
    const float* wo = (const float*)d_in[9];
    const float* bo = (const float*)d_in[10];
    float* out = (float*)d_out;

    __half *Abp, *Wbp, *Qbp, *Kbp, *Vbp, *kvTp;
    float *kvp, *zp, *zb;
    cudaGetSymbolAddress((void**)&Abp, g_Ab);
    cudaGetSymbolAddress((void**)&Wbp, g_Wb);
    cudaGetSymbolAddress((void**)&Qbp, g_Qb);
    cudaGetSymbolAddress((void**)&Kbp, g_Kb);
    cudaGetSymbolAddress((void**)&Vbp, g_Vb);
    cudaGetSymbolAddress((void**)&kvTp, g_kvT);
    cudaGetSymbolAddress((void**)&kvp, g_kvp);
    cudaGetSymbolAddress((void**)&zp,  g_zp);
    cudaGetSymbolAddress((void**)&zb,  g_z);

    cudaFuncSetAttribute(gemm_f16<true , true >, cudaFuncAttributeMaxDynamicSharedMemorySize, SMEM_BYTES);
    cudaFuncSetAttribute(gemm_f16<false, true >, cudaFuncAttributeMaxDynamicSharedMemorySize, SMEM_BYTES);
    cudaFuncSetAttribute(gemm_f16<false, false>, cudaFuncAttributeMaxDynamicSharedMemorySize, SMEM_BYTES);
    cudaFuncSetAttribute(kv_hmma,   cudaFuncAttributeMaxDynamicSharedMemorySize, KV_SMEM);
    cudaFuncSetAttribute(attn_hmma, cudaFuncAttributeMaxDynamicSharedMemorySize, AT_SMEM);

    const int WSZ = DMODEL * DMODEL;
    const int XN4 = ROWS * DMODEL / 4;
    const int WN4 = WSZ / 4;

    dim3 gg(DMODEL / BN, ROWS / BM);       // (8, 128)
    dim3 gb(GTHREADS);

    // weights -> blocked-swizzled fp16 (once)
    cvt_swz<<<1024, 256>>>(wq, Wbp + 0 * WSZ, WN4);
    cvt_swz<<<1024, 256>>>(wk, Wbp + 1 * WSZ, WN4);
    cvt_swz<<<1024, 256>>>(wv, Wbp + 2 * WSZ, WN4);
    cvt_swz<<<1024, 256>>>(wo, Wbp + 3 * WSZ, WN4);

    // projections (fp16 blocked outputs)
    cvt_swz<<<4096, 256>>>(queries, Abp, XN4);
    gemm_f16<true , true ><<<gg, gb, SMEM_BYTES>>>(Abp, Wbp + 0 * WSZ, bq, Qbp);
    cvt_swz<<<4096, 256>>>(keys, Abp, XN4);
    gemm_f16<true , true ><<<gg, gb, SMEM_BYTES>>>(Abp, Wbp + 1 * WSZ, bk, Kbp);
    cvt_swz<<<4096, 256>>>(values, Abp, XN4);
    gemm_f16<false, true ><<<gg, gb, SMEM_BYTES>>>(Abp, Wbp + 2 * WSZ, bv, Vbp);

    kv_hmma  <<<BATCH * HEADS * KSPLIT, 128, KV_SMEM>>>(Kbp, Vbp, kvp, zp);
    kv_reduce<<<BATCH * HEADS, 256>>>(kvp, zp, kvTp, zb);
    attn_hmma<<<ROWS / 128, 256, AT_SMEM>>>(Qbp, kvTp, zb, Abp);   // S -> blocked

    // output projection (fp32 out)
    gemm_f16<false, false><<<gg, gb, SMEM_BYTES>>>(Abp, Wbp + 3 * WSZ, bo, out);
}

// round 10
// speedup vs baseline: 10.1384x; 1.1314x over previous
#include <cuda_runtime.h>
#include <cuda_fp16.h>
#include <cstdint>

// Problem constants (fixed by reference)
#define DMODEL 1024
#define HEADS  16
#define DH     64
#define BATCH  4
#define SEQ    4096
#define ROWS   (BATCH * SEQ)   // 16384
#define KSPLIT 8
#define EPSV   1e-6f

// GEMM tiling (HMMA mma.sync; tcgen05 unavailable on compute_103 virtual arch)
#define BM 128
#define BN 128
#define NCH (DMODEL / 64)       // 16 chunks of 64 fp16 per 1024-row
#define GTHREADS 256
#define STAGES 3                // 99KB smem -> 2 CTAs/SM

// Blocked-swizzled fp16 layout: 16KB block per (row-tile of 128, 64-col chunk).
#define BLK_BYTES 16384

#define A_PL 0
#define B_PL 16384
#define STAGE 32768
#define SMEM_BYTES (1024 + STAGES * STAGE)   // 99328

#define KV_STAGE 32768                        // K 16KB + V 16KB
#define KV_SMEM  (1024 + 2 * KV_STAGE)        // 66560
#define AT_STAGE 24576                        // Q 16KB + kvT 8KB
#define AT_SMEM  (1024 + 2 * AT_STAGE)        // 50176

#define ASTRIDE ((size_t)ROWS * DMODEL)

// ---------------- scratch (device globals; no allocation allowed) ------------
__device__ __half g_Xb[3 * ROWS * DMODEL];          // blocked q/k/v inputs
__device__ __half g_Ab[ROWS * DMODEL];              // S (blocked)
__device__ __half g_Wb[4 * DMODEL * DMODEL];        // blocked wq,wk,wv,wo
__device__ __half g_Qb[ROWS * DMODEL];              // Q fp16 blocked
__device__ __half g_Kb[ROWS * DMODEL];              // K fp16 blocked
__device__ __half g_Vb[ROWS * DMODEL];              // V fp16 blocked
__device__ float g_kvp[BATCH * HEADS * KSPLIT * DH * DH];
__device__ float g_zp [BATCH * HEADS * KSPLIT * DH];
__device__ __half g_kvT[BATCH * HEADS * DH * DH];   // kv^T fp16 swizzled [e][d]
__device__ float g_z  [BATCH * HEADS * DH];

// =============================== helpers ====================================
__device__ __forceinline__ uint32_t smem_u32(const void* p) {
    uint32_t a;
    asm("{ .reg .u64 t; cvta.to.shared.u64 t, %1; cvt.u32.u64 %0, t; }"
        : "=r"(a) : "l"(p));
    return a;
}
__device__ __forceinline__ void ldsm4(uint32_t& r0, uint32_t& r1, uint32_t& r2,
                                      uint32_t& r3, uint32_t addr) {
    asm volatile("ldmatrix.sync.aligned.m8n8.x4.shared.b16 {%0,%1,%2,%3}, [%4];"
                 : "=r"(r0), "=r"(r1), "=r"(r2), "=r"(r3) : "r"(addr));
}
__device__ __forceinline__ void ldsm4t(uint32_t& r0, uint32_t& r1, uint32_t& r2,
                                       uint32_t& r3, uint32_t addr) {
    asm volatile("ldmatrix.sync.aligned.m8n8.x4.trans.shared.b16 {%0,%1,%2,%3}, [%4];"
                 : "=r"(r0), "=r"(r1), "=r"(r2), "=r"(r3) : "r"(addr));
}
__device__ __forceinline__ void mma_fp16(float* c, const uint32_t* a, const uint32_t* b) {
    asm volatile(
        "mma.sync.aligned.m16n8k16.row.col.f32.f16.f16.f32 "
        "{%0,%1,%2,%3}, {%4,%5,%6,%7}, {%8,%9}, {%0,%1,%2,%3};"
        : "+f"(c[0]), "+f"(c[1]), "+f"(c[2]), "+f"(c[3])
        : "r"(a[0]), "r"(a[1]), "r"(a[2]), "r"(a[3]), "r"(b[0]), "r"(b[1]));
}
__device__ __forceinline__ void mbar_init(uint32_t addr, uint32_t cnt) {
    asm volatile("mbarrier.init.shared.b64 [%0], %1;" :: "r"(addr), "r"(cnt) : "memory");
}
__device__ __forceinline__ void mbar_expect_tx(uint32_t addr, uint32_t bytes) {
    asm volatile("mbarrier.arrive.expect_tx.shared.b64 _, [%0], %1;"
                 :: "r"(addr), "r"(bytes) : "memory");
}
__device__ __forceinline__ void mbar_wait(uint32_t addr, uint32_t parity) {
    asm volatile(
        "{\n\t.reg .pred P;\n"
        "W%=:\n\t"
        "mbarrier.try_wait.parity.acquire.cta.shared::cta.b64 P, [%0], %1, 0x989680;\n\t"
        "@!P bra W%=;\n\t"
        "}"
        :: "r"(addr), "r"(parity) : "memory");
}
__device__ __forceinline__ void bulk_cp(uint32_t sdst, const void* gsrc,
                                        uint32_t bytes, uint32_t mbar) {
    asm volatile(
        "cp.async.bulk.shared::cta.global.mbarrier::complete_tx::bytes [%0], [%1], %2, [%3];"
        :: "r"(sdst), "l"(gsrc), "r"(bytes), "r"(mbar) : "memory");
}
__device__ __forceinline__ uint2 cvt_f16x4(float4 v) {
    __half2 p01 = __floats2half2_rn(v.x, v.y);
    __half2 p23 = __floats2half2_rn(v.z, v.w);
    return make_uint2(*(uint32_t*)&p01, *(uint32_t*)&p23);
}
__device__ __forceinline__ float h2sum(uint32_t r) {
    float2 f = __half22float2(*(__half2*)&r);
    return f.x + f.y;
}

// =============================================================================
// fp32 [rows][1024] -> blocked-swizzled fp16; up to 4 tensors per launch (z-dim)
// =============================================================================
__global__ __launch_bounds__(256)
void cvt_swz_multi(const float* __restrict__ s0, const float* __restrict__ s1,
                   const float* __restrict__ s2, const float* __restrict__ s3,
                   __half* __restrict__ dst, size_t dstride, int n4) {
    const float* src = (blockIdx.z == 0) ? s0 : (blockIdx.z == 1) ? s1
                     : (blockIdx.z == 2) ? s2 : s3;
    __half* d = dst + (size_t)blockIdx.z * dstride;
    for (int i = blockIdx.x * 256 + threadIdx.x; i < n4; i += gridDim.x * 256) {
        const int grow = i >> 8;
        const int gcol = (i & 255) * 4;
        const int blk  = grow >> 7;
        const int r    = grow & 127;
        const int c    = gcol >> 6;
        const uint32_t colb = (uint32_t)((gcol & 63) * 2);
        const size_t off = ((size_t)(blk * NCH + c) << 14)
                         + (uint32_t)(r * 128) + (colb ^ ((uint32_t)(r & 7) << 4));
        *(uint2*)((char*)d + off) = cvt_f16x4(((const float4*)src)[i]);
    }
}

// =============================================================================
// Merged QKV projection GEMM (NT): grid.z selects {input, weight, bias, out, phi}.
// fp16 blocked-swizzled in and out. 3 stages -> 2 CTAs/SM.
// =============================================================================
__global__ __launch_bounds__(GTHREADS, 2)
void gemm_qkv(const __half* __restrict__ Xb, const __half* __restrict__ Wb,
              const float* __restrict__ bq, const float* __restrict__ bk,
              const float* __restrict__ bv,
              __half* __restrict__ Qb, __half* __restrict__ Kb,
              __half* __restrict__ Vb) {
    extern __shared__ char sm[];
    const uint32_t sbase = smem_u32(sm);
    const int tid = threadIdx.x;
    const int lane = tid & 31;
    const int wid = tid >> 5;
    const int wm = wid & 3;
    const int wn = wid >> 2;
    const int bm = blockIdx.y;
    const int bn = blockIdx.x;
    const int zi = blockIdx.z;

    const __half* Ab = Xb + (size_t)zi * ASTRIDE;
    const __half* Bb = Wb + (size_t)zi * (DMODEL * DMODEL);
    const float* bias = (zi == 0) ? bq : (zi == 1) ? bk : bv;
    __half* Yh = (zi == 0) ? Qb : (zi == 1) ? Kb : Vb;
    const bool phi = (zi != 2);

    if (tid == 0) {
        #pragma unroll
        for (int s = 0; s < STAGES; s++) mbar_init(sbase + s * 8, 1);
    }
    __syncthreads();

    const char* gAb = (const char*)Ab + ((size_t)(bm * NCH) << 14);
    const char* gBb = (const char*)Bb + ((size_t)(bn * NCH) << 14);

    int row_a[2];
    row_a[0] = wm * 32 + (lane & 15);
    row_a[1] = row_a[0] + 16;
    const uint32_t a_colb = (uint32_t)((lane >> 4) << 4);
    uint32_t a_base[2], a_mask[2];
    #pragma unroll
    for (int mt = 0; mt < 2; mt++) {
        a_base[mt] = (uint32_t)(row_a[mt] * 128);
        a_mask[mt] = (uint32_t)((row_a[mt] & 7) << 4);
    }
    int nrow[4];
    #pragma unroll
    for (int ntp = 0; ntp < 4; ntp++)
        nrow[ntp] = wn * 64 + ntp * 16 + (lane & 7) + ((lane >> 4) << 3);
    const uint32_t b_colb = (lane & 8) ? 16u : 0u;
    uint32_t b_base[4], b_mask[4];
    #pragma unroll
    for (int ntp = 0; ntp < 4; ntp++) {
        b_base[ntp] = (uint32_t)(nrow[ntp] * 128);
        b_mask[ntp] = (uint32_t)((nrow[ntp] & 7) << 4);
    }

    float acc[2][8][4];
    #pragma unroll
    for (int mt = 0; mt < 2; mt++)
        #pragma unroll
        for (int nt = 0; nt < 8; nt++)
            #pragma unroll
            for (int i = 0; i < 4; i++) acc[mt][nt][i] = 0.f;

    auto issue = [&](int c) {
        const int s = c % STAGES;
        const uint32_t mb = sbase + s * 8;
        const uint32_t st = sbase + 1024 + s * STAGE;
        mbar_expect_tx(mb, 2 * BLK_BYTES);
        bulk_cp(st + A_PL, gAb + ((size_t)c << 14), BLK_BYTES, mb);
        bulk_cp(st + B_PL, gBb + ((size_t)c << 14), BLK_BYTES, mb);
    };

    if (tid == 0) { issue(0); issue(1); }

    for (int c = 0; c < NCH; c++) {
        mbar_wait(sbase + (c % STAGES) * 8, (c / STAGES) & 1);
        if (tid == 0 && c + 2 < NCH) issue(c + 2);

        const uint32_t stg = sbase + 1024 + (uint32_t)((c % STAGES) * STAGE);
        #pragma unroll
        for (int ks = 0; ks < 4; ks++) {
            const uint32_t kb = (uint32_t)(ks * 32);
            uint32_t Ar[2][4];
            #pragma unroll
            for (int mt = 0; mt < 2; mt++) {
                uint32_t off = a_base[mt] + ((kb + a_colb) ^ a_mask[mt]);
                ldsm4(Ar[mt][0], Ar[mt][1], Ar[mt][2], Ar[mt][3], stg + A_PL + off);
            }
            uint32_t Br[8][2];
            #pragma unroll
            for (int ntp = 0; ntp < 4; ntp++) {
                uint32_t off = b_base[ntp] + ((kb + b_colb) ^ b_mask[ntp]);
                ldsm4(Br[2 * ntp][0], Br[2 * ntp][1], Br[2 * ntp + 1][0], Br[2 * ntp + 1][1],
                      stg + B_PL + off);
            }
            #pragma unroll
            for (int mt = 0; mt < 2; mt++)
                #pragma unroll
                for (int nt = 0; nt < 8; nt++)
                    mma_fp16(acc[mt][nt], Ar[mt], Br[nt]);
        }
        __syncthreads();
    }

    // ---- epilogue: bias (+ phi), store fp16 blocked ----
    const int lr = lane >> 2;
    const int lc = lane & 3;
    #pragma unroll
    for (int mt = 0; mt < 2; mt++) {
        const int r0l = wm * 32 + mt * 16 + lr;
        #pragma unroll
        for (int nt = 0; nt < 8; nt++) {
            const int gc = bn * BN + wn * 64 + nt * 8 + lc * 2;
            const float b0 = __ldg(&bias[gc]);
            const float b1 = __ldg(&bias[gc + 1]);
            float o00 = acc[mt][nt][0] + b0;
            float o01 = acc[mt][nt][1] + b1;
            float o10 = acc[mt][nt][2] + b0;
            float o11 = acc[mt][nt][3] + b1;
            if (phi) {
                o00 = (o00 > 0.f) ? (o00 + 1.f) : __expf(o00);
                o01 = (o01 > 0.f) ? (o01 + 1.f) : __expf(o01);
                o10 = (o10 > 0.f) ? (o10 + 1.f) : __expf(o10);
                o11 = (o11 > 0.f) ? (o11 + 1.f) : __expf(o11);
            }
            const int cch = gc >> 6;
            const uint32_t colb = (uint32_t)((gc & 63) * 2);
            const size_t blkb = ((size_t)(bm * NCH + cch)) << 14;
            __half2 p0 = __floats2half2_rn(o00, o01);
            __half2 p1 = __floats2half2_rn(o10, o11);
            const uint32_t ra = (uint32_t)r0l, rb = (uint32_t)(r0l + 8);
            *(uint32_t*)((char*)Yh + blkb + ra * 128 + (colb ^ ((ra & 7) << 4))) =
                *(uint32_t*)&p0;
            *(uint32_t*)((char*)Yh + blkb + rb * 128 + (colb ^ ((rb & 7) << 4))) =
                *(uint32_t*)&p1;
        }
    }
}

// =============================================================================
// Output projection GEMM (fp32 row-major out), same engine.
// =============================================================================
__global__ __launch_bounds__(GTHREADS, 2)
void gemm_out(const __half* __restrict__ Ab, const __half* __restrict__ Bb,
              const float* __restrict__ bias, float* __restrict__ Y) {
    extern __shared__ char sm[];
    const uint32_t sbase = smem_u32(sm);
    const int tid = threadIdx.x;
    const int lane = tid & 31;
    const int wid = tid >> 5;
    const int wm = wid & 3;
    const int wn = wid >> 2;
    const int bm = blockIdx.y;
    const int bn = blockIdx.x;

    if (tid == 0) {
        #pragma unroll
        for (int s = 0; s < STAGES; s++) mbar_init(sbase + s * 8, 1);
    }
    __syncthreads();

    const char* gAb = (const char*)Ab + ((size_t)(bm * NCH) << 14);
    const char* gBb = (const char*)Bb + ((size_t)(bn * NCH) << 14);

    int row_a[2];
    row_a[0] = wm * 32 + (lane & 15);
    row_a[1] = row_a[0] + 16;
    const uint32_t a_colb = (uint32_t)((lane >> 4) << 4);
    uint32_t a_base[2], a_mask[2];
    #pragma unroll
    for (int mt = 0; mt < 2; mt++) {
        a_base[mt] = (uint32_t)(row_a[mt] * 128);
        a_mask[mt] = (uint32_t)((row_a[mt] & 7) << 4);
    }
    int nrow[4];
    #pragma unroll
    for (int ntp = 0; ntp < 4; ntp++)
        nrow[ntp] = wn * 64 + ntp * 16 + (lane & 7) + ((lane >> 4) << 3);
    const uint32_t b_colb = (lane & 8) ? 16u : 0u;
    uint32_t b_base[4], b_mask[4];
    #pragma unroll
    for (int ntp = 0; ntp < 4; ntp++) {
        b_base[ntp] = (uint32_t)(nrow[ntp] * 128);
        b_mask[ntp] = (uint32_t)((nrow[ntp] & 7) << 4);
    }

    float acc[2][8][4];
    #pragma unroll
    for (int mt = 0; mt < 2; mt++)
        #pragma unroll
        for (int nt = 0; nt < 8; nt++)
            #pragma unroll
            for (int i = 0; i < 4; i++) acc[mt][nt][i] = 0.f;

    auto issue = [&](int c) {
        const int s = c % STAGES;
        const uint32_t mb = sbase + s * 8;
        const uint32_t st = sbase + 1024 + s * STAGE;
        mbar_expect_tx(mb, 2 * BLK_BYTES);
        bulk_cp(st + A_PL, gAb + ((size_t)c << 14), BLK_BYTES, mb);
        bulk_cp(st + B_PL, gBb + ((size_t)c << 14), BLK_BYTES, mb);
    };

    if (tid == 0) { issue(0); issue(1); }

    for (int c = 0; c < NCH; c++) {
        mbar_wait(sbase + (c % STAGES) * 8, (c / STAGES) & 1);
        if (tid == 0 && c + 2 < NCH) issue(c + 2);

        const uint32_t stg = sbase + 1024 + (uint32_t)((c % STAGES) * STAGE);
        #pragma unroll
        for (int ks = 0; ks < 4; ks++) {
            const uint32_t kb = (uint32_t)(ks * 32);
            uint32_t Ar[2][4];
            #pragma unroll
            for (int mt = 0; mt < 2; mt++) {
                uint32_t off = a_base[mt] + ((kb + a_colb) ^ a_mask[mt]);
                ldsm4(Ar[mt][0], Ar[mt][1], Ar[mt][2], Ar[mt][3], stg + A_PL + off);
            }
            uint32_t Br[8][2];
            #pragma unroll
            for (int ntp = 0; ntp < 4; ntp++) {
                uint32_t off = b_base[ntp] + ((kb + b_colb) ^ b_mask[ntp]);
                ldsm4(Br[2 * ntp][0], Br[2 * ntp][1], Br[2 * ntp + 1][0], Br[2 * ntp + 1][1],
                      stg + B_PL + off);
            }
            #pragma unroll
            for (int mt = 0; mt < 2; mt++)
                #pragma unroll
                for (int nt = 0; nt < 8; nt++)
                    mma_fp16(acc[mt][nt], Ar[mt], Br[nt]);
        }
        __syncthreads();
    }

    const int lr = lane >> 2;
    const int lc = lane & 3;
    #pragma unroll
    for (int mt = 0; mt < 2; mt++) {
        const int gr0 = bm * BM + wm * 32 + mt * 16 + lr;
        #pragma unroll
        for (int nt = 0; nt < 8; nt++) {
            const int gc = bn * BN + wn * 64 + nt * 8 + lc * 2;
            const float b0 = __ldg(&bias[gc]);
            const float b1 = __ldg(&bias[gc + 1]);
            *(float2*)(Y + (size_t)gr0 * DMODEL + gc) =
                make_float2(acc[mt][nt][0] + b0, acc[mt][nt][1] + b1);
            *(float2*)(Y + (size_t)(gr0 + 8) * DMODEL + gc) =
                make_float2(acc[mt][nt][2] + b0, acc[mt][nt][3] + b1);
        }
    }
}

// =============================================================================
// kv partial via HMMA:  C[d][e] = sum_m K[m][d]*V[m][e]  over 512-m split,
// z[d] = sum_m K[m][d] from A fragments.
// =============================================================================
__global__ __launch_bounds__(128, 1)
void kv_hmma(const __half* __restrict__ Kb, const __half* __restrict__ Vb,
             float* __restrict__ kvp, float* __restrict__ zp) {
    extern __shared__ char sm[];
    const uint32_t sbase = smem_u32(sm);
    const int tid = threadIdx.x;
    const int lane = tid & 31;
    const int wid = tid >> 5;

    const int s  = blockIdx.x % KSPLIT;
    const int bh = blockIdx.x / KSPLIT;
    const int b = bh / HEADS, h = bh % HEADS;
    const int blkbase = b * (SEQ / 128) + s * 4;

    if (tid == 0) { mbar_init(sbase, 1); mbar_init(sbase + 8, 1); }
    __syncthreads();

    auto issue = [&](int j) {
        const int st = j & 1;
        const uint32_t mb = sbase + st * 8;
        const uint32_t dst = sbase + 1024 + st * KV_STAGE;
        mbar_expect_tx(mb, 2 * BLK_BYTES);
        const size_t off = ((size_t)((blkbase + j) * NCH + h)) << 14;
        bulk_cp(dst,         (const char*)Kb + off, BLK_BYTES, mb);
        bulk_cp(dst + 16384, (const char*)Vb + off, BLK_BYTES, mb);
    };
    if (tid == 0) { issue(0); issue(1); }

    const int d0 = wid * 16;
    const int a_rloc = (lane & 7) + ((lane >> 4) << 3);
    const uint32_t a_cb = (uint32_t)(d0 * 2) + (uint32_t)(((lane >> 3) & 1) << 4);
    const uint32_t a_off = (uint32_t)(a_rloc * 128) + (a_cb ^ ((uint32_t)(a_rloc & 7) << 4));
    const int b_rloc = (lane & 7) + (((lane >> 3) & 1) << 3);
    const uint32_t b_cb0 = (uint32_t)((lane >> 4) << 4);
    uint32_t b_off[4];
    #pragma unroll
    for (int e4 = 0; e4 < 4; e4++)
        b_off[e4] = (uint32_t)(b_rloc * 128)
                  + (((uint32_t)(e4 * 32) + b_cb0) ^ ((uint32_t)(b_rloc & 7) << 4));

    float acc[8][4];
    #pragma unroll
    for (int nt = 0; nt < 8; nt++)
        #pragma unroll
        for (int i = 0; i < 4; i++) acc[nt][i] = 0.f;
    float zs0 = 0.f, zs1 = 0.f;

    for (int j = 0; j < 4; j++) {
        mbar_wait(sbase + (j & 1) * 8, (j >> 1) & 1);
        const uint32_t bK = sbase + 1024 + (j & 1) * KV_STAGE;
        const uint32_t bV = bK + 16384;
        #pragma unroll
        for (int ks = 0; ks < 8; ks++) {
            uint32_t Ar[4];
            ldsm4t(Ar[0], Ar[1], Ar[2], Ar[3], bK + (uint32_t)(ks * 2048) + a_off);
            uint32_t Br[8][2];
            #pragma unroll
            for (int e4 = 0; e4 < 4; e4++) {
                uint32_t r0, r1, r2, r3;
                ldsm4t(r0, r1, r2, r3, bV + (uint32_t)(ks * 2048) + b_off[e4]);
                Br[2 * e4][0] = r0; Br[2 * e4][1] = r1;
                Br[2 * e4 + 1][0] = r2; Br[2 * e4 + 1][1] = r3;
            }
            #pragma unroll
            for (int nt = 0; nt < 8; nt++) mma_fp16(acc[nt], Ar, Br[nt]);
            zs0 += h2sum(Ar[0]) + h2sum(Ar[2]);
            zs1 += h2sum(Ar[1]) + h2sum(Ar[3]);
        }
        __syncthreads();
        if (tid == 0 && j + 2 < 4) issue(j + 2);
    }

    zs0 += __shfl_xor_sync(0xFFFFFFFF, zs0, 1);
    zs0 += __shfl_xor_sync(0xFFFFFFFF, zs0, 2);
    zs1 += __shfl_xor_sync(0xFFFFFFFF, zs1, 1);
    zs1 += __shfl_xor_sync(0xFFFFFFFF, zs1, 2);

    const int g = lane >> 2;
    const int ec = 2 * (lane & 3);
    float* kout = kvp + (size_t)blockIdx.x * (DH * DH);
    #pragma unroll
    for (int nt = 0; nt < 8; nt++) {
        *(float2*)&kout[(d0 + g) * DH + nt * 8 + ec]     = make_float2(acc[nt][0], acc[nt][1]);
        *(float2*)&kout[(d0 + g + 8) * DH + nt * 8 + ec] = make_float2(acc[nt][2], acc[nt][3]);
    }
    if ((lane & 3) == 0) {
        zp[(size_t)blockIdx.x * DH + d0 + g]     = zs0;
        zp[(size_t)blockIdx.x * DH + d0 + g + 8] = zs1;
    }
}

// =============================================================================
// reduce partials -> kvT fp16 swizzled [e][d] + z fp32
// =============================================================================
__global__ __launch_bounds__(256)
void kv_reduce(const float* __restrict__ kvp, const float* __restrict__ zp,
               __half* __restrict__ kvT, float* __restrict__ zo) {
    const int bh = blockIdx.x;
    const int tid = threadIdx.x;
    for (int i = tid; i < DH * DH; i += 256) {
        float sum = 0.f;
        #pragma unroll
        for (int s = 0; s < KSPLIT; s++)
            sum += kvp[((size_t)bh * KSPLIT + s) * (DH * DH) + i];
        const int d = i >> 6, e = i & 63;
        const size_t off = (size_t)bh * 8192 + (uint32_t)(e * 128)
                         + (((uint32_t)(d * 2)) ^ ((uint32_t)(e & 7) << 4));
        *(__half*)((char*)kvT + off) = __float2half_rn(sum);
    }
    if (tid < DH) {
        float sum = 0.f;
        #pragma unroll
        for (int s = 0; s < KSPLIT; s++)
            sum += zp[((size_t)bh * KSPLIT + s) * DH + tid];
        zo[(size_t)bh * DH + tid] = sum;
    }
}

// =============================================================================
// attn via HMMA: out[n][e] = (sum_d Q[n][d] kvT[e][d]) / (q.z + eps), fp16 in/out.
// =============================================================================
__global__ __launch_bounds__(256, 1)
void attn_hmma(const __half* __restrict__ Qb, const __half* __restrict__ kvT,
               const float* __restrict__ z, __half* __restrict__ Sb) {
    extern __shared__ char sm[];
    __shared__ float zsm[2][64];
    const uint32_t sbase = smem_u32(sm);
    const int tid = threadIdx.x;
    const int lane = tid & 31;
    const int wid = tid >> 5;
    const int blk = blockIdx.x;
    const int b = blk >> 5;

    if (tid == 0) { mbar_init(sbase, 1); mbar_init(sbase + 8, 1); }

    auto issue = [&](int h) {
        const int st = h & 1;
        const uint32_t mb = sbase + st * 8;
        const uint32_t dst = sbase + 1024 + st * AT_STAGE;
        mbar_expect_tx(mb, 16384 + 8192);
        bulk_cp(dst, (const char*)Qb + (((size_t)(blk * NCH + h)) << 14), 16384, mb);
        bulk_cp(dst + 16384, (const char*)kvT + (((size_t)(b * HEADS + h)) << 13), 8192, mb);
    };
    __syncthreads();
    if (tid == 0) { issue(0); issue(1); }
    if (tid < 64) {
        zsm[0][tid] = z[(size_t)(b * HEADS + 0) * DH + tid];
        zsm[1][tid] = z[(size_t)(b * HEADS + 1) * DH + tid];
    }
    __syncthreads();

    const int row_a = wid * 16 + (lane & 15);
    const uint32_t a_base = (uint32_t)(row_a * 128);
    const uint32_t a_mask = (uint32_t)((row_a & 7) << 4);
    const uint32_t a_colb = (uint32_t)((lane >> 4) << 4);
    int nrow[4];
    #pragma unroll
    for (int ntp = 0; ntp < 4; ntp++)
        nrow[ntp] = ntp * 16 + (lane & 7) + ((lane >> 4) << 3);
    const uint32_t b_colb = (lane & 8) ? 16u : 0u;
    uint32_t b_base[4], b_mask[4];
    #pragma unroll
    for (int ntp = 0; ntp < 4; ntp++) {
        b_base[ntp] = (uint32_t)(nrow[ntp] * 128);
        b_mask[ntp] = (uint32_t)((nrow[ntp] & 7) << 4);
    }

    const int g = lane >> 2;
    const int ec = 2 * (lane & 3);

    for (int h = 0; h < HEADS; h++) {
        const int st = h & 1;
        mbar_wait(sbase + st * 8, (h >> 1) & 1);
        const uint32_t bQ = sbase + 1024 + st * AT_STAGE;
        const uint32_t bKV = bQ + 16384;

        float acc[8][4];
        #pragma unroll
        for (int nt = 0; nt < 8; nt++)
            #pragma unroll
            for (int i = 0; i < 4; i++) acc[nt][i] = 0.f;
        float den0 = 0.f, den1 = 0.f;

        #pragma unroll
        for (int ks = 0; ks < 4; ks++) {
            const uint32_t kb = (uint32_t)(ks * 32);
            uint32_t Ar[4];
            ldsm4(Ar[0], Ar[1], Ar[2], Ar[3], bQ + a_base + ((kb + a_colb) ^ a_mask));
            uint32_t Br[8][2];
            #pragma unroll
            for (int ntp = 0; ntp < 4; ntp++) {
                uint32_t off = b_base[ntp] + ((kb + b_colb) ^ b_mask[ntp]);
                ldsm4(Br[2 * ntp][0], Br[2 * ntp][1], Br[2 * ntp + 1][0], Br[2 * ntp + 1][1],
                      bKV + off);
            }
            #pragma unroll
            for (int nt = 0; nt < 8; nt++) mma_fp16(acc[nt], Ar, Br[nt]);

            const int dbase = ks * 16 + ec;
            const float z0 = zsm[st][dbase],     z1 = zsm[st][dbase + 1];
            const float z8 = zsm[st][dbase + 8], z9 = zsm[st][dbase + 9];
            float2 a0 = __half22float2(*(__half2*)&Ar[0]);
            float2 a1 = __half22float2(*(__half2*)&Ar[1]);
            float2 a2 = __half22float2(*(__half2*)&Ar[2]);
            float2 a3 = __half22float2(*(__half2*)&Ar[3]);
            den0 += a0.x * z0 + a0.y * z1 + a2.x * z8 + a2.y * z9;
            den1 += a1.x * z0 + a1.y * z1 + a3.x * z8 + a3.y * z9;
        }
        den0 += __shfl_xor_sync(0xFFFFFFFF, den0, 1);
        den0 += __shfl_xor_sync(0xFFFFFFFF, den0, 2);
        den1 += __shfl_xor_sync(0xFFFFFFFF, den1, 1);
        den1 += __shfl_xor_sync(0xFFFFFFFF, den1, 2);
        const float rinv0 = 1.0f / (den0 + EPSV);
        const float rinv1 = 1.0f / (den1 + EPSV);

        const size_t blkb = ((size_t)(blk * NCH + h)) << 14;
        const uint32_t ra = (uint32_t)(wid * 16 + g);
        const uint32_t rb = ra + 8;
        #pragma unroll
        for (int nt = 0; nt < 8; nt++) {
            const uint32_t colb = (uint32_t)((nt * 8 + ec) * 2);
            __half2 p0 = __floats2half2_rn(acc[nt][0] * rinv0, acc[nt][1] * rinv0);
            __half2 p1 = __floats2half2_rn(acc[nt][2] * rinv1, acc[nt][3] * rinv1);
            *(uint32_t*)((char*)Sb + blkb + ra * 128 + (colb ^ ((ra & 7) << 4))) =
                *(uint32_t*)&p0;
            *(uint32_t*)((char*)Sb + blkb + rb * 128 + (colb ^ ((rb & 7) << 4))) =
                *(uint32_t*)&p1;
        }
        __syncthreads();
        if (tid == 0 && h + 2 < HEADS) issue(h + 2);
        if (tid < 64 && h + 2 < HEADS)
            zsm[st][tid] = z[(size_t)(b * HEADS + h + 2) * DH + tid];
    }
}

// =============================================================================
extern "C" void kernel_launch(void* const* d_in, const int* in_sizes, int n_in,
                              void* d_out, int out_size) {
    const float* queries = (const float*)d_in[0];
    const float* keys    = (const float*)d_in[1];
    const float* values  = (const float*)d_in[2];
    const float* wq = (const float*)d_in[3];
    const float* bq = (const float*)d_in[4];
    const float* wk = (const float*)d_in[5];
    const float* bk = (const float*)d_in[6];
    const float* wv = (const float*)d_in[7];
    const float* bv = (const float*)d_in[8];
    const float* wo = (const float*)d_in[9];
    const float* bo = (const float*)d_in[10];
    float* out = (float*)d_out;

    __half *Xbp, *Abp, *Wbp, *Qbp, *Kbp, *Vbp, *kvTp;
    float *kvp, *zp, *zb;
    cudaGetSymbolAddress((void**)&Xbp, g_Xb);
    cudaGetSymbolAddress((void**)&Abp, g_Ab);
    cudaGetSymbolAddress((void**)&Wbp, g_Wb);
    cudaGetSymbolAddress((void**)&Qbp, g_Qb);
    cudaGetSymbolAddress((void**)&Kbp, g_Kb);
    cudaGetSymbolAddress((void**)&Vbp, g_Vb);
    cudaGetSymbolAddress((void**)&kvTp, g_kvT);
    cudaGetSymbolAddress((void**)&kvp, g_kvp);
    cudaGetSymbolAddress((void**)&zp,  g_zp);
    cudaGetSymbolAddress((void**)&zb,  g_z);

    cudaFuncSetAttribute(gemm_qkv, cudaFuncAttributeMaxDynamicSharedMemorySize, SMEM_BYTES);
    cudaFuncSetAttribute(gemm_out, cudaFuncAttributeMaxDynamicSharedMemorySize, SMEM_BYTES);
    cudaFuncSetAttribute(kv_hmma,   cudaFuncAttributeMaxDynamicSharedMemorySize, KV_SMEM);
    cudaFuncSetAttribute(attn_hmma, cudaFuncAttributeMaxDynamicSharedMemorySize, AT_SMEM);

    const int WSZ = DMODEL * DMODEL;
    const int XN4 = ROWS * DMODEL / 4;
    const int WN4 = WSZ / 4;

    dim3 gb(GTHREADS);

    // weights -> blocked fp16, one launch (z = 4 tensors)
    cvt_swz_multi<<<dim3(512, 1, 4), 256>>>(wq, wk, wv, wo, Wbp, (size_t)WSZ, WN4);
    // activations -> blocked fp16, one launch (z = 3 tensors)
    cvt_swz_multi<<<dim3(2048, 1, 3), 256>>>(queries, keys, values, nullptr,
                                             Xbp, ASTRIDE, XN4);

    // merged QKV projections (3072 CTAs, one wave-packed launch)
    gemm_qkv<<<dim3(DMODEL / BN, ROWS / BM, 3), gb, SMEM_BYTES>>>(
        Xbp, Wbp, bq, bk, bv, Qbp, Kbp, Vbp);

    kv_hmma  <<<BATCH * HEADS * KSPLIT, 128, KV_SMEM>>>(Kbp, Vbp, kvp, zp);
    kv_reduce<<<BATCH * HEADS, 256>>>(kvp, zp, kvTp, zb);
    attn_hmma<<<ROWS / 128, 256, AT_SMEM>>>(Qbp, kvTp, zb, Abp);   // S -> blocked

    // output projection (fp32 out)
    gemm_out<<<dim3(DMODEL / BN, ROWS / BM), gb, SMEM_BYTES>>>(
        Abp, Wbp + 3 * WSZ, bo, out);
}

// round 11
// speedup vs baseline: 10.2168x; 1.0077x over previous
#include <cuda_runtime.h>
#include <cuda_fp16.h>
#include <cstdint>

// Problem constants (fixed by reference)
#define DMODEL 1024
#define HEADS  16
#define DH     64
#define BATCH  4
#define SEQ    4096
#define ROWS   (BATCH * SEQ)   // 16384
#define KSPLIT 16
#define EPSV   1e-6f

// GEMM tiling (HMMA mma.sync; tcgen05 unavailable on compute_103 virtual arch)
#define BM 128
#define BN 128
#define NCH (DMODEL / 64)       // 16 chunks of 64 fp16 per 1024-row
#define GTHREADS 256
#define STAGES 3                // 99KB smem -> 2 CTAs/SM

// Blocked-swizzled fp16 layout: 16KB block per (row-tile of 128, 64-col chunk).
#define BLK_BYTES 16384

#define A_PL 0
#define B_PL 16384
#define STAGE 32768
#define SMEM_BYTES (1024 + STAGES * STAGE)   // 99328

#define KV_STAGE 32768                        // K 16KB + V 16KB
#define KV_SMEM  (1024 + 2 * KV_STAGE)        // 66560
#define AT_STAGE 24576                        // Q 16KB + kvT 8KB
#define AT_SMEM  (1024 + 2 * AT_STAGE)        // 50176

#define ASTRIDE ((size_t)ROWS * DMODEL)

// ---------------- scratch (device globals; no allocation allowed) ------------
__device__ __half g_Xb[3 * ROWS * DMODEL];          // blocked q/k/v inputs
__device__ __half g_Ab[ROWS * DMODEL];              // S (blocked)
__device__ __half g_Wb[4 * DMODEL * DMODEL];        // blocked wq,wk,wv,wo
__device__ __half g_Qb[ROWS * DMODEL];              // Q fp16 blocked
__device__ __half g_Kb[ROWS * DMODEL];              // K fp16 blocked
__device__ __half g_Vb[ROWS * DMODEL];              // V fp16 blocked
__device__ float g_kvp[BATCH * HEADS * KSPLIT * DH * DH];
__device__ float g_zp [BATCH * HEADS * KSPLIT * DH];
__device__ __half g_kvT[BATCH * HEADS * DH * DH];   // kv^T fp16 swizzled [e][d]
__device__ float g_z  [BATCH * HEADS * DH];

// =============================== helpers ====================================
__device__ __forceinline__ uint32_t smem_u32(const void* p) {
    uint32_t a;
    asm("{ .reg .u64 t; cvta.to.shared.u64 t, %1; cvt.u32.u64 %0, t; }"
        : "=r"(a) : "l"(p));
    return a;
}
__device__ __forceinline__ void ldsm4(uint32_t& r0, uint32_t& r1, uint32_t& r2,
                                      uint32_t& r3, uint32_t addr) {
    asm volatile("ldmatrix.sync.aligned.m8n8.x4.shared.b16 {%0,%1,%2,%3}, [%4];"
                 : "=r"(r0), "=r"(r1), "=r"(r2), "=r"(r3) : "r"(addr));
}
__device__ __forceinline__ void ldsm4t(uint32_t& r0, uint32_t& r1, uint32_t& r2,
                                       uint32_t& r3, uint32_t addr) {
    asm volatile("ldmatrix.sync.aligned.m8n8.x4.trans.shared.b16 {%0,%1,%2,%3}, [%4];"
                 : "=r"(r0), "=r"(r1), "=r"(r2), "=r"(r3) : "r"(addr));
}
__device__ __forceinline__ void mma_fp16(float* c, const uint32_t* a, const uint32_t* b) {
    asm volatile(
        "mma.sync.aligned.m16n8k16.row.col.f32.f16.f16.f32 "
        "{%0,%1,%2,%3}, {%4,%5,%6,%7}, {%8,%9}, {%0,%1,%2,%3};"
        : "+f"(c[0]), "+f"(c[1]), "+f"(c[2]), "+f"(c[3])
        : "r"(a[0]), "r"(a[1]), "r"(a[2]), "r"(a[3]), "r"(b[0]), "r"(b[1]));
}
__device__ __forceinline__ void mbar_init(uint32_t addr, uint32_t cnt) {
    asm volatile("mbarrier.init.shared.b64 [%0], %1;" :: "r"(addr), "r"(cnt) : "memory");
}
__device__ __forceinline__ void mbar_expect_tx(uint32_t addr, uint32_t bytes) {
    asm volatile("mbarrier.arrive.expect_tx.shared.b64 _, [%0], %1;"
                 :: "r"(addr), "r"(bytes) : "memory");
}
__device__ __forceinline__ void mbar_wait(uint32_t addr, uint32_t parity) {
    asm volatile(
        "{\n\t.reg .pred P;\n"
        "W%=:\n\t"
        "mbarrier.try_wait.parity.acquire.cta.shared::cta.b64 P, [%0], %1, 0x989680;\n\t"
        "@!P bra W%=;\n\t"
        "}"
        :: "r"(addr), "r"(parity) : "memory");
}
__device__ __forceinline__ void bulk_cp(uint32_t sdst, const void* gsrc,
                                        uint32_t bytes, uint32_t mbar) {
    asm volatile(
        "cp.async.bulk.shared::cta.global.mbarrier::complete_tx::bytes [%0], [%1], %2, [%3];"
        :: "r"(sdst), "l"(gsrc), "r"(bytes), "r"(mbar) : "memory");
}
__device__ __forceinline__ uint2 cvt_f16x4(float4 v) {
    __half2 p01 = __floats2half2_rn(v.x, v.y);
    __half2 p23 = __floats2half2_rn(v.z, v.w);
    return make_uint2(*(uint32_t*)&p01, *(uint32_t*)&p23);
}
__device__ __forceinline__ float h2sum(uint32_t r) {
    float2 f = __half22float2(*(__half2*)&r);
    return f.x + f.y;
}

// =============================================================================
// fp32 [rows][1024] -> blocked-swizzled fp16; up to 4 tensors per launch (z).
// Each thread handles 8 floats -> ONE 16B store (16B = swizzle atom, aligned).
// =============================================================================
__global__ __launch_bounds__(256)
void cvt_swz_multi(const float* __restrict__ s0, const float* __restrict__ s1,
                   const float* __restrict__ s2, const float* __restrict__ s3,
                   __half* __restrict__ dst, size_t dstride, int n8) {
    const float* src = (blockIdx.z == 0) ? s0 : (blockIdx.z == 1) ? s1
                     : (blockIdx.z == 2) ? s2 : s3;
    __half* d = dst + (size_t)blockIdx.z * dstride;
    for (int i = blockIdx.x * 256 + threadIdx.x; i < n8; i += gridDim.x * 256) {
        const int grow = i >> 7;             // 128 groups of 8 per row
        const int gcol = (i & 127) * 8;
        const int blk  = grow >> 7;
        const int r    = grow & 127;
        const int c    = gcol >> 6;
        const uint32_t colb = (uint32_t)((gcol & 63) * 2);   // multiple of 16
        const size_t off = ((size_t)(blk * NCH + c) << 14)
                         + (uint32_t)(r * 128) + (colb ^ ((uint32_t)(r & 7) << 4));
        float4 va = ((const float4*)src)[2 * i];
        float4 vb = ((const float4*)src)[2 * i + 1];
        uint2 pa = cvt_f16x4(va);
        uint2 pb = cvt_f16x4(vb);
        uint4 pk = make_uint4(pa.x, pa.y, pb.x, pb.y);
        *(uint4*)((char*)d + off) = pk;
    }
}

// =============================================================================
// Merged QKV projection GEMM (NT): grid.z selects {input, weight, bias, out, phi}.
// =============================================================================
__global__ __launch_bounds__(GTHREADS, 2)
void gemm_qkv(const __half* __restrict__ Xb, const __half* __restrict__ Wb,
              const float* __restrict__ bq, const float* __restrict__ bk,
              const float* __restrict__ bv,
              __half* __restrict__ Qb, __half* __restrict__ Kb,
              __half* __restrict__ Vb) {
    extern __shared__ char sm[];
    const uint32_t sbase = smem_u32(sm);
    const int tid = threadIdx.x;
    const int lane = tid & 31;
    const int wid = tid >> 5;
    const int wm = wid & 3;
    const int wn = wid >> 2;
    const int bm = blockIdx.y;
    const int bn = blockIdx.x;
    const int zi = blockIdx.z;

    const __half* Ab = Xb + (size_t)zi * ASTRIDE;
    const __half* Bb = Wb + (size_t)zi * (DMODEL * DMODEL);
    const float* bias = (zi == 0) ? bq : (zi == 1) ? bk : bv;
    __half* Yh = (zi == 0) ? Qb : (zi == 1) ? Kb : Vb;
    const bool phi = (zi != 2);

    if (tid == 0) {
        #pragma unroll
        for (int s = 0; s < STAGES; s++) mbar_init(sbase + s * 8, 1);
    }
    __syncthreads();

    const char* gAb = (const char*)Ab + ((size_t)(bm * NCH) << 14);
    const char* gBb = (const char*)Bb + ((size_t)(bn * NCH) << 14);

    int row_a[2];
    row_a[0] = wm * 32 + (lane & 15);
    row_a[1] = row_a[0] + 16;
    const uint32_t a_colb = (uint32_t)((lane >> 4) << 4);
    uint32_t a_base[2], a_mask[2];
    #pragma unroll
    for (int mt = 0; mt < 2; mt++) {
        a_base[mt] = (uint32_t)(row_a[mt] * 128);
        a_mask[mt] = (uint32_t)((row_a[mt] & 7) << 4);
    }
    int nrow[4];
    #pragma unroll
    for (int ntp = 0; ntp < 4; ntp++)
        nrow[ntp] = wn * 64 + ntp * 16 + (lane & 7) + ((lane >> 4) << 3);
    const uint32_t b_colb = (lane & 8) ? 16u : 0u;
    uint32_t b_base[4], b_mask[4];
    #pragma unroll
    for (int ntp = 0; ntp < 4; ntp++) {
        b_base[ntp] = (uint32_t)(nrow[ntp] * 128);
        b_mask[ntp] = (uint32_t)((nrow[ntp] & 7) << 4);
    }

    float acc[2][8][4];
    #pragma unroll
    for (int mt = 0; mt < 2; mt++)
        #pragma unroll
        for (int nt = 0; nt < 8; nt++)
            #pragma unroll
            for (int i = 0; i < 4; i++) acc[mt][nt][i] = 0.f;

    auto issue = [&](int c) {
        const int s = c % STAGES;
        const uint32_t mb = sbase + s * 8;
        const uint32_t st = sbase + 1024 + s * STAGE;
        mbar_expect_tx(mb, 2 * BLK_BYTES);
        bulk_cp(st + A_PL, gAb + ((size_t)c << 14), BLK_BYTES, mb);
        bulk_cp(st + B_PL, gBb + ((size_t)c << 14), BLK_BYTES, mb);
    };

    if (tid == 0) { issue(0); issue(1); }

    for (int c = 0; c < NCH; c++) {
        mbar_wait(sbase + (c % STAGES) * 8, (c / STAGES) & 1);
        if (tid == 0 && c + 2 < NCH) issue(c + 2);

        const uint32_t stg = sbase + 1024 + (uint32_t)((c % STAGES) * STAGE);
        #pragma unroll
        for (int ks = 0; ks < 4; ks++) {
            const uint32_t kb = (uint32_t)(ks * 32);
            uint32_t Ar[2][4];
            #pragma unroll
            for (int mt = 0; mt < 2; mt++) {
                uint32_t off = a_base[mt] + ((kb + a_colb) ^ a_mask[mt]);
                ldsm4(Ar[mt][0], Ar[mt][1], Ar[mt][2], Ar[mt][3], stg + A_PL + off);
            }
            uint32_t Br[8][2];
            #pragma unroll
            for (int ntp = 0; ntp < 4; ntp++) {
                uint32_t off = b_base[ntp] + ((kb + b_colb) ^ b_mask[ntp]);
                ldsm4(Br[2 * ntp][0], Br[2 * ntp][1], Br[2 * ntp + 1][0], Br[2 * ntp + 1][1],
                      stg + B_PL + off);
            }
            #pragma unroll
            for (int mt = 0; mt < 2; mt++)
                #pragma unroll
                for (int nt = 0; nt < 8; nt++)
                    mma_fp16(acc[mt][nt], Ar[mt], Br[nt]);
        }
        __syncthreads();
    }

    // ---- epilogue: bias (+ phi), store fp16 blocked ----
    const int lr = lane >> 2;
    const int lc = lane & 3;
    #pragma unroll
    for (int mt = 0; mt < 2; mt++) {
        const int r0l = wm * 32 + mt * 16 + lr;
        #pragma unroll
        for (int nt = 0; nt < 8; nt++) {
            const int gc = bn * BN + wn * 64 + nt * 8 + lc * 2;
            const float b0 = __ldg(&bias[gc]);
            const float b1 = __ldg(&bias[gc + 1]);
            float o00 = acc[mt][nt][0] + b0;
            float o01 = acc[mt][nt][1] + b1;
            float o10 = acc[mt][nt][2] + b0;
            float o11 = acc[mt][nt][3] + b1;
            if (phi) {
                o00 = (o00 > 0.f) ? (o00 + 1.f) : __expf(o00);
                o01 = (o01 > 0.f) ? (o01 + 1.f) : __expf(o01);
                o10 = (o10 > 0.f) ? (o10 + 1.f) : __expf(o10);
                o11 = (o11 > 0.f) ? (o11 + 1.f) : __expf(o11);
            }
            const int cch = gc >> 6;
            const uint32_t colb = (uint32_t)((gc & 63) * 2);
            const size_t blkb = ((size_t)(bm * NCH + cch)) << 14;
            __half2 p0 = __floats2half2_rn(o00, o01);
            __half2 p1 = __floats2half2_rn(o10, o11);
            const uint32_t ra = (uint32_t)r0l, rb = (uint32_t)(r0l + 8);
            *(uint32_t*)((char*)Yh + blkb + ra * 128 + (colb ^ ((ra & 7) << 4))) =
                *(uint32_t*)&p0;
            *(uint32_t*)((char*)Yh + blkb + rb * 128 + (colb ^ ((rb & 7) << 4))) =
                *(uint32_t*)&p1;
        }
    }
}

// =============================================================================
// Output projection GEMM (fp32 row-major out), same engine.
// =============================================================================
__global__ __launch_bounds__(GTHREADS, 2)
void gemm_out(const __half* __restrict__ Ab, const __half* __restrict__ Bb,
              const float* __restrict__ bias, float* __restrict__ Y) {
    extern __shared__ char sm[];
    const uint32_t sbase = smem_u32(sm);
    const int tid = threadIdx.x;
    const int lane = tid & 31;
    const int wid = tid >> 5;
    const int wm = wid & 3;
    const int wn = wid >> 2;
    const int bm = blockIdx.y;
    const int bn = blockIdx.x;

    if (tid == 0) {
        #pragma unroll
        for (int s = 0; s < STAGES; s++) mbar_init(sbase + s * 8, 1);
    }
    __syncthreads();

    const char* gAb = (const char*)Ab + ((size_t)(bm * NCH) << 14);
    const char* gBb = (const char*)Bb + ((size_t)(bn * NCH) << 14);

    int row_a[2];
    row_a[0] = wm * 32 + (lane & 15);
    row_a[1] = row_a[0] + 16;
    const uint32_t a_colb = (uint32_t)((lane >> 4) << 4);
    uint32_t a_base[2], a_mask[2];
    #pragma unroll
    for (int mt = 0; mt < 2; mt++) {
        a_base[mt] = (uint32_t)(row_a[mt] * 128);
        a_mask[mt] = (uint32_t)((row_a[mt] & 7) << 4);
    }
    int nrow[4];
    #pragma unroll
    for (int ntp = 0; ntp < 4; ntp++)
        nrow[ntp] = wn * 64 + ntp * 16 + (lane & 7) + ((lane >> 4) << 3);
    const uint32_t b_colb = (lane & 8) ? 16u : 0u;
    uint32_t b_base[4], b_mask[4];
    #pragma unroll
    for (int ntp = 0; ntp < 4; ntp++) {
        b_base[ntp] = (uint32_t)(nrow[ntp] * 128);
        b_mask[ntp] = (uint32_t)((nrow[ntp] & 7) << 4);
    }

    float acc[2][8][4];
    #pragma unroll
    for (int mt = 0; mt < 2; mt++)
        #pragma unroll
        for (int nt = 0; nt < 8; nt++)
            #pragma unroll
            for (int i = 0; i < 4; i++) acc[mt][nt][i] = 0.f;

    auto issue = [&](int c) {
        const int s = c % STAGES;
        const uint32_t mb = sbase + s * 8;
        const uint32_t st = sbase + 1024 + s * STAGE;
        mbar_expect_tx(mb, 2 * BLK_BYTES);
        bulk_cp(st + A_PL, gAb + ((size_t)c << 14), BLK_BYTES, mb);
        bulk_cp(st + B_PL, gBb + ((size_t)c << 14), BLK_BYTES, mb);
    };

    if (tid == 0) { issue(0); issue(1); }

    for (int c = 0; c < NCH; c++) {
        mbar_wait(sbase + (c % STAGES) * 8, (c / STAGES) & 1);
        if (tid == 0 && c + 2 < NCH) issue(c + 2);

        const uint32_t stg = sbase + 1024 + (uint32_t)((c % STAGES) * STAGE);
        #pragma unroll
        for (int ks = 0; ks < 4; ks++) {
            const uint32_t kb = (uint32_t)(ks * 32);
            uint32_t Ar[2][4];
            #pragma unroll
            for (int mt = 0; mt < 2; mt++) {
                uint32_t off = a_base[mt] + ((kb + a_colb) ^ a_mask[mt]);
                ldsm4(Ar[mt][0], Ar[mt][1], Ar[mt][2], Ar[mt][3], stg + A_PL + off);
            }
            uint32_t Br[8][2];
            #pragma unroll
            for (int ntp = 0; ntp < 4; ntp++) {
                uint32_t off = b_base[ntp] + ((kb + b_colb) ^ b_mask[ntp]);
                ldsm4(Br[2 * ntp][0], Br[2 * ntp][1], Br[2 * ntp + 1][0], Br[2 * ntp + 1][1],
                      stg + B_PL + off);
            }
            #pragma unroll
            for (int mt = 0; mt < 2; mt++)
                #pragma unroll
                for (int nt = 0; nt < 8; nt++)
                    mma_fp16(acc[mt][nt], Ar[mt], Br[nt]);
        }
        __syncthreads();
    }

    const int lr = lane >> 2;
    const int lc = lane & 3;
    #pragma unroll
    for (int mt = 0; mt < 2; mt++) {
        const int gr0 = bm * BM + wm * 32 + mt * 16 + lr;
        #pragma unroll
        for (int nt = 0; nt < 8; nt++) {
            const int gc = bn * BN + wn * 64 + nt * 8 + lc * 2;
            const float b0 = __ldg(&bias[gc]);
            const float b1 = __ldg(&bias[gc + 1]);
            *(float2*)(Y + (size_t)gr0 * DMODEL + gc) =
                make_float2(acc[mt][nt][0] + b0, acc[mt][nt][1] + b1);
            *(float2*)(Y + (size_t)(gr0 + 8) * DMODEL + gc) =
                make_float2(acc[mt][nt][2] + b0, acc[mt][nt][3] + b1);
        }
    }
}

// =============================================================================
// kv partial via HMMA: C[d][e] = sum_m K[m][d]*V[m][e] over 256-m split (KSPLIT 16),
// z[d] = sum_m K[m][d] from A fragments.
// =============================================================================
__global__ __launch_bounds__(128, 1)
void kv_hmma(const __half* __restrict__ Kb, const __half* __restrict__ Vb,
             float* __restrict__ kvp, float* __restrict__ zp) {
    extern __shared__ char sm[];
    const uint32_t sbase = smem_u32(sm);
    const int tid = threadIdx.x;
    const int lane = tid & 31;
    const int wid = tid >> 5;

    const int s  = blockIdx.x % KSPLIT;
    const int bh = blockIdx.x / KSPLIT;
    const int b = bh / HEADS, h = bh % HEADS;
    const int blkbase = b * (SEQ / 128) + s * 2;

    if (tid == 0) { mbar_init(sbase, 1); mbar_init(sbase + 8, 1); }
    __syncthreads();

    auto issue = [&](int j) {
        const int st = j & 1;
        const uint32_t mb = sbase + st * 8;
        const uint32_t dst = sbase + 1024 + st * KV_STAGE;
        mbar_expect_tx(mb, 2 * BLK_BYTES);
        const size_t off = ((size_t)((blkbase + j) * NCH + h)) << 14;
        bulk_cp(dst,         (const char*)Kb + off, BLK_BYTES, mb);
        bulk_cp(dst + 16384, (const char*)Vb + off, BLK_BYTES, mb);
    };
    if (tid == 0) { issue(0); issue(1); }

    const int d0 = wid * 16;
    const int a_rloc = (lane & 7) + ((lane >> 4) << 3);
    const uint32_t a_cb = (uint32_t)(d0 * 2) + (uint32_t)(((lane >> 3) & 1) << 4);
    const uint32_t a_off = (uint32_t)(a_rloc * 128) + (a_cb ^ ((uint32_t)(a_rloc & 7) << 4));
    const int b_rloc = (lane & 7) + (((lane >> 3) & 1) << 3);
    const uint32_t b_cb0 = (uint32_t)((lane >> 4) << 4);
    uint32_t b_off[4];
    #pragma unroll
    for (int e4 = 0; e4 < 4; e4++)
        b_off[e4] = (uint32_t)(b_rloc * 128)
                  + (((uint32_t)(e4 * 32) + b_cb0) ^ ((uint32_t)(b_rloc & 7) << 4));

    float acc[8][4];
    #pragma unroll
    for (int nt = 0; nt < 8; nt++)
        #pragma unroll
        for (int i = 0; i < 4; i++) acc[nt][i] = 0.f;
    float zs0 = 0.f, zs1 = 0.f;

    #pragma unroll
    for (int j = 0; j < 2; j++) {
        mbar_wait(sbase + (j & 1) * 8, 0);
        const uint32_t bK = sbase + 1024 + (j & 1) * KV_STAGE;
        const uint32_t bV = bK + 16384;
        #pragma unroll
        for (int ks = 0; ks < 8; ks++) {
            uint32_t Ar[4];
            ldsm4t(Ar[0], Ar[1], Ar[2], Ar[3], bK + (uint32_t)(ks * 2048) + a_off);
            uint32_t Br[8][2];
            #pragma unroll
            for (int e4 = 0; e4 < 4; e4++) {
                uint32_t r0, r1, r2, r3;
                ldsm4t(r0, r1, r2, r3, bV + (uint32_t)(ks * 2048) + b_off[e4]);
                Br[2 * e4][0] = r0; Br[2 * e4][1] = r1;
                Br[2 * e4 + 1][0] = r2; Br[2 * e4 + 1][1] = r3;
            }
            #pragma unroll
            for (int nt = 0; nt < 8; nt++) mma_fp16(acc[nt], Ar, Br[nt]);
            zs0 += h2sum(Ar[0]) + h2sum(Ar[2]);
            zs1 += h2sum(Ar[1]) + h2sum(Ar[3]);
        }
    }

    zs0 += __shfl_xor_sync(0xFFFFFFFF, zs0, 1);
    zs0 += __shfl_xor_sync(0xFFFFFFFF, zs0, 2);
    zs1 += __shfl_xor_sync(0xFFFFFFFF, zs1, 1);
    zs1 += __shfl_xor_sync(0xFFFFFFFF, zs1, 2);

    const int g = lane >> 2;
    const int ec = 2 * (lane & 3);
    float* kout = kvp + (size_t)blockIdx.x * (DH * DH);
    #pragma unroll
    for (int nt = 0; nt < 8; nt++) {
        *(float2*)&kout[(d0 + g) * DH + nt * 8 + ec]     = make_float2(acc[nt][0], acc[nt][1]);
        *(float2*)&kout[(d0 + g + 8) * DH + nt * 8 + ec] = make_float2(acc[nt][2], acc[nt][3]);
    }
    if ((lane & 3) == 0) {
        zp[(size_t)blockIdx.x * DH + d0 + g]     = zs0;
        zp[(size_t)blockIdx.x * DH + d0 + g + 8] = zs1;
    }
}

// =============================================================================
// reduce partials -> kvT fp16 swizzled [e][d] + z fp32
// =============================================================================
__global__ __launch_bounds__(256)
void kv_reduce(const float* __restrict__ kvp, const float* __restrict__ zp,
               __half* __restrict__ kvT, float* __restrict__ zo) {
    const int bh = blockIdx.x;
    const int tid = threadIdx.x;
    for (int i = tid; i < DH * DH; i += 256) {
        float sum = 0.f;
        #pragma unroll
        for (int s = 0; s < KSPLIT; s++)
            sum += kvp[((size_t)bh * KSPLIT + s) * (DH * DH) + i];
        const int d = i >> 6, e = i & 63;
        const size_t off = (size_t)bh * 8192 + (uint32_t)(e * 128)
                         + (((uint32_t)(d * 2)) ^ ((uint32_t)(e & 7) << 4));
        *(__half*)((char*)kvT + off) = __float2half_rn(sum);
    }
    if (tid < DH) {
        float sum = 0.f;
        #pragma unroll
        for (int s = 0; s < KSPLIT; s++)
            sum += zp[((size_t)bh * KSPLIT + s) * DH + tid];
        zo[(size_t)bh * DH + tid] = sum;
    }
}

// =============================================================================
// attn via HMMA: out[n][e] = (sum_d Q[n][d] kvT[e][d]) / (q.z + eps).
// grid = (ROWS/128, 2): grid.y picks 8-head range (256 CTAs -> >1 full wave).
// =============================================================================
__global__ __launch_bounds__(256, 1)
void attn_hmma(const __half* __restrict__ Qb, const __half* __restrict__ kvT,
               const float* __restrict__ z, __half* __restrict__ Sb) {
    extern __shared__ char sm[];
    __shared__ float zsm[2][64];
    const uint32_t sbase = smem_u32(sm);
    const int tid = threadIdx.x;
    const int lane = tid & 31;
    const int wid = tid >> 5;
    const int blk = blockIdx.x;
    const int h0 = blockIdx.y * 8;
    const int b = blk >> 5;

    if (tid == 0) { mbar_init(sbase, 1); mbar_init(sbase + 8, 1); }

    auto issue = [&](int hh) {      // hh = local head index 0..7
        const int h = h0 + hh;
        const int st = hh & 1;
        const uint32_t mb = sbase + st * 8;
        const uint32_t dst = sbase + 1024 + st * AT_STAGE;
        mbar_expect_tx(mb, 16384 + 8192);
        bulk_cp(dst, (const char*)Qb + (((size_t)(blk * NCH + h)) << 14), 16384, mb);
        bulk_cp(dst + 16384, (const char*)kvT + (((size_t)(b * HEADS + h)) << 13), 8192, mb);
    };
    __syncthreads();
    if (tid == 0) { issue(0); issue(1); }
    if (tid < 64) {
        zsm[0][tid] = z[(size_t)(b * HEADS + h0 + 0) * DH + tid];
        zsm[1][tid] = z[(size_t)(b * HEADS + h0 + 1) * DH + tid];
    }
    __syncthreads();

    const int row_a = wid * 16 + (lane & 15);
    const uint32_t a_base = (uint32_t)(row_a * 128);
    const uint32_t a_mask = (uint32_t)((row_a & 7) << 4);
    const uint32_t a_colb = (uint32_t)((lane >> 4) << 4);
    int nrow[4];
    #pragma unroll
    for (int ntp = 0; ntp < 4; ntp++)
        nrow[ntp] = ntp * 16 + (lane & 7) + ((lane >> 4) << 3);
    const uint32_t b_colb = (lane & 8) ? 16u : 0u;
    uint32_t b_base[4], b_mask[4];
    #pragma unroll
    for (int ntp = 0; ntp < 4; ntp++) {
        b_base[ntp] = (uint32_t)(nrow[ntp] * 128);
        b_mask[ntp] = (uint32_t)((nrow[ntp] & 7) << 4);
    }

    const int g = lane >> 2;
    const int ec = 2 * (lane & 3);

    for (int hh = 0; hh < 8; hh++) {
        const int h = h0 + hh;
        const int st = hh & 1;
        mbar_wait(sbase + st * 8, (hh >> 1) & 1);
        const uint32_t bQ = sbase + 1024 + st * AT_STAGE;
        const uint32_t bKV = bQ + 16384;

        float acc[8][4];
        #pragma unroll
        for (int nt = 0; nt < 8; nt++)
            #pragma unroll
            for (int i = 0; i < 4; i++) acc[nt][i] = 0.f;
        float den0 = 0.f, den1 = 0.f;

        #pragma unroll
        for (int ks = 0; ks < 4; ks++) {
            const uint32_t kb = (uint32_t)(ks * 32);
            uint32_t Ar[4];
            ldsm4(Ar[0], Ar[1], Ar[2], Ar[3], bQ + a_base + ((kb + a_colb) ^ a_mask));
            uint32_t Br[8][2];
            #pragma unroll
            for (int ntp = 0; ntp < 4; ntp++) {
                uint32_t off = b_base[ntp] + ((kb + b_colb) ^ b_mask[ntp]);
                ldsm4(Br[2 * ntp][0], Br[2 * ntp][1], Br[2 * ntp + 1][0], Br[2 * ntp + 1][1],
                      bKV + off);
            }
            #pragma unroll
            for (int nt = 0; nt < 8; nt++) mma_fp16(acc[nt], Ar, Br[nt]);

            const int dbase = ks * 16 + ec;
            const float z0 = zsm[st][dbase],     z1 = zsm[st][dbase + 1];
            const float z8 = zsm[st][dbase + 8], z9 = zsm[st][dbase + 9];
            float2 a0 = __half22float2(*(__half2*)&Ar[0]);
            float2 a1 = __half22float2(*(__half2*)&Ar[1]);
            float2 a2 = __half22float2(*(__half2*)&Ar[2]);
            float2 a3 = __half22float2(*(__half2*)&Ar[3]);
            den0 += a0.x * z0 + a0.y * z1 + a2.x * z8 + a2.y * z9;
            den1 += a1.x * z0 + a1.y * z1 + a3.x * z8 + a3.y * z9;
        }
        den0 += __shfl_xor_sync(0xFFFFFFFF, den0, 1);
        den0 += __shfl_xor_sync(0xFFFFFFFF, den0, 2);
        den1 += __shfl_xor_sync(0xFFFFFFFF, den1, 1);
        den1 += __shfl_xor_sync(0xFFFFFFFF, den1, 2);
        const float rinv0 = 1.0f / (den0 + EPSV);
        const float rinv1 = 1.0f / (den1 + EPSV);

        const size_t blkb = ((size_t)(blk * NCH + h)) << 14;
        const uint32_t ra = (uint32_t)(wid * 16 + g);
        const uint32_t rb = ra + 8;
        #pragma unroll
        for (int nt = 0; nt < 8; nt++) {
            const uint32_t colb = (uint32_t)((nt * 8 + ec) * 2);
            __half2 p0 = __floats2half2_rn(acc[nt][0] * rinv0, acc[nt][1] * rinv0);
            __half2 p1 = __floats2half2_rn(acc[nt][2] * rinv1, acc[nt][3] * rinv1);
            *(uint32_t*)((char*)Sb + blkb + ra * 128 + (colb ^ ((ra & 7) << 4))) =
                *(uint32_t*)&p0;
            *(uint32_t*)((char*)Sb + blkb + rb * 128 + (colb ^ ((rb & 7) << 4))) =
                *(uint32_t*)&p1;
        }
        __syncthreads();
        if (tid == 0 && hh + 2 < 8) issue(hh + 2);
        if (tid < 64 && hh + 2 < 8)
            zsm[st][tid] = z[(size_t)(b * HEADS + h0 + hh + 2) * DH + tid];
    }
}

// =============================================================================
extern "C" void kernel_launch(void* const* d_in, const int* in_sizes, int n_in,
                              void* d_out, int out_size) {
    const float* queries = (const float*)d_in[0];
    const float* keys    = (const float*)d_in[1];
    const float* values  = (const float*)d_in[2];
    const float* wq = (const float*)d_in[3];
    const float* bq = (const float*)d_in[4];
    const float* wk = (const float*)d_in[5];
    const float* bk = (const float*)d_in[6];
    const float* wv = (const float*)d_in[7];
    const float* bv = (const float*)d_in[8];
    const float* wo = (const float*)d_in[9];
    const float* bo = (const float*)d_in[10];
    float* out = (float*)d_out;

    __half *Xbp, *Abp, *Wbp, *Qbp, *Kbp, *Vbp, *kvTp;
    float *kvp, *zp, *zb;
    cudaGetSymbolAddress((void**)&Xbp, g_Xb);
    cudaGetSymbolAddress((void**)&Abp, g_Ab);
    cudaGetSymbolAddress((void**)&Wbp, g_Wb);
    cudaGetSymbolAddress((void**)&Qbp, g_Qb);
    cudaGetSymbolAddress((void**)&Kbp, g_Kb);
    cudaGetSymbolAddress((void**)&Vbp, g_Vb);
    cudaGetSymbolAddress((void**)&kvTp, g_kvT);
    cudaGetSymbolAddress((void**)&kvp, g_kvp);
    cudaGetSymbolAddress((void**)&zp,  g_zp);
    cudaGetSymbolAddress((void**)&zb,  g_z);

    cudaFuncSetAttribute(gemm_qkv, cudaFuncAttributeMaxDynamicSharedMemorySize, SMEM_BYTES);
    cudaFuncSetAttribute(gemm_out, cudaFuncAttributeMaxDynamicSharedMemorySize, SMEM_BYTES);
    cudaFuncSetAttribute(kv_hmma,   cudaFuncAttributeMaxDynamicSharedMemorySize, KV_SMEM);
    cudaFuncSetAttribute(attn_hmma, cudaFuncAttributeMaxDynamicSharedMemorySize, AT_SMEM);

    const int WSZ = DMODEL * DMODEL;
    const int XN8 = ROWS * DMODEL / 8;
    const int WN8 = WSZ / 8;

    dim3 gb(GTHREADS);

    // weights -> blocked fp16, one launch (z = 4 tensors)
    cvt_swz_multi<<<dim3(512, 1, 4), 256>>>(wq, wk, wv, wo, Wbp, (size_t)WSZ, WN8);
    // activations -> blocked fp16, one launch (z = 3 tensors)
    cvt_swz_multi<<<dim3(2048, 1, 3), 256>>>(queries, keys, values, nullptr,
                                             Xbp, ASTRIDE, XN8);

    // merged QKV projections (3072 CTAs, one wave-packed launch)
    gemm_qkv<<<dim3(DMODEL / BN, ROWS / BM, 3), gb, SMEM_BYTES>>>(
        Xbp, Wbp, bq, bk, bv, Qbp, Kbp, Vbp);

    kv_hmma  <<<BATCH * HEADS * KSPLIT, 128, KV_SMEM>>>(Kbp, Vbp, kvp, zp);
    kv_reduce<<<BATCH * HEADS, 256>>>(kvp, zp, kvTp, zb);
    attn_hmma<<<dim3(ROWS / 128, 2), 256, AT_SMEM>>>(Qbp, kvTp, zb, Abp);

    // output projection (fp32 out)
    gemm_out<<<dim3(DMODEL / BN, ROWS / BM), gb, SMEM_BYTES>>>(
        Abp, Wbp + 3 * WSZ, bo, out);
}